// round 5
// baseline (speedup 1.0000x reference)
#include <cuda_runtime.h>
#include <cuda_bf16.h>
#include <cstdint>

// ============================================================================
// CrossDepthAttention, mma.sync tensor cores (base-target legal).
//   K0: convert Wv, Wo -> bf16
//   K1: q    = cur @ Wq^T            tf32  (8192 x 1024 x 1024, NT)
//   K2: qk_h = q_h @ Wk_h            tf32  (NN, K=64, x16) -> bf16
//   K3: fused attention               qk(bf16) -> hbar(bf16)
//   K4: out_h = hbar_h @ Wv_h^T      bf16  (NT, N=64, x16) -> bf16
//   K5: final = cur + out @ Wo^T     bf16  (NT + residual) -> fp32
// ============================================================================

#define D_DIM   1024
#define H_HEADS 16
#define HD      64
#define NPREV   8
#define M_MAX   8192

__device__ float         g_q[M_MAX * D_DIM];                        // q (fp32)
__device__ __nv_bfloat16 g_qk[(size_t)M_MAX * H_HEADS * D_DIM];     // qk (bf16)
__device__ __nv_bfloat16 g_hb[(size_t)M_MAX * H_HEADS * D_DIM];     // hbar (bf16)
__device__ __nv_bfloat16 g_out[M_MAX * D_DIM];                      // out (bf16)
__device__ __nv_bfloat16 g_wv[D_DIM * D_DIM];                       // Wv bf16
__device__ __nv_bfloat16 g_wo[D_DIM * D_DIM];                       // Wo bf16

// ---------------------------------------------------------------------------
__device__ __forceinline__ uint32_t smem_u32(const void* p) {
    uint32_t a;
    asm("{ .reg .u64 t; cvta.to.shared.u64 t, %1; cvt.u32.u64 %0, t; }"
        : "=r"(a) : "l"(p));
    return a;
}
__device__ __forceinline__ void cp16(uint32_t s, const void* g) {
    asm volatile("cp.async.cg.shared.global [%0], [%1], 16;\n" :: "r"(s), "l"(g));
}
__device__ __forceinline__ void cp_commit() {
    asm volatile("cp.async.commit_group;\n" ::: "memory");
}
template <int N> __device__ __forceinline__ void cp_wait() {
    asm volatile("cp.async.wait_group %0;\n" :: "n"(N) : "memory");
}
__device__ __forceinline__ void mma_tf32(float* c, const uint32_t* a,
                                         const uint32_t* b) {
    asm volatile(
        "mma.sync.aligned.m16n8k8.row.col.f32.tf32.tf32.f32 "
        "{%0,%1,%2,%3}, {%4,%5,%6,%7}, {%8,%9}, {%0,%1,%2,%3};\n"
        : "+f"(c[0]), "+f"(c[1]), "+f"(c[2]), "+f"(c[3])
        : "r"(a[0]), "r"(a[1]), "r"(a[2]), "r"(a[3]), "r"(b[0]), "r"(b[1]));
}
__device__ __forceinline__ void mma_bf16(float* c, const uint32_t* a,
                                         const uint32_t* b) {
    asm volatile(
        "mma.sync.aligned.m16n8k16.row.col.f32.bf16.bf16.f32 "
        "{%0,%1,%2,%3}, {%4,%5,%6,%7}, {%8,%9}, {%0,%1,%2,%3};\n"
        : "+f"(c[0]), "+f"(c[1]), "+f"(c[2]), "+f"(c[3])
        : "r"(a[0]), "r"(a[1]), "r"(a[2]), "r"(a[3]), "r"(b[0]), "r"(b[1]));
}

// ---------------------------------------------------------------------------
// K0: weight conversion fp32 -> bf16 (Wv, Wo)
// ---------------------------------------------------------------------------
__global__ void __launch_bounds__(256) convert_w(
    const float* __restrict__ wv, const float* __restrict__ wo,
    __nv_bfloat16* __restrict__ ov, __nv_bfloat16* __restrict__ oo)
{
    int i = (blockIdx.x * 256 + threadIdx.x) * 4;
    if (i < D_DIM * D_DIM) {
        float4 a = *(const float4*)(wv + i);
        float4 b = *(const float4*)(wo + i);
        __nv_bfloat162 a0 = __float22bfloat162_rn(make_float2(a.x, a.y));
        __nv_bfloat162 a1 = __float22bfloat162_rn(make_float2(a.z, a.w));
        __nv_bfloat162 b0 = __float22bfloat162_rn(make_float2(b.x, b.y));
        __nv_bfloat162 b1 = __float22bfloat162_rn(make_float2(b.z, b.w));
        *(__nv_bfloat162*)(ov + i)     = a0;
        *(__nv_bfloat162*)(ov + i + 2) = a1;
        *(__nv_bfloat162*)(oo + i)     = b0;
        *(__nv_bfloat162*)(oo + i + 2) = b1;
    }
}

// ---------------------------------------------------------------------------
// tf32 GEMM (as R4): C[m,n] = sum_k A[m,k] * B'[n,k]
// ---------------------------------------------------------------------------
template <int BN, bool B_NN, bool OUT_BF16, bool RESID>
__global__ void __launch_bounds__(256)
gemm_mma(const float* __restrict__ A, int lda, long long sA,
         const float* __restrict__ B, int ldb, long long sB,
         const float* __restrict__ R,
         void* __restrict__ C, int ldc, long long sC,
         int K)
{
    constexpr int WM = (BN == 128) ? 2 : 4;
    constexpr int MT = 8 / WM;
    constexpr int A_FLOATS = 128 * 36;
    constexpr int B_FLOATS = BN * 36;

    extern __shared__ float smem_f[];
    const uint32_t sbase = smem_u32(smem_f);

    const int tid = threadIdx.x;
    const int wid = tid >> 5, lane = tid & 31;
    const int wm = wid % WM, wn = wid / WM;
    const int bx = blockIdx.x, by = blockIdx.y, bz = blockIdx.z;

    const float* Af = A + (long long)bz * sA + (size_t)(by * 128) * lda;
    const float* Bg = B_NN ? (B + (long long)bz * sB + bx * BN)
                           : (B + (long long)bz * sB + (size_t)(bx * BN) * ldb);

    auto fill = [&](int buf, int k0) {
        const uint32_t As_b = sbase + (uint32_t)(buf * A_FLOATS) * 4u;
        const uint32_t Bs_b = sbase + (uint32_t)(2 * A_FLOATS + buf * B_FLOATS) * 4u;
#pragma unroll
        for (int p = 0; p < 4; ++p) {
            int ch = tid + p * 256;
            int row = ch >> 3, c4 = ch & 7;
            cp16(As_b + (uint32_t)(row * 36 + c4 * 4) * 4u,
                 Af + (size_t)row * lda + k0 + c4 * 4);
        }
        if (!B_NN) {
#pragma unroll
            for (int p = 0; p < BN * 8 / 256; ++p) {
                int ch = tid + p * 256;
                int row = ch >> 3, c4 = ch & 7;
                cp16(Bs_b + (uint32_t)(row * 36 + c4 * 4) * 4u,
                     Bg + (size_t)row * ldb + k0 + c4 * 4);
            }
        } else {
            float* Bs_p = smem_f + 2 * A_FLOATS + buf * B_FLOATS;
#pragma unroll
            for (int p = 0; p < BN * 32 / 256; ++p) {
                int idx = tid + p * 256;
                int n = idx % BN, k = idx / BN;
                Bs_p[n * 36 + k] = Bg[(size_t)(k0 + k) * ldb + n];
            }
        }
    };

    float acc[MT][4][4];
#pragma unroll
    for (int mt = 0; mt < MT; ++mt)
#pragma unroll
        for (int nt = 0; nt < 4; ++nt)
#pragma unroll
            for (int j = 0; j < 4; ++j) acc[mt][nt][j] = 0.0f;

    const int a_off = (wm * (128 / WM) + (lane >> 2)) * 36 + (lane & 3);
    const int b_off = (wn * 32 + (lane >> 2)) * 36 + (lane & 3);

    const int NC = K / 32;
    fill(0, 0);
    cp_commit();

    for (int c = 0; c < NC; ++c) {
        if (c + 1 < NC) { fill((c + 1) & 1, (c + 1) * 32); cp_commit(); cp_wait<1>(); }
        else            { cp_wait<0>(); }
        __syncthreads();

        const int buf = c & 1;
        const float* As_c = smem_f + buf * A_FLOATS;
        const float* Bs_c = smem_f + 2 * A_FLOATS + buf * B_FLOATS;

#pragma unroll
        for (int s = 0; s < 4; ++s) {
            uint32_t af[MT][4];
#pragma unroll
            for (int mt = 0; mt < MT; ++mt) {
                const float* p = As_c + a_off + mt * 16 * 36 + s * 8;
                af[mt][0] = __float_as_uint(p[0]);
                af[mt][1] = __float_as_uint(p[8 * 36]);
                af[mt][2] = __float_as_uint(p[4]);
                af[mt][3] = __float_as_uint(p[8 * 36 + 4]);
            }
            uint32_t bf[4][2];
#pragma unroll
            for (int nt = 0; nt < 4; ++nt) {
                const float* p = Bs_c + b_off + nt * 8 * 36 + s * 8;
                bf[nt][0] = __float_as_uint(p[0]);
                bf[nt][1] = __float_as_uint(p[4]);
            }
#pragma unroll
            for (int mt = 0; mt < MT; ++mt)
#pragma unroll
                for (int nt = 0; nt < 4; ++nt)
                    mma_tf32(acc[mt][nt], af[mt], bf[nt]);
        }
        __syncthreads();
    }

    const int row0 = by * 128 + wm * (128 / WM) + (lane >> 2);
    const int coll = wn * 32 + (lane & 3) * 2;
#pragma unroll
    for (int mt = 0; mt < MT; ++mt) {
        const int m = row0 + mt * 16;
#pragma unroll
        for (int nt = 0; nt < 4; ++nt) {
            const int n = bx * BN + coll + nt * 8;
            if (!OUT_BF16) {
                float* Cg = (float*)C + (long long)bz * sC;
                float2 v0 = make_float2(acc[mt][nt][0], acc[mt][nt][1]);
                float2 v1 = make_float2(acc[mt][nt][2], acc[mt][nt][3]);
                if (RESID) {
                    float2 r0 = *(const float2*)(R + (size_t)m * ldc + n);
                    float2 r1 = *(const float2*)(R + (size_t)(m + 8) * ldc + n);
                    v0.x += r0.x; v0.y += r0.y;
                    v1.x += r1.x; v1.y += r1.y;
                }
                *(float2*)(Cg + (size_t)m * ldc + n)       = v0;
                *(float2*)(Cg + (size_t)(m + 8) * ldc + n) = v1;
            } else {
                __nv_bfloat16* Cg = (__nv_bfloat16*)C + (long long)bz * sC;
                *(__nv_bfloat162*)(Cg + (size_t)m * ldc + n) =
                    __float22bfloat162_rn(make_float2(acc[mt][nt][0], acc[mt][nt][1]));
                *(__nv_bfloat162*)(Cg + (size_t)(m + 8) * ldc + n) =
                    __float22bfloat162_rn(make_float2(acc[mt][nt][2], acc[mt][nt][3]));
            }
        }
    }
}

// ---------------------------------------------------------------------------
// bf16 GEMM (m16n8k16): C[m,n] = sum_k A[m,k] * B[n,k]   (both NT, bf16)
// CTA tile 128 x BN x 64. SMEM stride 72 halves (36 words, ≡4 mod 32).
// ---------------------------------------------------------------------------
template <int BN, bool OUT_BF16, bool RESID>
__global__ void __launch_bounds__(256)
gemm_bf16(const __nv_bfloat16* __restrict__ A, int lda, long long sA,
          const __nv_bfloat16* __restrict__ B, int ldb, long long sB,
          const float* __restrict__ R,
          void* __restrict__ C, int ldc, long long sC,
          int K)
{
    constexpr int WM = (BN == 128) ? 2 : 4;
    constexpr int MT = 8 / WM;
    constexpr int A_HALVES = 128 * 72;
    constexpr int B_HALVES = BN * 72;

    extern __shared__ __align__(16) __nv_bfloat16 smem_h[];
    const uint32_t sbase = smem_u32(smem_h);
    const uint32_t* smem_w = (const uint32_t*)smem_h;

    const int tid = threadIdx.x;
    const int wid = tid >> 5, lane = tid & 31;
    const int wm = wid % WM, wn = wid / WM;
    const int bx = blockIdx.x, by = blockIdx.y, bz = blockIdx.z;

    const __nv_bfloat16* Af = A + (long long)bz * sA + (size_t)(by * 128) * lda;
    const __nv_bfloat16* Bg = B + (long long)bz * sB + (size_t)(bx * BN) * ldb;

    auto fill = [&](int buf, int k0) {
        const uint32_t As_b = sbase + (uint32_t)(buf * A_HALVES) * 2u;
        const uint32_t Bs_b = sbase + (uint32_t)(2 * A_HALVES + buf * B_HALVES) * 2u;
        // A: 128 rows x 64 halves = 8 chunks/row, 1024 chunks
#pragma unroll
        for (int p = 0; p < 4; ++p) {
            int ch = tid + p * 256;
            int row = ch >> 3, c8 = ch & 7;
            cp16(As_b + (uint32_t)(row * 72 + c8 * 8) * 2u,
                 Af + (size_t)row * lda + k0 + c8 * 8);
        }
#pragma unroll
        for (int p = 0; p < BN * 8 / 256; ++p) {
            int ch = tid + p * 256;
            int row = ch >> 3, c8 = ch & 7;
            cp16(Bs_b + (uint32_t)(row * 72 + c8 * 8) * 2u,
                 Bg + (size_t)row * ldb + k0 + c8 * 8);
        }
    };

    float acc[MT][4][4];
#pragma unroll
    for (int mt = 0; mt < MT; ++mt)
#pragma unroll
        for (int nt = 0; nt < 4; ++nt)
#pragma unroll
            for (int j = 0; j < 4; ++j) acc[mt][nt][j] = 0.0f;

    const int g = lane >> 2, tg = lane & 3;
    const int a_off = (wm * (128 / WM) + g) * 36 + tg;     // word index
    const int b_off = (wn * 32 + g) * 36 + tg;

    const int NC = K / 64;
    fill(0, 0);
    cp_commit();

    for (int c = 0; c < NC; ++c) {
        if (c + 1 < NC) { fill((c + 1) & 1, (c + 1) * 64); cp_commit(); cp_wait<1>(); }
        else            { cp_wait<0>(); }
        __syncthreads();

        const int buf = c & 1;
        const uint32_t* As_w = smem_w + buf * (A_HALVES / 2);
        const uint32_t* Bs_w = smem_w + A_HALVES + buf * (B_HALVES / 2);

#pragma unroll
        for (int s = 0; s < 4; ++s) {          // 4 k16 steps per 64-chunk
            uint32_t af[MT][4];
#pragma unroll
            for (int mt = 0; mt < MT; ++mt) {
                const uint32_t* p = As_w + a_off + mt * 16 * 36 + s * 8;
                af[mt][0] = p[0];
                af[mt][1] = p[8 * 36];
                af[mt][2] = p[4];
                af[mt][3] = p[8 * 36 + 4];
            }
            uint32_t bf2[4][2];
#pragma unroll
            for (int nt = 0; nt < 4; ++nt) {
                const uint32_t* p = Bs_w + b_off + nt * 8 * 36 + s * 8;
                bf2[nt][0] = p[0];
                bf2[nt][1] = p[4];
            }
#pragma unroll
            for (int mt = 0; mt < MT; ++mt)
#pragma unroll
                for (int nt = 0; nt < 4; ++nt)
                    mma_bf16(acc[mt][nt], af[mt], bf2[nt]);
        }
        __syncthreads();
    }

    const int row0 = by * 128 + wm * (128 / WM) + g;
    const int coll = wn * 32 + tg * 2;
#pragma unroll
    for (int mt = 0; mt < MT; ++mt) {
        const int m = row0 + mt * 16;
#pragma unroll
        for (int nt = 0; nt < 4; ++nt) {
            const int n = bx * BN + coll + nt * 8;
            if (!OUT_BF16) {
                float* Cg = (float*)C + (long long)bz * sC;
                float2 v0 = make_float2(acc[mt][nt][0], acc[mt][nt][1]);
                float2 v1 = make_float2(acc[mt][nt][2], acc[mt][nt][3]);
                if (RESID) {
                    float2 r0 = *(const float2*)(R + (size_t)m * ldc + n);
                    float2 r1 = *(const float2*)(R + (size_t)(m + 8) * ldc + n);
                    v0.x += r0.x; v0.y += r0.y;
                    v1.x += r1.x; v1.y += r1.y;
                }
                *(float2*)(Cg + (size_t)m * ldc + n)       = v0;
                *(float2*)(Cg + (size_t)(m + 8) * ldc + n) = v1;
            } else {
                __nv_bfloat16* Cg = (__nv_bfloat16*)C + (long long)bz * sC;
                *(__nv_bfloat162*)(Cg + (size_t)m * ldc + n) =
                    __float22bfloat162_rn(make_float2(acc[mt][nt][0], acc[mt][nt][1]));
                *(__nv_bfloat162*)(Cg + (size_t)(m + 8) * ldc + n) =
                    __float22bfloat162_rn(make_float2(acc[mt][nt][2], acc[mt][nt][3]));
            }
        }
    }
}

// ---------------------------------------------------------------------------
// K3: fused attention, one CTA per row m. hbar written bf16.
// ---------------------------------------------------------------------------
__global__ void __launch_bounds__(256) attn_kernel(
    const float* __restrict__ hist, const __nv_bfloat16* __restrict__ qk,
    __nv_bfloat16* __restrict__ hbar)
{
    __shared__ float red[NPREV][8];
    __shared__ float attn_s[NPREV];

    const int m    = blockIdx.x;
    const int tid  = threadIdx.x;
    const int lane = tid & 31;
    const int warp = tid >> 5;

    float4 hv[NPREV];
    const float* hg = hist + (size_t)m * NPREV * D_DIM + tid * 4;
#pragma unroll
    for (int n = 0; n < NPREV; n++)
        hv[n] = *(const float4*)(hg + n * D_DIM);

    const __nv_bfloat16* qrow = qk + (size_t)m * (H_HEADS * D_DIM) + tid * 4;
    __nv_bfloat16* orow = hbar + (size_t)m * (H_HEADS * D_DIM) + tid * 4;

    for (int h = 0; h < H_HEADS; h++) {
        uint2 raw = *(const uint2*)(qrow + h * D_DIM);
        float2 qa = __bfloat1622float2(*reinterpret_cast<__nv_bfloat162*>(&raw.x));
        float2 qb = __bfloat1622float2(*reinterpret_cast<__nv_bfloat162*>(&raw.y));

        float part[NPREV];
#pragma unroll
        for (int n = 0; n < NPREV; n++)
            part[n] = qa.x * hv[n].x + qa.y * hv[n].y + qb.x * hv[n].z + qb.y * hv[n].w;
#pragma unroll
        for (int n = 0; n < NPREV; n++) {
            float v = part[n];
#pragma unroll
            for (int o = 16; o > 0; o >>= 1)
                v += __shfl_xor_sync(0xffffffffu, v, o);
            if (lane == 0) red[n][warp] = v;
        }
        __syncthreads();
        if (tid == 0) {
            float lg[NPREV]; float mx = -1e30f;
#pragma unroll
            for (int n = 0; n < NPREV; n++) {
                float s = 0.0f;
#pragma unroll
                for (int w = 0; w < 8; w++) s += red[n][w];
                lg[n] = s * 0.125f;
                mx = fmaxf(mx, lg[n]);
            }
            float den = 0.0f;
#pragma unroll
            for (int n = 0; n < NPREV; n++) { lg[n] = expf(lg[n] - mx); den += lg[n]; }
            float inv = 1.0f / den;
#pragma unroll
            for (int n = 0; n < NPREV; n++) attn_s[n] = lg[n] * inv;
        }
        __syncthreads();
        float4 a4 = make_float4(0.f, 0.f, 0.f, 0.f);
#pragma unroll
        for (int n = 0; n < NPREV; n++) {
            float w = attn_s[n];
            a4.x = fmaf(w, hv[n].x, a4.x);
            a4.y = fmaf(w, hv[n].y, a4.y);
            a4.z = fmaf(w, hv[n].z, a4.z);
            a4.w = fmaf(w, hv[n].w, a4.w);
        }
        uint2 ov;
        __nv_bfloat162 o0 = __float22bfloat162_rn(make_float2(a4.x, a4.y));
        __nv_bfloat162 o1 = __float22bfloat162_rn(make_float2(a4.z, a4.w));
        ov.x = *reinterpret_cast<uint32_t*>(&o0);
        ov.y = *reinterpret_cast<uint32_t*>(&o1);
        *(uint2*)(orow + h * D_DIM) = ov;
    }
}

// ---------------------------------------------------------------------------
extern "C" void kernel_launch(void* const* d_in, const int* in_sizes, int n_in,
                              void* d_out, int out_size)
{
    const float* cur  = (const float*)d_in[0];
    const float* hist = (const float*)d_in[1];
    const float* Wq   = (const float*)d_in[2];
    const float* Wk   = (const float*)d_in[3];
    const float* Wv   = (const float*)d_in[4];
    const float* Wo   = (const float*)d_in[5];
    float* out = (float*)d_out;

    const int D = D_DIM;
    const int M = in_sizes[0] / D;   // 8192

    float* q = nullptr;
    __nv_bfloat16 *qk = nullptr, *hb = nullptr, *ob = nullptr, *wv = nullptr, *wo = nullptr;
    cudaGetSymbolAddress((void**)&q,  g_q);
    cudaGetSymbolAddress((void**)&qk, g_qk);
    cudaGetSymbolAddress((void**)&hb, g_hb);
    cudaGetSymbolAddress((void**)&ob, g_out);
    cudaGetSymbolAddress((void**)&wv, g_wv);
    cudaGetSymbolAddress((void**)&wo, g_wo);

    constexpr int SM128 = (2 * 128 * 36 + 2 * 128 * 36) * 4;   // tf32: 73728
    constexpr int HB128 = (2 * 128 * 72 + 2 * 128 * 72) * 2;   // bf16: 73728
    constexpr int HB64  = (2 * 128 * 72 + 2 * 64 * 72) * 2;    // bf16: 55296

    cudaFuncSetAttribute(gemm_mma<128, false, false, false>,
                         cudaFuncAttributeMaxDynamicSharedMemorySize, SM128);
    cudaFuncSetAttribute(gemm_mma<128, true,  true,  false>,
                         cudaFuncAttributeMaxDynamicSharedMemorySize, SM128);
    cudaFuncSetAttribute(gemm_bf16<64,  true,  false>,
                         cudaFuncAttributeMaxDynamicSharedMemorySize, HB64);
    cudaFuncSetAttribute(gemm_bf16<128, false, true>,
                         cudaFuncAttributeMaxDynamicSharedMemorySize, HB128);

    // K0: Wv, Wo -> bf16
    convert_w<<<(D * D / 4 + 255) / 256, 256>>>(Wv, Wo, wv, wo);

    // K1: q = cur @ Wq^T   (tf32)
    gemm_mma<128, false, false, false>
        <<<dim3(D / 128, M / 128, 1), 256, SM128>>>(
            cur, D, 0, Wq, D, 0, nullptr, q, D, 0, D);

    // K2: qk_h = q_h @ Wk_h (tf32, NN, K=64, x16) -> bf16
    gemm_mma<128, true, true, false>
        <<<dim3(D / 128, M / 128, H_HEADS), 256, SM128>>>(
            q, D, HD,
            Wk, D, (long long)HD * D,
            nullptr,
            qk, H_HEADS * D, D,
            HD);

    // K3: attention -> hbar bf16
    attn_kernel<<<M, 256>>>(hist, qk, hb);

    // K4: out_h = hbar_h @ Wv_h^T (bf16, N=64, x16) -> bf16
    gemm_bf16<64, true, false>
        <<<dim3(1, M / 128, H_HEADS), 256, HB64>>>(
            hb, H_HEADS * D, D,        // A = hbar[:, h, :], head col offset
            wv, D, (long long)HD * D,  // B = Wv rows [h*64, h*64+64)
            nullptr,
            ob, D, HD,                 // C = out[:, h*64..], bf16
            D);

    // K5: final = cur + out @ Wo^T  (bf16 -> fp32 + residual)
    gemm_bf16<128, false, true>
        <<<dim3(D / 128, M / 128, 1), 256, HB128>>>(
            ob, D, 0, wo, D, 0, cur, out, D, 0, D);
}

// round 6
// speedup vs baseline: 1.5799x; 1.5799x over previous
#include <cuda_runtime.h>
#include <cuda_bf16.h>
#include <cstdint>

// ============================================================================
// CrossDepthAttention via mma.sync (m16n8k8 tf32) — base-target tensor cores.
//   K1: q    = cur @ Wq^T                       (8192 x 1024 x 1024, NT)
//   K2: qk_h = q_h @ Wk_h    (NN, K=64, x16)    -> bf16
//   K3: fused attention (restructured: 2 barriers, full prefetch)
//   K4: out_h = hbar_h @ Wv_h^T (NT, N=64, x16) -> fp32
//   K5: final = cur + out @ Wo^T                (NT + residual)
// ============================================================================

#define D_DIM   1024
#define H_HEADS 16
#define HD      64
#define NPREV   8
#define M_MAX   8192

__device__ float         g_q[M_MAX * D_DIM];                       // q, then out
__device__ __nv_bfloat16 g_qk[(size_t)M_MAX * H_HEADS * D_DIM];    // qk (bf16)
__device__ float         g_hbar[(size_t)M_MAX * H_HEADS * D_DIM];  // hbar (fp32)

// ---------------------------------------------------------------------------
__device__ __forceinline__ uint32_t smem_u32(const void* p) {
    uint32_t a;
    asm("{ .reg .u64 t; cvta.to.shared.u64 t, %1; cvt.u32.u64 %0, t; }"
        : "=r"(a) : "l"(p));
    return a;
}
__device__ __forceinline__ void cp16(uint32_t s, const void* g) {
    asm volatile("cp.async.cg.shared.global [%0], [%1], 16;\n" :: "r"(s), "l"(g));
}
__device__ __forceinline__ void cp_commit() {
    asm volatile("cp.async.commit_group;\n" ::: "memory");
}
template <int N> __device__ __forceinline__ void cp_wait() {
    asm volatile("cp.async.wait_group %0;\n" :: "n"(N) : "memory");
}
__device__ __forceinline__ void mma_tf32(float* c, const uint32_t* a,
                                         const uint32_t* b) {
    asm volatile(
        "mma.sync.aligned.m16n8k8.row.col.f32.tf32.tf32.f32 "
        "{%0,%1,%2,%3}, {%4,%5,%6,%7}, {%8,%9}, {%0,%1,%2,%3};\n"
        : "+f"(c[0]), "+f"(c[1]), "+f"(c[2]), "+f"(c[3])
        : "r"(a[0]), "r"(a[1]), "r"(a[2]), "r"(a[3]), "r"(b[0]), "r"(b[1]));
}

// ---------------------------------------------------------------------------
// Tiled mma.sync tf32 GEMM: C[m,n] = sum_k A[m,k] * B'[n,k]
//   B_NN=false : B'[n,k] = B[n*ldb + k]   (NT, k contiguous -> cp.async)
//   B_NN=true  : B'[n,k] = B[k*ldb + n]   (NN, manual transpose STS)
// CTA tile 128 x BN x 32. 256 threads (8 warps). SMEM stride 36 (pad 4).
// ---------------------------------------------------------------------------
template <int BN, bool B_NN, bool OUT_BF16, bool RESID>
__global__ void __launch_bounds__(256)
gemm_mma(const float* __restrict__ A, int lda, long long sA,
         const float* __restrict__ B, int ldb, long long sB,
         const float* __restrict__ R,
         void* __restrict__ C, int ldc, long long sC,
         int K)
{
    constexpr int WM = (BN == 128) ? 2 : 4;        // warps along M
    constexpr int MT = 8 / WM;                     // 16-row mma tiles per warp
    constexpr int A_FLOATS = 128 * 36;
    constexpr int B_FLOATS = BN * 36;

    extern __shared__ float smem_f[];
    const uint32_t sbase = smem_u32(smem_f);

    const int tid = threadIdx.x;
    const int wid = tid >> 5, lane = tid & 31;
    const int wm = wid % WM, wn = wid / WM;
    const int bx = blockIdx.x, by = blockIdx.y, bz = blockIdx.z;

    const float* Af = A + (long long)bz * sA + (size_t)(by * 128) * lda;
    const float* Bg = B_NN ? (B + (long long)bz * sB + bx * BN)
                           : (B + (long long)bz * sB + (size_t)(bx * BN) * ldb);

    auto fill = [&](int buf, int k0) {
        const uint32_t As_b = sbase + (uint32_t)(buf * A_FLOATS) * 4u;
        const uint32_t Bs_b = sbase + (uint32_t)(2 * A_FLOATS + buf * B_FLOATS) * 4u;
#pragma unroll
        for (int p = 0; p < 4; ++p) {
            int ch = tid + p * 256;
            int row = ch >> 3, c4 = ch & 7;
            cp16(As_b + (uint32_t)(row * 36 + c4 * 4) * 4u,
                 Af + (size_t)row * lda + k0 + c4 * 4);
        }
        if (!B_NN) {
#pragma unroll
            for (int p = 0; p < BN * 8 / 256; ++p) {
                int ch = tid + p * 256;
                int row = ch >> 3, c4 = ch & 7;
                cp16(Bs_b + (uint32_t)(row * 36 + c4 * 4) * 4u,
                     Bg + (size_t)row * ldb + k0 + c4 * 4);
            }
        } else {
            float* Bs_p = smem_f + 2 * A_FLOATS + buf * B_FLOATS;
#pragma unroll
            for (int p = 0; p < BN * 32 / 256; ++p) {
                int idx = tid + p * 256;
                int n = idx % BN, k = idx / BN;
                Bs_p[n * 36 + k] = Bg[(size_t)(k0 + k) * ldb + n];
            }
        }
    };

    float acc[MT][4][4];
#pragma unroll
    for (int mt = 0; mt < MT; ++mt)
#pragma unroll
        for (int nt = 0; nt < 4; ++nt)
#pragma unroll
            for (int j = 0; j < 4; ++j) acc[mt][nt][j] = 0.0f;

    const int a_off = (wm * (128 / WM) + (lane >> 2)) * 36 + (lane & 3);
    const int b_off = (wn * 32 + (lane >> 2)) * 36 + (lane & 3);

    const int NC = K / 32;
    fill(0, 0);
    cp_commit();

    for (int c = 0; c < NC; ++c) {
        if (c + 1 < NC) { fill((c + 1) & 1, (c + 1) * 32); cp_commit(); cp_wait<1>(); }
        else            { cp_wait<0>(); }
        __syncthreads();

        const int buf = c & 1;
        const float* As_c = smem_f + buf * A_FLOATS;
        const float* Bs_c = smem_f + 2 * A_FLOATS + buf * B_FLOATS;

#pragma unroll
        for (int s = 0; s < 4; ++s) {
            uint32_t af[MT][4];
#pragma unroll
            for (int mt = 0; mt < MT; ++mt) {
                const float* p = As_c + a_off + mt * 16 * 36 + s * 8;
                af[mt][0] = __float_as_uint(p[0]);
                af[mt][1] = __float_as_uint(p[8 * 36]);
                af[mt][2] = __float_as_uint(p[4]);
                af[mt][3] = __float_as_uint(p[8 * 36 + 4]);
            }
            uint32_t bf[4][2];
#pragma unroll
            for (int nt = 0; nt < 4; ++nt) {
                const float* p = Bs_c + b_off + nt * 8 * 36 + s * 8;
                bf[nt][0] = __float_as_uint(p[0]);
                bf[nt][1] = __float_as_uint(p[4]);
            }
#pragma unroll
            for (int mt = 0; mt < MT; ++mt)
#pragma unroll
                for (int nt = 0; nt < 4; ++nt)
                    mma_tf32(acc[mt][nt], af[mt], bf[nt]);
        }
        __syncthreads();
    }

    // ---- epilogue ----
    const int row0 = by * 128 + wm * (128 / WM) + (lane >> 2);
    const int coll = wn * 32 + (lane & 3) * 2;
#pragma unroll
    for (int mt = 0; mt < MT; ++mt) {
        const int m = row0 + mt * 16;
#pragma unroll
        for (int nt = 0; nt < 4; ++nt) {
            const int n = bx * BN + coll + nt * 8;
            if (!OUT_BF16) {
                float* Cg = (float*)C + (long long)bz * sC;
                float2 v0 = make_float2(acc[mt][nt][0], acc[mt][nt][1]);
                float2 v1 = make_float2(acc[mt][nt][2], acc[mt][nt][3]);
                if (RESID) {
                    float2 r0 = *(const float2*)(R + (size_t)m * ldc + n);
                    float2 r1 = *(const float2*)(R + (size_t)(m + 8) * ldc + n);
                    v0.x += r0.x; v0.y += r0.y;
                    v1.x += r1.x; v1.y += r1.y;
                }
                *(float2*)(Cg + (size_t)m * ldc + n)       = v0;
                *(float2*)(Cg + (size_t)(m + 8) * ldc + n) = v1;
            } else {
                __nv_bfloat16* Cg = (__nv_bfloat16*)C + (long long)bz * sC;
                *(__nv_bfloat162*)(Cg + (size_t)m * ldc + n) =
                    __float22bfloat162_rn(make_float2(acc[mt][nt][0], acc[mt][nt][1]));
                *(__nv_bfloat162*)(Cg + (size_t)(m + 8) * ldc + n) =
                    __float22bfloat162_rn(make_float2(acc[mt][nt][2], acc[mt][nt][3]));
            }
        }
    }
}

// ---------------------------------------------------------------------------
// K3: fused attention — restructured.
//   One CTA per row m, 256 threads. ALL loads prefetched (MLP 24).
//   Phase A: all 16 heads' dot partials + shfl reductions (no barriers).
//   Barrier. Phase B: 16 threads softmax 16 heads in parallel.
//   Barrier. Phase C: all 16 heads' weighted sums + fp32 stores.
// ---------------------------------------------------------------------------
__global__ void __launch_bounds__(256) attn_kernel(
    const float* __restrict__ hist, const __nv_bfloat16* __restrict__ qk,
    float* __restrict__ hbar)
{
    __shared__ float red[H_HEADS][NPREV][8];       // 4 KB
    __shared__ __align__(16) float attn_s[H_HEADS][NPREV];  // 512 B

    const int m    = blockIdx.x;
    const int tid  = threadIdx.x;
    const int lane = tid & 31;
    const int warp = tid >> 5;

    // ---- prefetch everything: 16 qk heads + 8 history vectors ----
    const __nv_bfloat16* qrow = qk + (size_t)m * (H_HEADS * D_DIM) + tid * 4;
    uint2 q2[H_HEADS];
#pragma unroll
    for (int h = 0; h < H_HEADS; h++)
        q2[h] = *(const uint2*)(qrow + h * D_DIM);

    float4 hv[NPREV];
    const float* hg = hist + (size_t)m * NPREV * D_DIM + tid * 4;
#pragma unroll
    for (int n = 0; n < NPREV; n++)
        hv[n] = *(const float4*)(hg + n * D_DIM);

    // ---- Phase A: partial dots + warp reductions, all heads ----
#pragma unroll
    for (int h = 0; h < H_HEADS; h++) {
        float2 qa = __bfloat1622float2(*reinterpret_cast<__nv_bfloat162*>(&q2[h].x));
        float2 qb = __bfloat1622float2(*reinterpret_cast<__nv_bfloat162*>(&q2[h].y));
        float part[NPREV];
#pragma unroll
        for (int n = 0; n < NPREV; n++)
            part[n] = qa.x * hv[n].x + qa.y * hv[n].y
                    + qb.x * hv[n].z + qb.y * hv[n].w;
#pragma unroll
        for (int n = 0; n < NPREV; n++) {
            float v = part[n];
#pragma unroll
            for (int o = 16; o > 0; o >>= 1)
                v += __shfl_xor_sync(0xffffffffu, v, o);
            if (lane == 0) red[h][n][warp] = v;
        }
    }
    __syncthreads();

    // ---- Phase B: 16 parallel softmaxes ----
    if (tid < H_HEADS) {
        const int h = tid;
        float lg[NPREV];
        float mx = -1e30f;
#pragma unroll
        for (int n = 0; n < NPREV; n++) {
            float4 s0 = *(const float4*)&red[h][n][0];
            float4 s1 = *(const float4*)&red[h][n][4];
            float s = (s0.x + s0.y) + (s0.z + s0.w)
                    + (s1.x + s1.y) + (s1.z + s1.w);
            lg[n] = s * 0.125f;                   // 1/sqrt(Hd=64)
            mx = fmaxf(mx, lg[n]);
        }
        float den = 0.0f;
#pragma unroll
        for (int n = 0; n < NPREV; n++) { lg[n] = expf(lg[n] - mx); den += lg[n]; }
        float inv = 1.0f / den;
#pragma unroll
        for (int n = 0; n < NPREV; n++) attn_s[h][n] = lg[n] * inv;
    }
    __syncthreads();

    // ---- Phase C: weighted sums + stores, all heads ----
    float* orow = hbar + (size_t)m * (H_HEADS * D_DIM) + tid * 4;
#pragma unroll
    for (int h = 0; h < H_HEADS; h++) {
        float4 w0 = *(const float4*)&attn_s[h][0];
        float4 w1 = *(const float4*)&attn_s[h][4];
        float4 a4;
        a4.x = w0.x * hv[0].x; a4.y = w0.x * hv[0].y;
        a4.z = w0.x * hv[0].z; a4.w = w0.x * hv[0].w;
        a4.x = fmaf(w0.y, hv[1].x, a4.x); a4.y = fmaf(w0.y, hv[1].y, a4.y);
        a4.z = fmaf(w0.y, hv[1].z, a4.z); a4.w = fmaf(w0.y, hv[1].w, a4.w);
        a4.x = fmaf(w0.z, hv[2].x, a4.x); a4.y = fmaf(w0.z, hv[2].y, a4.y);
        a4.z = fmaf(w0.z, hv[2].z, a4.z); a4.w = fmaf(w0.z, hv[2].w, a4.w);
        a4.x = fmaf(w0.w, hv[3].x, a4.x); a4.y = fmaf(w0.w, hv[3].y, a4.y);
        a4.z = fmaf(w0.w, hv[3].z, a4.z); a4.w = fmaf(w0.w, hv[3].w, a4.w);
        a4.x = fmaf(w1.x, hv[4].x, a4.x); a4.y = fmaf(w1.x, hv[4].y, a4.y);
        a4.z = fmaf(w1.x, hv[4].z, a4.z); a4.w = fmaf(w1.x, hv[4].w, a4.w);
        a4.x = fmaf(w1.y, hv[5].x, a4.x); a4.y = fmaf(w1.y, hv[5].y, a4.y);
        a4.z = fmaf(w1.y, hv[5].z, a4.z); a4.w = fmaf(w1.y, hv[5].w, a4.w);
        a4.x = fmaf(w1.z, hv[6].x, a4.x); a4.y = fmaf(w1.z, hv[6].y, a4.y);
        a4.z = fmaf(w1.z, hv[6].z, a4.z); a4.w = fmaf(w1.z, hv[6].w, a4.w);
        a4.x = fmaf(w1.w, hv[7].x, a4.x); a4.y = fmaf(w1.w, hv[7].y, a4.y);
        a4.z = fmaf(w1.w, hv[7].z, a4.z); a4.w = fmaf(w1.w, hv[7].w, a4.w);
        *(float4*)(orow + h * D_DIM) = a4;
    }
}

// ---------------------------------------------------------------------------
extern "C" void kernel_launch(void* const* d_in, const int* in_sizes, int n_in,
                              void* d_out, int out_size)
{
    const float* cur  = (const float*)d_in[0];
    const float* hist = (const float*)d_in[1];
    const float* Wq   = (const float*)d_in[2];
    const float* Wk   = (const float*)d_in[3];
    const float* Wv   = (const float*)d_in[4];
    const float* Wo   = (const float*)d_in[5];
    float* out = (float*)d_out;

    const int D = D_DIM;
    const int M = in_sizes[0] / D;   // 8192

    float* q = nullptr;
    __nv_bfloat16* qk = nullptr;
    float* hbar = nullptr;
    cudaGetSymbolAddress((void**)&q,    g_q);
    cudaGetSymbolAddress((void**)&qk,   g_qk);
    cudaGetSymbolAddress((void**)&hbar, g_hbar);

    constexpr int SM128 = (2 * 128 * 36 + 2 * 128 * 36) * 4;   // 73728
    constexpr int SM64  = (2 * 128 * 36 + 2 * 64 * 36) * 4;    // 55296

    cudaFuncSetAttribute(gemm_mma<128, false, false, false>,
                         cudaFuncAttributeMaxDynamicSharedMemorySize, SM128);
    cudaFuncSetAttribute(gemm_mma<128, true,  true,  false>,
                         cudaFuncAttributeMaxDynamicSharedMemorySize, SM128);
    cudaFuncSetAttribute(gemm_mma<64,  false, false, false>,
                         cudaFuncAttributeMaxDynamicSharedMemorySize, SM64);
    cudaFuncSetAttribute(gemm_mma<128, false, false, true>,
                         cudaFuncAttributeMaxDynamicSharedMemorySize, SM128);

    // K1: q = cur @ Wq^T
    gemm_mma<128, false, false, false>
        <<<dim3(D / 128, M / 128, 1), 256, SM128>>>(
            cur, D, 0, Wq, D, 0, nullptr, q, D, 0, D);

    // K2: qk_h = q_h @ Wk_h  (NN, K=64, x16 heads) -> bf16
    gemm_mma<128, true, true, false>
        <<<dim3(D / 128, M / 128, H_HEADS), 256, SM128>>>(
            q, D, HD,
            Wk, D, (long long)HD * D,
            nullptr,
            qk, H_HEADS * D, D,
            HD);

    // K3: attention
    attn_kernel<<<M, 256>>>(hist, qk, hbar);

    // K4: out_h = hbar_h @ Wv_h^T (NT, N=64, x16) -> g_q
    gemm_mma<64, false, false, false>
        <<<dim3(1, M / 128, H_HEADS), 256, SM64>>>(
            hbar, H_HEADS * D, D,
            Wv, D, (long long)HD * D,
            nullptr,
            q, D, HD,
            D);

    // K5: final = cur + out @ Wo^T
    gemm_mma<128, false, false, true>
        <<<dim3(D / 128, M / 128, 1), 256, SM128>>>(
            q, D, 0, Wo, D, 0, cur, out, D, 0, D);
}

// round 7
// speedup vs baseline: 1.6267x; 1.0296x over previous
#include <cuda_runtime.h>
#include <cuda_bf16.h>
#include <cstdint>

// ============================================================================
// CrossDepthAttention via mma.sync (m16n8k8 tf32) — base-target tensor cores.
//   K1: q    = cur @ Wq^T                       (8192 x 1024 x 1024, NT)
//   K2: qk_h = q_h @ Wk_h    (NN, K=64, x16)    -> bf16
//   K3: fused attention (2 barriers, full prefetch) -> hbar bf16
//   K4: out_h = hbar_h @ Wv_h^T (NT, N=64, x16), A operand bf16->tf32 -> fp32
//   K5: final = cur + out @ Wo^T                (NT + residual)
// ============================================================================

#define D_DIM   1024
#define H_HEADS 16
#define HD      64
#define NPREV   8
#define M_MAX   8192

__device__ float         g_q[M_MAX * D_DIM];                       // q, then out
__device__ __nv_bfloat16 g_qk[(size_t)M_MAX * H_HEADS * D_DIM];    // qk (bf16)
__device__ __nv_bfloat16 g_hb[(size_t)M_MAX * H_HEADS * D_DIM];    // hbar (bf16)

// ---------------------------------------------------------------------------
__device__ __forceinline__ uint32_t smem_u32(const void* p) {
    uint32_t a;
    asm("{ .reg .u64 t; cvta.to.shared.u64 t, %1; cvt.u32.u64 %0, t; }"
        : "=r"(a) : "l"(p));
    return a;
}
__device__ __forceinline__ void cp16(uint32_t s, const void* g) {
    asm volatile("cp.async.cg.shared.global [%0], [%1], 16;\n" :: "r"(s), "l"(g));
}
__device__ __forceinline__ void cp_commit() {
    asm volatile("cp.async.commit_group;\n" ::: "memory");
}
template <int N> __device__ __forceinline__ void cp_wait() {
    asm volatile("cp.async.wait_group %0;\n" :: "n"(N) : "memory");
}
__device__ __forceinline__ void mma_tf32(float* c, const uint32_t* a,
                                         const uint32_t* b) {
    asm volatile(
        "mma.sync.aligned.m16n8k8.row.col.f32.tf32.tf32.f32 "
        "{%0,%1,%2,%3}, {%4,%5,%6,%7}, {%8,%9}, {%0,%1,%2,%3};\n"
        : "+f"(c[0]), "+f"(c[1]), "+f"(c[2]), "+f"(c[3])
        : "r"(a[0]), "r"(a[1]), "r"(a[2]), "r"(a[3]), "r"(b[0]), "r"(b[1]));
}

// ---------------------------------------------------------------------------
// Tiled mma.sync tf32 GEMM: C[m,n] = sum_k A[m,k] * B'[n,k]
//   B_NN=false : B'[n,k] = B[n*ldb + k]   (NT, k contiguous -> cp.async)
//   B_NN=true  : B'[n,k] = B[k*ldb + n]   (NN, manual transpose STS)
//   A_BF16     : A in GMEM/SMEM is bf16; converted to fp32 at fragment load.
// CTA tile 128 x BN x 32. 256 threads (8 warps).
// SMEM strides: fp32 A/B = 36 floats (pad 4); bf16 A = 40 halves (80B rows).
// ---------------------------------------------------------------------------
template <int BN, bool B_NN, bool A_BF16, bool OUT_BF16, bool RESID>
__global__ void __launch_bounds__(256)
gemm_mma(const void* __restrict__ Aptr, int lda, long long sA,
         const float* __restrict__ B, int ldb, long long sB,
         const float* __restrict__ R,
         void* __restrict__ C, int ldc, long long sC,
         int K)
{
    constexpr int WM = (BN == 128) ? 2 : 4;        // warps along M
    constexpr int MT = 8 / WM;                     // 16-row mma tiles per warp
    constexpr int A_BYTES = A_BF16 ? (128 * 40 * 2) : (128 * 36 * 4);
    constexpr int B_BYTES = BN * 36 * 4;

    extern __shared__ __align__(16) char smem_c[];
    const uint32_t sbase = smem_u32(smem_c);

    const int tid = threadIdx.x;
    const int wid = tid >> 5, lane = tid & 31;
    const int wm = wid % WM, wn = wid / WM;
    const int bx = blockIdx.x, by = blockIdx.y, bz = blockIdx.z;

    const float*         Af = A_BF16 ? nullptr
        : (const float*)Aptr + (long long)bz * sA + (size_t)(by * 128) * lda;
    const __nv_bfloat16* Ah = A_BF16
        ? (const __nv_bfloat16*)Aptr + (long long)bz * sA + (size_t)(by * 128) * lda
        : nullptr;
    const float* Bg = B_NN ? (B + (long long)bz * sB + bx * BN)
                           : (B + (long long)bz * sB + (size_t)(bx * BN) * ldb);

    auto fill = [&](int buf, int k0) {
        const uint32_t As_b = sbase + (uint32_t)(buf * A_BYTES);
        const uint32_t Bs_b = sbase + (uint32_t)(2 * A_BYTES + buf * B_BYTES);
        // ---- A tile: 128 rows x 32 elements ----
        if (!A_BF16) {
#pragma unroll
            for (int p = 0; p < 4; ++p) {
                int ch = tid + p * 256;
                int row = ch >> 3, c4 = ch & 7;
                cp16(As_b + (uint32_t)(row * 36 + c4 * 4) * 4u,
                     Af + (size_t)row * lda + k0 + c4 * 4);
            }
        } else {
            // 128 rows x 32 halves, 4 x 16B chunks per row, 512 chunks
#pragma unroll
            for (int p = 0; p < 2; ++p) {
                int ch = tid + p * 256;
                int row = ch >> 2, c8 = ch & 3;
                cp16(As_b + (uint32_t)(row * 80 + c8 * 16),
                     Ah + (size_t)row * lda + k0 + c8 * 8);
            }
        }
        // ---- B tile ----
        if (!B_NN) {
#pragma unroll
            for (int p = 0; p < BN * 8 / 256; ++p) {
                int ch = tid + p * 256;
                int row = ch >> 3, c4 = ch & 7;
                cp16(Bs_b + (uint32_t)(row * 36 + c4 * 4) * 4u,
                     Bg + (size_t)row * ldb + k0 + c4 * 4);
            }
        } else {
            float* Bs_p = (float*)(smem_c + 2 * A_BYTES + buf * B_BYTES);
#pragma unroll
            for (int p = 0; p < BN * 32 / 256; ++p) {
                int idx = tid + p * 256;
                int n = idx % BN, k = idx / BN;
                Bs_p[n * 36 + k] = Bg[(size_t)(k0 + k) * ldb + n];
            }
        }
    };

    float acc[MT][4][4];
#pragma unroll
    for (int mt = 0; mt < MT; ++mt)
#pragma unroll
        for (int nt = 0; nt < 4; ++nt)
#pragma unroll
            for (int j = 0; j < 4; ++j) acc[mt][nt][j] = 0.0f;

    const int g  = lane >> 2, tg = lane & 3;
    const int a_off_f = (wm * (128 / WM) + g) * 36 + tg;   // fp32 A (floats)
    const int a_off_h = (wm * (128 / WM) + g) * 40 + tg;   // bf16 A (halves)
    const int b_off   = (wn * 32 + g) * 36 + tg;

    const int NC = K / 32;
    fill(0, 0);
    cp_commit();

    for (int c = 0; c < NC; ++c) {
        if (c + 1 < NC) { fill((c + 1) & 1, (c + 1) * 32); cp_commit(); cp_wait<1>(); }
        else            { cp_wait<0>(); }
        __syncthreads();

        const int buf = c & 1;
        const float*         As_f = (const float*)(smem_c + buf * A_BYTES);
        const __nv_bfloat16* As_h = (const __nv_bfloat16*)(smem_c + buf * A_BYTES);
        const float*         Bs_c = (const float*)(smem_c + 2 * A_BYTES + buf * B_BYTES);

#pragma unroll
        for (int s = 0; s < 4; ++s) {
            uint32_t af[MT][4];
#pragma unroll
            for (int mt = 0; mt < MT; ++mt) {
                if (!A_BF16) {
                    const float* p = As_f + a_off_f + mt * 16 * 36 + s * 8;
                    af[mt][0] = __float_as_uint(p[0]);
                    af[mt][1] = __float_as_uint(p[8 * 36]);
                    af[mt][2] = __float_as_uint(p[4]);
                    af[mt][3] = __float_as_uint(p[8 * 36 + 4]);
                } else {
                    const __nv_bfloat16* p = As_h + a_off_h + mt * 16 * 40 + s * 8;
                    af[mt][0] = __float_as_uint(__bfloat162float(p[0]));
                    af[mt][1] = __float_as_uint(__bfloat162float(p[8 * 40]));
                    af[mt][2] = __float_as_uint(__bfloat162float(p[4]));
                    af[mt][3] = __float_as_uint(__bfloat162float(p[8 * 40 + 4]));
                }
            }
            uint32_t bf[4][2];
#pragma unroll
            for (int nt = 0; nt < 4; ++nt) {
                const float* p = Bs_c + b_off + nt * 8 * 36 + s * 8;
                bf[nt][0] = __float_as_uint(p[0]);
                bf[nt][1] = __float_as_uint(p[4]);
            }
#pragma unroll
            for (int mt = 0; mt < MT; ++mt)
#pragma unroll
                for (int nt = 0; nt < 4; ++nt)
                    mma_tf32(acc[mt][nt], af[mt], bf[nt]);
        }
        __syncthreads();
    }

    // ---- epilogue ----
    const int row0 = by * 128 + wm * (128 / WM) + g;
    const int coll = wn * 32 + tg * 2;
#pragma unroll
    for (int mt = 0; mt < MT; ++mt) {
        const int m = row0 + mt * 16;
#pragma unroll
        for (int nt = 0; nt < 4; ++nt) {
            const int n = bx * BN + coll + nt * 8;
            if (!OUT_BF16) {
                float* Cg = (float*)C + (long long)bz * sC;
                float2 v0 = make_float2(acc[mt][nt][0], acc[mt][nt][1]);
                float2 v1 = make_float2(acc[mt][nt][2], acc[mt][nt][3]);
                if (RESID) {
                    float2 r0 = *(const float2*)(R + (size_t)m * ldc + n);
                    float2 r1 = *(const float2*)(R + (size_t)(m + 8) * ldc + n);
                    v0.x += r0.x; v0.y += r0.y;
                    v1.x += r1.x; v1.y += r1.y;
                }
                *(float2*)(Cg + (size_t)m * ldc + n)       = v0;
                *(float2*)(Cg + (size_t)(m + 8) * ldc + n) = v1;
            } else {
                __nv_bfloat16* Cg = (__nv_bfloat16*)C + (long long)bz * sC;
                *(__nv_bfloat162*)(Cg + (size_t)m * ldc + n) =
                    __float22bfloat162_rn(make_float2(acc[mt][nt][0], acc[mt][nt][1]));
                *(__nv_bfloat162*)(Cg + (size_t)(m + 8) * ldc + n) =
                    __float22bfloat162_rn(make_float2(acc[mt][nt][2], acc[mt][nt][3]));
            }
        }
    }
}

// ---------------------------------------------------------------------------
// K3: fused attention — 2-barrier structure, full prefetch. hbar -> bf16.
// ---------------------------------------------------------------------------
__global__ void __launch_bounds__(256) attn_kernel(
    const float* __restrict__ hist, const __nv_bfloat16* __restrict__ qk,
    __nv_bfloat16* __restrict__ hbar)
{
    __shared__ float red[H_HEADS][NPREV][8];
    __shared__ __align__(16) float attn_s[H_HEADS][NPREV];

    const int m    = blockIdx.x;
    const int tid  = threadIdx.x;
    const int lane = tid & 31;
    const int warp = tid >> 5;

    // ---- prefetch: 16 qk heads + 8 history vectors ----
    const __nv_bfloat16* qrow = qk + (size_t)m * (H_HEADS * D_DIM) + tid * 4;
    uint2 q2[H_HEADS];
#pragma unroll
    for (int h = 0; h < H_HEADS; h++)
        q2[h] = *(const uint2*)(qrow + h * D_DIM);

    float4 hv[NPREV];
    const float* hg = hist + (size_t)m * NPREV * D_DIM + tid * 4;
#pragma unroll
    for (int n = 0; n < NPREV; n++)
        hv[n] = *(const float4*)(hg + n * D_DIM);

    // ---- Phase A: partial dots + warp reductions ----
#pragma unroll
    for (int h = 0; h < H_HEADS; h++) {
        float2 qa = __bfloat1622float2(*reinterpret_cast<__nv_bfloat162*>(&q2[h].x));
        float2 qb = __bfloat1622float2(*reinterpret_cast<__nv_bfloat162*>(&q2[h].y));
        float part[NPREV];
#pragma unroll
        for (int n = 0; n < NPREV; n++)
            part[n] = qa.x * hv[n].x + qa.y * hv[n].y
                    + qb.x * hv[n].z + qb.y * hv[n].w;
#pragma unroll
        for (int n = 0; n < NPREV; n++) {
            float v = part[n];
#pragma unroll
            for (int o = 16; o > 0; o >>= 1)
                v += __shfl_xor_sync(0xffffffffu, v, o);
            if (lane == 0) red[h][n][warp] = v;
        }
    }
    __syncthreads();

    // ---- Phase B: 16 parallel softmaxes ----
    if (tid < H_HEADS) {
        const int h = tid;
        float lg[NPREV];
        float mx = -1e30f;
#pragma unroll
        for (int n = 0; n < NPREV; n++) {
            float4 s0 = *(const float4*)&red[h][n][0];
            float4 s1 = *(const float4*)&red[h][n][4];
            float s = (s0.x + s0.y) + (s0.z + s0.w)
                    + (s1.x + s1.y) + (s1.z + s1.w);
            lg[n] = s * 0.125f;                   // 1/sqrt(Hd=64)
            mx = fmaxf(mx, lg[n]);
        }
        float den = 0.0f;
#pragma unroll
        for (int n = 0; n < NPREV; n++) { lg[n] = expf(lg[n] - mx); den += lg[n]; }
        float inv = 1.0f / den;
#pragma unroll
        for (int n = 0; n < NPREV; n++) attn_s[h][n] = lg[n] * inv;
    }
    __syncthreads();

    // ---- Phase C: weighted sums + bf16 stores ----
    __nv_bfloat16* orow = hbar + (size_t)m * (H_HEADS * D_DIM) + tid * 4;
#pragma unroll
    for (int h = 0; h < H_HEADS; h++) {
        float4 w0 = *(const float4*)&attn_s[h][0];
        float4 w1 = *(const float4*)&attn_s[h][4];
        float4 a4;
        a4.x = w0.x * hv[0].x; a4.y = w0.x * hv[0].y;
        a4.z = w0.x * hv[0].z; a4.w = w0.x * hv[0].w;
        a4.x = fmaf(w0.y, hv[1].x, a4.x); a4.y = fmaf(w0.y, hv[1].y, a4.y);
        a4.z = fmaf(w0.y, hv[1].z, a4.z); a4.w = fmaf(w0.y, hv[1].w, a4.w);
        a4.x = fmaf(w0.z, hv[2].x, a4.x); a4.y = fmaf(w0.z, hv[2].y, a4.y);
        a4.z = fmaf(w0.z, hv[2].z, a4.z); a4.w = fmaf(w0.z, hv[2].w, a4.w);
        a4.x = fmaf(w0.w, hv[3].x, a4.x); a4.y = fmaf(w0.w, hv[3].y, a4.y);
        a4.z = fmaf(w0.w, hv[3].z, a4.z); a4.w = fmaf(w0.w, hv[3].w, a4.w);
        a4.x = fmaf(w1.x, hv[4].x, a4.x); a4.y = fmaf(w1.x, hv[4].y, a4.y);
        a4.z = fmaf(w1.x, hv[4].z, a4.z); a4.w = fmaf(w1.x, hv[4].w, a4.w);
        a4.x = fmaf(w1.y, hv[5].x, a4.x); a4.y = fmaf(w1.y, hv[5].y, a4.y);
        a4.z = fmaf(w1.y, hv[5].z, a4.z); a4.w = fmaf(w1.y, hv[5].w, a4.w);
        a4.x = fmaf(w1.z, hv[6].x, a4.x); a4.y = fmaf(w1.z, hv[6].y, a4.y);
        a4.z = fmaf(w1.z, hv[6].z, a4.z); a4.w = fmaf(w1.z, hv[6].w, a4.w);
        a4.x = fmaf(w1.w, hv[7].x, a4.x); a4.y = fmaf(w1.w, hv[7].y, a4.y);
        a4.z = fmaf(w1.w, hv[7].z, a4.z); a4.w = fmaf(w1.w, hv[7].w, a4.w);
        uint2 ov;
        __nv_bfloat162 o0 = __float22bfloat162_rn(make_float2(a4.x, a4.y));
        __nv_bfloat162 o1 = __float22bfloat162_rn(make_float2(a4.z, a4.w));
        ov.x = *reinterpret_cast<uint32_t*>(&o0);
        ov.y = *reinterpret_cast<uint32_t*>(&o1);
        *(uint2*)(orow + h * D_DIM) = ov;
    }
}

// ---------------------------------------------------------------------------
extern "C" void kernel_launch(void* const* d_in, const int* in_sizes, int n_in,
                              void* d_out, int out_size)
{
    const float* cur  = (const float*)d_in[0];
    const float* hist = (const float*)d_in[1];
    const float* Wq   = (const float*)d_in[2];
    const float* Wk   = (const float*)d_in[3];
    const float* Wv   = (const float*)d_in[4];
    const float* Wo   = (const float*)d_in[5];
    float* out = (float*)d_out;

    const int D = D_DIM;
    const int M = in_sizes[0] / D;   // 8192

    float* q = nullptr;
    __nv_bfloat16 *qk = nullptr, *hb = nullptr;
    cudaGetSymbolAddress((void**)&q,  g_q);
    cudaGetSymbolAddress((void**)&qk, g_qk);
    cudaGetSymbolAddress((void**)&hb, g_hb);

    constexpr int SM128  = 2 * (128 * 36 * 4) + 2 * (128 * 36 * 4);  // 73728
    constexpr int SM64_H = 2 * (128 * 40 * 2) + 2 * (64 * 36 * 4);   // 38912

    cudaFuncSetAttribute(gemm_mma<128, false, false, false, false>,
                         cudaFuncAttributeMaxDynamicSharedMemorySize, SM128);
    cudaFuncSetAttribute(gemm_mma<128, true,  false, true,  false>,
                         cudaFuncAttributeMaxDynamicSharedMemorySize, SM128);
    cudaFuncSetAttribute(gemm_mma<64,  false, true,  false, false>,
                         cudaFuncAttributeMaxDynamicSharedMemorySize, SM64_H);
    cudaFuncSetAttribute(gemm_mma<128, false, false, false, true>,
                         cudaFuncAttributeMaxDynamicSharedMemorySize, SM128);

    // K1: q = cur @ Wq^T
    gemm_mma<128, false, false, false, false>
        <<<dim3(D / 128, M / 128, 1), 256, SM128>>>(
            cur, D, 0, Wq, D, 0, nullptr, q, D, 0, D);

    // K2: qk_h = q_h @ Wk_h  (NN, K=64, x16 heads) -> bf16
    gemm_mma<128, true, false, true, false>
        <<<dim3(D / 128, M / 128, H_HEADS), 256, SM128>>>(
            q, D, HD,
            Wk, D, (long long)HD * D,
            nullptr,
            qk, H_HEADS * D, D,
            HD);

    // K3: attention -> hbar (bf16)
    attn_kernel<<<M, 256>>>(hist, qk, hb);

    // K4: out_h = hbar_h @ Wv_h^T (NT, N=64, x16), A bf16 -> g_q fp32
    gemm_mma<64, false, true, false, false>
        <<<dim3(1, M / 128, H_HEADS), 256, SM64_H>>>(
            hb, H_HEADS * D, D,
            Wv, D, (long long)HD * D,
            nullptr,
            q, D, HD,
            D);

    // K5: final = cur + out @ Wo^T
    gemm_mma<128, false, false, false, true>
        <<<dim3(D / 128, M / 128, 1), 256, SM128>>>(
            q, D, 0, Wo, D, 0, cur, out, D, 0, D);
}

// round 8
// speedup vs baseline: 1.7995x; 1.1063x over previous
#include <cuda_runtime.h>
#include <cuda_bf16.h>
#include <cstdint>

// ============================================================================
// CrossDepthAttention via mma.sync — base-target tensor cores.
//   P0: transpose Wk -> g_wkt (fp32), convert Wv -> g_wv (bf16)
//   K1: q    = cur @ Wq^T          tf32  (8192 x 1024 x 1024, NT)
//   K2: qk_h = q_h @ Wk_h          tf32  (NT via WkT, K=64, x16) -> bf16
//   K3: fused attention (2 barriers, full prefetch) -> hbar bf16
//   K4: out_h = hbar_h @ Wv_h^T    bf16 m16n8k16 (N=64, x16) -> fp32
//   K5: final = cur + out @ Wo^T   tf32  (NT + residual)
// ============================================================================

#define D_DIM   1024
#define H_HEADS 16
#define HD      64
#define NPREV   8
#define M_MAX   8192

__device__ float         g_q[M_MAX * D_DIM];                       // q, then out
__device__ __nv_bfloat16 g_qk[(size_t)M_MAX * H_HEADS * D_DIM];    // qk (bf16)
__device__ __nv_bfloat16 g_hb[(size_t)M_MAX * H_HEADS * D_DIM];    // hbar (bf16)
__device__ float         g_wkt[D_DIM * D_DIM];                     // Wk^T (fp32)
__device__ __nv_bfloat16 g_wv[D_DIM * D_DIM];                      // Wv (bf16)

// ---------------------------------------------------------------------------
__device__ __forceinline__ uint32_t smem_u32(const void* p) {
    uint32_t a;
    asm("{ .reg .u64 t; cvta.to.shared.u64 t, %1; cvt.u32.u64 %0, t; }"
        : "=r"(a) : "l"(p));
    return a;
}
__device__ __forceinline__ void cp16(uint32_t s, const void* g) {
    asm volatile("cp.async.cg.shared.global [%0], [%1], 16;\n" :: "r"(s), "l"(g));
}
__device__ __forceinline__ void cp_commit() {
    asm volatile("cp.async.commit_group;\n" ::: "memory");
}
template <int N> __device__ __forceinline__ void cp_wait() {
    asm volatile("cp.async.wait_group %0;\n" :: "n"(N) : "memory");
}
__device__ __forceinline__ void mma_tf32(float* c, const uint32_t* a,
                                         const uint32_t* b) {
    asm volatile(
        "mma.sync.aligned.m16n8k8.row.col.f32.tf32.tf32.f32 "
        "{%0,%1,%2,%3}, {%4,%5,%6,%7}, {%8,%9}, {%0,%1,%2,%3};\n"
        : "+f"(c[0]), "+f"(c[1]), "+f"(c[2]), "+f"(c[3])
        : "r"(a[0]), "r"(a[1]), "r"(a[2]), "r"(a[3]), "r"(b[0]), "r"(b[1]));
}
__device__ __forceinline__ void mma_bf16(float* c, const uint32_t* a,
                                         const uint32_t* b) {
    asm volatile(
        "mma.sync.aligned.m16n8k16.row.col.f32.bf16.bf16.f32 "
        "{%0,%1,%2,%3}, {%4,%5,%6,%7}, {%8,%9}, {%0,%1,%2,%3};\n"
        : "+f"(c[0]), "+f"(c[1]), "+f"(c[2]), "+f"(c[3])
        : "r"(a[0]), "r"(a[1]), "r"(a[2]), "r"(a[3]), "r"(b[0]), "r"(b[1]));
}

// ---------------------------------------------------------------------------
// P0a: Wk transpose (fp32), tiled 32x32.
// ---------------------------------------------------------------------------
__global__ void __launch_bounds__(256) transpose_wk(
    const float* __restrict__ in, float* __restrict__ outp)
{
    __shared__ float t[32][33];
    const int bx = blockIdx.x * 32, by = blockIdx.y * 32;
    int x = bx + threadIdx.x;
#pragma unroll
    for (int i = 0; i < 32; i += 8)
        t[threadIdx.y + i][threadIdx.x] = in[(size_t)(by + threadIdx.y + i) * D_DIM + x];
    __syncthreads();
    x = by + threadIdx.x;
#pragma unroll
    for (int i = 0; i < 32; i += 8)
        outp[(size_t)(bx + threadIdx.y + i) * D_DIM + x] = t[threadIdx.x][threadIdx.y + i];
}

// P0b: Wv -> bf16
__global__ void __launch_bounds__(256) convert_wv(
    const float* __restrict__ in, __nv_bfloat16* __restrict__ outp)
{
    int i = (blockIdx.x * 256 + threadIdx.x) * 4;
    float4 v = *(const float4*)(in + i);
    __nv_bfloat162 p0 = __float22bfloat162_rn(make_float2(v.x, v.y));
    __nv_bfloat162 p1 = __float22bfloat162_rn(make_float2(v.z, v.w));
    *(__nv_bfloat162*)(outp + i)     = p0;
    *(__nv_bfloat162*)(outp + i + 2) = p1;
}

// ---------------------------------------------------------------------------
// Tiled mma.sync tf32 GEMM (NT): C[m,n] = sum_k A[m,k] * B[n*ldb + k]
// CTA tile 128 x BN x 32, 256 threads, SMEM stride 36 floats, double buffer.
// ---------------------------------------------------------------------------
template <int BN, bool OUT_BF16, bool RESID>
__global__ void __launch_bounds__(256)
gemm_mma(const float* __restrict__ A, int lda, long long sA,
         const float* __restrict__ B, int ldb, long long sB,
         const float* __restrict__ R,
         void* __restrict__ C, int ldc, long long sC,
         int K)
{
    constexpr int WM = (BN == 128) ? 2 : 4;
    constexpr int MT = 8 / WM;
    constexpr int A_FLOATS = 128 * 36;
    constexpr int B_FLOATS = BN * 36;

    extern __shared__ float smem_f[];
    const uint32_t sbase = smem_u32(smem_f);

    const int tid = threadIdx.x;
    const int wid = tid >> 5, lane = tid & 31;
    const int wm = wid % WM, wn = wid / WM;
    const int bx = blockIdx.x, by = blockIdx.y, bz = blockIdx.z;

    const float* Af = A + (long long)bz * sA + (size_t)(by * 128) * lda;
    const float* Bg = B + (long long)bz * sB + (size_t)(bx * BN) * ldb;

    auto fill = [&](int buf, int k0) {
        const uint32_t As_b = sbase + (uint32_t)(buf * A_FLOATS) * 4u;
        const uint32_t Bs_b = sbase + (uint32_t)(2 * A_FLOATS + buf * B_FLOATS) * 4u;
#pragma unroll
        for (int p = 0; p < 4; ++p) {
            int ch = tid + p * 256;
            int row = ch >> 3, c4 = ch & 7;
            cp16(As_b + (uint32_t)(row * 36 + c4 * 4) * 4u,
                 Af + (size_t)row * lda + k0 + c4 * 4);
        }
#pragma unroll
        for (int p = 0; p < BN * 8 / 256; ++p) {
            int ch = tid + p * 256;
            int row = ch >> 3, c4 = ch & 7;
            cp16(Bs_b + (uint32_t)(row * 36 + c4 * 4) * 4u,
                 Bg + (size_t)row * ldb + k0 + c4 * 4);
        }
    };

    float acc[MT][4][4];
#pragma unroll
    for (int mt = 0; mt < MT; ++mt)
#pragma unroll
        for (int nt = 0; nt < 4; ++nt)
#pragma unroll
            for (int j = 0; j < 4; ++j) acc[mt][nt][j] = 0.0f;

    const int g = lane >> 2, tg = lane & 3;
    const int a_off = (wm * (128 / WM) + g) * 36 + tg;
    const int b_off = (wn * 32 + g) * 36 + tg;

    const int NC = K / 32;
    fill(0, 0);
    cp_commit();

    for (int c = 0; c < NC; ++c) {
        if (c + 1 < NC) { fill((c + 1) & 1, (c + 1) * 32); cp_commit(); cp_wait<1>(); }
        else            { cp_wait<0>(); }
        __syncthreads();

        const int buf = c & 1;
        const float* As_c = smem_f + buf * A_FLOATS;
        const float* Bs_c = smem_f + 2 * A_FLOATS + buf * B_FLOATS;

#pragma unroll
        for (int s = 0; s < 4; ++s) {
            uint32_t af[MT][4];
#pragma unroll
            for (int mt = 0; mt < MT; ++mt) {
                const float* p = As_c + a_off + mt * 16 * 36 + s * 8;
                af[mt][0] = __float_as_uint(p[0]);
                af[mt][1] = __float_as_uint(p[8 * 36]);
                af[mt][2] = __float_as_uint(p[4]);
                af[mt][3] = __float_as_uint(p[8 * 36 + 4]);
            }
            uint32_t bf[4][2];
#pragma unroll
            for (int nt = 0; nt < 4; ++nt) {
                const float* p = Bs_c + b_off + nt * 8 * 36 + s * 8;
                bf[nt][0] = __float_as_uint(p[0]);
                bf[nt][1] = __float_as_uint(p[4]);
            }
#pragma unroll
            for (int mt = 0; mt < MT; ++mt)
#pragma unroll
                for (int nt = 0; nt < 4; ++nt)
                    mma_tf32(acc[mt][nt], af[mt], bf[nt]);
        }
        __syncthreads();
    }

    const int row0 = by * 128 + wm * (128 / WM) + g;
    const int coll = wn * 32 + tg * 2;
#pragma unroll
    for (int mt = 0; mt < MT; ++mt) {
        const int m = row0 + mt * 16;
#pragma unroll
        for (int nt = 0; nt < 4; ++nt) {
            const int n = bx * BN + coll + nt * 8;
            if (!OUT_BF16) {
                float* Cg = (float*)C + (long long)bz * sC;
                float2 v0 = make_float2(acc[mt][nt][0], acc[mt][nt][1]);
                float2 v1 = make_float2(acc[mt][nt][2], acc[mt][nt][3]);
                if (RESID) {
                    float2 r0 = *(const float2*)(R + (size_t)m * ldc + n);
                    float2 r1 = *(const float2*)(R + (size_t)(m + 8) * ldc + n);
                    v0.x += r0.x; v0.y += r0.y;
                    v1.x += r1.x; v1.y += r1.y;
                }
                *(float2*)(Cg + (size_t)m * ldc + n)       = v0;
                *(float2*)(Cg + (size_t)(m + 8) * ldc + n) = v1;
            } else {
                __nv_bfloat16* Cg = (__nv_bfloat16*)C + (long long)bz * sC;
                *(__nv_bfloat162*)(Cg + (size_t)m * ldc + n) =
                    __float22bfloat162_rn(make_float2(acc[mt][nt][0], acc[mt][nt][1]));
                *(__nv_bfloat162*)(Cg + (size_t)(m + 8) * ldc + n) =
                    __float22bfloat162_rn(make_float2(acc[mt][nt][2], acc[mt][nt][3]));
            }
        }
    }
}

// ---------------------------------------------------------------------------
// K4: bf16 m16n8k16 GEMM (NT): C[m,n] = sum_k A[m,k]*B[n*ldb+k], A,B bf16.
// CTA tile 128 x 64, BK=64 halves, 256 threads, SMEM stride 72 halves
// (= 36 words; fragment LDS banks 4g+tg, conflict-free). Double buffered.
// ---------------------------------------------------------------------------
__global__ void __launch_bounds__(256)
gemm_k4_bf16(const __nv_bfloat16* __restrict__ A, int lda, long long sA,
             const __nv_bfloat16* __restrict__ B, int ldb, long long sB,
             float* __restrict__ C, int ldc, long long sC, int K)
{
    constexpr int A_HALVES = 128 * 72;
    constexpr int B_HALVES = 64 * 72;

    extern __shared__ __align__(16) __nv_bfloat16 sm_h[];
    const uint32_t sbase = smem_u32(sm_h);

    const int tid = threadIdx.x;
    const int wid = tid >> 5, lane = tid & 31;
    const int wm = wid & 3, wn = wid >> 2;          // 4 x 2 warp grid
    const int by = blockIdx.y, bz = blockIdx.z;

    const __nv_bfloat16* Ah = A + (long long)bz * sA + (size_t)(by * 128) * lda;
    const __nv_bfloat16* Bh = B + (long long)bz * sB;

    auto fill = [&](int buf, int k0) {
        const uint32_t Ab = sbase + (uint32_t)(buf * A_HALVES) * 2u;
        const uint32_t Bb = sbase + (uint32_t)(2 * A_HALVES + buf * B_HALVES) * 2u;
        // A: 128 rows x 64 halves = 1024 x 16B chunks
#pragma unroll
        for (int p = 0; p < 4; ++p) {
            int ch = tid + p * 256;
            int row = ch >> 3, c8 = ch & 7;
            cp16(Ab + (uint32_t)(row * 72 + c8 * 8) * 2u,
                 Ah + (size_t)row * lda + k0 + c8 * 8);
        }
        // B: 64 rows x 64 halves = 512 chunks
#pragma unroll
        for (int p = 0; p < 2; ++p) {
            int ch = tid + p * 256;
            int row = ch >> 3, c8 = ch & 7;
            cp16(Bb + (uint32_t)(row * 72 + c8 * 8) * 2u,
                 Bh + (size_t)row * ldb + k0 + c8 * 8);
        }
    };

    float acc[2][4][4];
#pragma unroll
    for (int mt = 0; mt < 2; ++mt)
#pragma unroll
        for (int nt = 0; nt < 4; ++nt)
#pragma unroll
            for (int j = 0; j < 4; ++j) acc[mt][nt][j] = 0.0f;

    const int g = lane >> 2, tg = lane & 3;
    const int a_off = (wm * 32 + g) * 36 + tg;      // word index
    const int b_off = (wn * 32 + g) * 36 + tg;

    const int NC = K / 64;
    fill(0, 0);
    cp_commit();

    for (int c = 0; c < NC; ++c) {
        if (c + 1 < NC) { fill((c + 1) & 1, (c + 1) * 64); cp_commit(); cp_wait<1>(); }
        else            { cp_wait<0>(); }
        __syncthreads();

        const int buf = c & 1;
        const uint32_t* Aw = (const uint32_t*)sm_h + buf * (A_HALVES / 2);
        const uint32_t* Bw = (const uint32_t*)sm_h + A_HALVES + buf * (B_HALVES / 2);

#pragma unroll
        for (int s = 0; s < 4; ++s) {               // 4 x k16 per 64-half chunk
            uint32_t af[2][4];
#pragma unroll
            for (int mt = 0; mt < 2; ++mt) {
                const uint32_t* p = Aw + a_off + mt * 16 * 36 + s * 8;
                af[mt][0] = p[0];
                af[mt][1] = p[8 * 36];
                af[mt][2] = p[4];
                af[mt][3] = p[8 * 36 + 4];
            }
            uint32_t bfr[4][2];
#pragma unroll
            for (int nt = 0; nt < 4; ++nt) {
                const uint32_t* p = Bw + b_off + nt * 8 * 36 + s * 8;
                bfr[nt][0] = p[0];
                bfr[nt][1] = p[4];
            }
#pragma unroll
            for (int mt = 0; mt < 2; ++mt)
#pragma unroll
                for (int nt = 0; nt < 4; ++nt)
                    mma_bf16(acc[mt][nt], af[mt], bfr[nt]);
        }
        __syncthreads();
    }

    const int row0 = by * 128 + wm * 32 + g;
    const int coll = wn * 32 + tg * 2;
#pragma unroll
    for (int mt = 0; mt < 2; ++mt) {
        const int m = row0 + mt * 16;
        float* Cg = C + (long long)bz * sC;
#pragma unroll
        for (int nt = 0; nt < 4; ++nt) {
            const int n = coll + nt * 8;
            *(float2*)(Cg + (size_t)m * ldc + n) =
                make_float2(acc[mt][nt][0], acc[mt][nt][1]);
            *(float2*)(Cg + (size_t)(m + 8) * ldc + n) =
                make_float2(acc[mt][nt][2], acc[mt][nt][3]);
        }
    }
}

// ---------------------------------------------------------------------------
// K3: fused attention — 2-barrier structure, full prefetch. hbar -> bf16.
// ---------------------------------------------------------------------------
__global__ void __launch_bounds__(256) attn_kernel(
    const float* __restrict__ hist, const __nv_bfloat16* __restrict__ qk,
    __nv_bfloat16* __restrict__ hbar)
{
    __shared__ float red[H_HEADS][NPREV][8];
    __shared__ __align__(16) float attn_s[H_HEADS][NPREV];

    const int m    = blockIdx.x;
    const int tid  = threadIdx.x;
    const int lane = tid & 31;
    const int warp = tid >> 5;

    const __nv_bfloat16* qrow = qk + (size_t)m * (H_HEADS * D_DIM) + tid * 4;
    uint2 q2[H_HEADS];
#pragma unroll
    for (int h = 0; h < H_HEADS; h++)
        q2[h] = *(const uint2*)(qrow + h * D_DIM);

    float4 hv[NPREV];
    const float* hg = hist + (size_t)m * NPREV * D_DIM + tid * 4;
#pragma unroll
    for (int n = 0; n < NPREV; n++)
        hv[n] = *(const float4*)(hg + n * D_DIM);

#pragma unroll
    for (int h = 0; h < H_HEADS; h++) {
        float2 qa = __bfloat1622float2(*reinterpret_cast<__nv_bfloat162*>(&q2[h].x));
        float2 qb = __bfloat1622float2(*reinterpret_cast<__nv_bfloat162*>(&q2[h].y));
        float part[NPREV];
#pragma unroll
        for (int n = 0; n < NPREV; n++)
            part[n] = qa.x * hv[n].x + qa.y * hv[n].y
                    + qb.x * hv[n].z + qb.y * hv[n].w;
#pragma unroll
        for (int n = 0; n < NPREV; n++) {
            float v = part[n];
#pragma unroll
            for (int o = 16; o > 0; o >>= 1)
                v += __shfl_xor_sync(0xffffffffu, v, o);
            if (lane == 0) red[h][n][warp] = v;
        }
    }
    __syncthreads();

    if (tid < H_HEADS) {
        const int h = tid;
        float lg[NPREV];
        float mx = -1e30f;
#pragma unroll
        for (int n = 0; n < NPREV; n++) {
            float4 s0 = *(const float4*)&red[h][n][0];
            float4 s1 = *(const float4*)&red[h][n][4];
            float s = (s0.x + s0.y) + (s0.z + s0.w)
                    + (s1.x + s1.y) + (s1.z + s1.w);
            lg[n] = s * 0.125f;
            mx = fmaxf(mx, lg[n]);
        }
        float den = 0.0f;
#pragma unroll
        for (int n = 0; n < NPREV; n++) { lg[n] = expf(lg[n] - mx); den += lg[n]; }
        float inv = 1.0f / den;
#pragma unroll
        for (int n = 0; n < NPREV; n++) attn_s[h][n] = lg[n] * inv;
    }
    __syncthreads();

    __nv_bfloat16* orow = hbar + (size_t)m * (H_HEADS * D_DIM) + tid * 4;
#pragma unroll
    for (int h = 0; h < H_HEADS; h++) {
        float4 w0 = *(const float4*)&attn_s[h][0];
        float4 w1 = *(const float4*)&attn_s[h][4];
        float4 a4;
        a4.x = w0.x * hv[0].x; a4.y = w0.x * hv[0].y;
        a4.z = w0.x * hv[0].z; a4.w = w0.x * hv[0].w;
        a4.x = fmaf(w0.y, hv[1].x, a4.x); a4.y = fmaf(w0.y, hv[1].y, a4.y);
        a4.z = fmaf(w0.y, hv[1].z, a4.z); a4.w = fmaf(w0.y, hv[1].w, a4.w);
        a4.x = fmaf(w0.z, hv[2].x, a4.x); a4.y = fmaf(w0.z, hv[2].y, a4.y);
        a4.z = fmaf(w0.z, hv[2].z, a4.z); a4.w = fmaf(w0.z, hv[2].w, a4.w);
        a4.x = fmaf(w0.w, hv[3].x, a4.x); a4.y = fmaf(w0.w, hv[3].y, a4.y);
        a4.z = fmaf(w0.w, hv[3].z, a4.z); a4.w = fmaf(w0.w, hv[3].w, a4.w);
        a4.x = fmaf(w1.x, hv[4].x, a4.x); a4.y = fmaf(w1.x, hv[4].y, a4.y);
        a4.z = fmaf(w1.x, hv[4].z, a4.z); a4.w = fmaf(w1.x, hv[4].w, a4.w);
        a4.x = fmaf(w1.y, hv[5].x, a4.x); a4.y = fmaf(w1.y, hv[5].y, a4.y);
        a4.z = fmaf(w1.y, hv[5].z, a4.z); a4.w = fmaf(w1.y, hv[5].w, a4.w);
        a4.x = fmaf(w1.z, hv[6].x, a4.x); a4.y = fmaf(w1.z, hv[6].y, a4.y);
        a4.z = fmaf(w1.z, hv[6].z, a4.z); a4.w = fmaf(w1.z, hv[6].w, a4.w);
        a4.x = fmaf(w1.w, hv[7].x, a4.x); a4.y = fmaf(w1.w, hv[7].y, a4.y);
        a4.z = fmaf(w1.w, hv[7].z, a4.z); a4.w = fmaf(w1.w, hv[7].w, a4.w);
        uint2 ov;
        __nv_bfloat162 o0 = __float22bfloat162_rn(make_float2(a4.x, a4.y));
        __nv_bfloat162 o1 = __float22bfloat162_rn(make_float2(a4.z, a4.w));
        ov.x = *reinterpret_cast<uint32_t*>(&o0);
        ov.y = *reinterpret_cast<uint32_t*>(&o1);
        *(uint2*)(orow + h * D_DIM) = ov;
    }
}

// ---------------------------------------------------------------------------
extern "C" void kernel_launch(void* const* d_in, const int* in_sizes, int n_in,
                              void* d_out, int out_size)
{
    const float* cur  = (const float*)d_in[0];
    const float* hist = (const float*)d_in[1];
    const float* Wq   = (const float*)d_in[2];
    const float* Wk   = (const float*)d_in[3];
    const float* Wv   = (const float*)d_in[4];
    const float* Wo   = (const float*)d_in[5];
    float* out = (float*)d_out;

    const int D = D_DIM;
    const int M = in_sizes[0] / D;   // 8192

    float *q = nullptr, *wkt = nullptr;
    __nv_bfloat16 *qk = nullptr, *hb = nullptr, *wv = nullptr;
    cudaGetSymbolAddress((void**)&q,   g_q);
    cudaGetSymbolAddress((void**)&qk,  g_qk);
    cudaGetSymbolAddress((void**)&hb,  g_hb);
    cudaGetSymbolAddress((void**)&wkt, g_wkt);
    cudaGetSymbolAddress((void**)&wv,  g_wv);

    constexpr int SM128 = 2 * (128 * 36 * 4) + 2 * (128 * 36 * 4);  // 73728
    constexpr int SMK4  = (2 * (128 * 72) + 2 * (64 * 72)) * 2;     // 55296

    cudaFuncSetAttribute(gemm_mma<128, false, false>,
                         cudaFuncAttributeMaxDynamicSharedMemorySize, SM128);
    cudaFuncSetAttribute(gemm_mma<128, true,  false>,
                         cudaFuncAttributeMaxDynamicSharedMemorySize, SM128);
    cudaFuncSetAttribute(gemm_mma<128, false, true>,
                         cudaFuncAttributeMaxDynamicSharedMemorySize, SM128);
    cudaFuncSetAttribute(gemm_k4_bf16,
                         cudaFuncAttributeMaxDynamicSharedMemorySize, SMK4);

    // P0: Wk transpose + Wv bf16 (independent of K1)
    transpose_wk<<<dim3(32, 32), dim3(32, 8)>>>(Wk, wkt);
    convert_wv<<<D * D / 4 / 256, 256>>>(Wv, wv);

    // K1: q = cur @ Wq^T
    gemm_mma<128, false, false>
        <<<dim3(D / 128, M / 128, 1), 256, SM128>>>(
            cur, D, 0, Wq, D, 0, nullptr, q, D, 0, D);

    // K2: qk_h = q_h @ Wk_h  (NT via WkT: B'[j,d] = WkT[j, h*64+d]) -> bf16
    gemm_mma<128, true, false>
        <<<dim3(D / 128, M / 128, H_HEADS), 256, SM128>>>(
            q, D, HD,                  // A = q[:, h*64 : (h+1)*64]
            wkt, D, HD,                // B = WkT[:, h*64 : (h+1)*64], rows j
            nullptr,
            qk, H_HEADS * D, D,
            HD);

    // K3: attention -> hbar (bf16)
    attn_kernel<<<M, 256>>>(hist, qk, hb);

    // K4: out_h = hbar_h @ Wv_h^T (bf16 m16n8k16) -> g_q fp32
    gemm_k4_bf16<<<dim3(1, M / 128, H_HEADS), 256, SMK4>>>(
            hb, H_HEADS * D, D,
            wv, D, (long long)HD * D,
            q, D, HD,
            D);

    // K5: final = cur + out @ Wo^T
    gemm_mma<128, false, true>
        <<<dim3(D / 128, M / 128, 1), 256, SM128>>>(
            q, D, 0, Wo, D, 0, cur, out, D, 0, D);
}

// round 9
// speedup vs baseline: 2.0213x; 1.1232x over previous
#include <cuda_runtime.h>
#include <cuda_bf16.h>
#include <cstdint>

// ============================================================================
// CrossDepthAttention, mma.sync tensor cores (base-target legal).
//   P0: Wk -> transpose+bf16 (g_wkt); Wv, Wo -> bf16
//   K1: q    = cur @ Wq^T            tf32 m16n8k8  -> q bf16
//   K2: qk_h = q_h @ Wk_h            bf16 m16n8k16 (NT via WkT, K=64, NC=1)
//   K3: fused attention (2 barriers) -> hbar bf16
//   K4: out_h = hbar_h @ Wv_h^T      bf16 m16n8k16 -> out bf16
//   K5: final = cur + out @ Wo^T     bf16 m16n8k16 + fp32 residual
// ============================================================================

#define D_DIM   1024
#define H_HEADS 16
#define HD      64
#define NPREV   8
#define M_MAX   8192

__device__ __nv_bfloat16 g_qb[M_MAX * D_DIM];                      // q (bf16)
__device__ __nv_bfloat16 g_qk[(size_t)M_MAX * H_HEADS * D_DIM];    // qk (bf16)
__device__ __nv_bfloat16 g_hb[(size_t)M_MAX * H_HEADS * D_DIM];    // hbar (bf16)
__device__ __nv_bfloat16 g_ob[M_MAX * D_DIM];                      // out (bf16)
__device__ __nv_bfloat16 g_wkt[D_DIM * D_DIM];                     // Wk^T (bf16)
__device__ __nv_bfloat16 g_wv[D_DIM * D_DIM];                      // Wv (bf16)
__device__ __nv_bfloat16 g_wo[D_DIM * D_DIM];                      // Wo (bf16)

// ---------------------------------------------------------------------------
__device__ __forceinline__ uint32_t smem_u32(const void* p) {
    uint32_t a;
    asm("{ .reg .u64 t; cvta.to.shared.u64 t, %1; cvt.u32.u64 %0, t; }"
        : "=r"(a) : "l"(p));
    return a;
}
__device__ __forceinline__ void cp16(uint32_t s, const void* g) {
    asm volatile("cp.async.cg.shared.global [%0], [%1], 16;\n" :: "r"(s), "l"(g));
}
__device__ __forceinline__ void cp_commit() {
    asm volatile("cp.async.commit_group;\n" ::: "memory");
}
template <int N> __device__ __forceinline__ void cp_wait() {
    asm volatile("cp.async.wait_group %0;\n" :: "n"(N) : "memory");
}
__device__ __forceinline__ void mma_tf32(float* c, const uint32_t* a,
                                         const uint32_t* b) {
    asm volatile(
        "mma.sync.aligned.m16n8k8.row.col.f32.tf32.tf32.f32 "
        "{%0,%1,%2,%3}, {%4,%5,%6,%7}, {%8,%9}, {%0,%1,%2,%3};\n"
        : "+f"(c[0]), "+f"(c[1]), "+f"(c[2]), "+f"(c[3])
        : "r"(a[0]), "r"(a[1]), "r"(a[2]), "r"(a[3]), "r"(b[0]), "r"(b[1]));
}
__device__ __forceinline__ void mma_bf16(float* c, const uint32_t* a,
                                         const uint32_t* b) {
    asm volatile(
        "mma.sync.aligned.m16n8k16.row.col.f32.bf16.bf16.f32 "
        "{%0,%1,%2,%3}, {%4,%5,%6,%7}, {%8,%9}, {%0,%1,%2,%3};\n"
        : "+f"(c[0]), "+f"(c[1]), "+f"(c[2]), "+f"(c[3])
        : "r"(a[0]), "r"(a[1]), "r"(a[2]), "r"(a[3]), "r"(b[0]), "r"(b[1]));
}

// ---------------------------------------------------------------------------
// P0a: Wk transpose + bf16 convert, tiled 32x32.
// ---------------------------------------------------------------------------
__global__ void __launch_bounds__(256) transpose_wk_bf16(
    const float* __restrict__ in, __nv_bfloat16* __restrict__ outp)
{
    __shared__ float t[32][33];
    const int bx = blockIdx.x * 32, by = blockIdx.y * 32;
    int x = bx + threadIdx.x;
#pragma unroll
    for (int i = 0; i < 32; i += 8)
        t[threadIdx.y + i][threadIdx.x] = in[(size_t)(by + threadIdx.y + i) * D_DIM + x];
    __syncthreads();
    x = by + threadIdx.x;
#pragma unroll
    for (int i = 0; i < 32; i += 8)
        outp[(size_t)(bx + threadIdx.y + i) * D_DIM + x] =
            __float2bfloat16(t[threadIdx.x][threadIdx.y + i]);
}

// P0b: Wv, Wo -> bf16
__global__ void __launch_bounds__(256) convert_w(
    const float* __restrict__ wv, const float* __restrict__ wo,
    __nv_bfloat16* __restrict__ ov, __nv_bfloat16* __restrict__ oo)
{
    int i = (blockIdx.x * 256 + threadIdx.x) * 4;
    float4 a = *(const float4*)(wv + i);
    float4 b = *(const float4*)(wo + i);
    *(__nv_bfloat162*)(ov + i)     = __float22bfloat162_rn(make_float2(a.x, a.y));
    *(__nv_bfloat162*)(ov + i + 2) = __float22bfloat162_rn(make_float2(a.z, a.w));
    *(__nv_bfloat162*)(oo + i)     = __float22bfloat162_rn(make_float2(b.x, b.y));
    *(__nv_bfloat162*)(oo + i + 2) = __float22bfloat162_rn(make_float2(b.z, b.w));
}

// ---------------------------------------------------------------------------
// tf32 GEMM (NT): C[m,n] = sum_k A[m,k] * B[n*ldb + k]. (K1 only.)
// CTA tile 128 x 128 x 32, 256 threads, SMEM stride 36 floats, double buffer.
// ---------------------------------------------------------------------------
template <bool OUT_BF16>
__global__ void __launch_bounds__(256)
gemm_tf32(const float* __restrict__ A, int lda,
          const float* __restrict__ B, int ldb,
          void* __restrict__ C, int ldc, int K)
{
    constexpr int A_FLOATS = 128 * 36;
    constexpr int B_FLOATS = 128 * 36;

    extern __shared__ float smem_f[];
    const uint32_t sbase = smem_u32(smem_f);

    const int tid = threadIdx.x;
    const int wid = tid >> 5, lane = tid & 31;
    const int wm = wid & 1, wn = wid >> 1;
    const int bx = blockIdx.x, by = blockIdx.y;

    const float* Af = A + (size_t)(by * 128) * lda;
    const float* Bg = B + (size_t)(bx * 128) * ldb;

    auto fill = [&](int buf, int k0) {
        const uint32_t As_b = sbase + (uint32_t)(buf * A_FLOATS) * 4u;
        const uint32_t Bs_b = sbase + (uint32_t)(2 * A_FLOATS + buf * B_FLOATS) * 4u;
#pragma unroll
        for (int p = 0; p < 4; ++p) {
            int ch = tid + p * 256;
            int row = ch >> 3, c4 = ch & 7;
            cp16(As_b + (uint32_t)(row * 36 + c4 * 4) * 4u,
                 Af + (size_t)row * lda + k0 + c4 * 4);
        }
#pragma unroll
        for (int p = 0; p < 4; ++p) {
            int ch = tid + p * 256;
            int row = ch >> 3, c4 = ch & 7;
            cp16(Bs_b + (uint32_t)(row * 36 + c4 * 4) * 4u,
                 Bg + (size_t)row * ldb + k0 + c4 * 4);
        }
    };

    float acc[4][4][4];
#pragma unroll
    for (int mt = 0; mt < 4; ++mt)
#pragma unroll
        for (int nt = 0; nt < 4; ++nt)
#pragma unroll
            for (int j = 0; j < 4; ++j) acc[mt][nt][j] = 0.0f;

    const int g = lane >> 2, tg = lane & 3;
    const int a_off = (wm * 64 + g) * 36 + tg;
    const int b_off = (wn * 32 + g) * 36 + tg;

    const int NC = K / 32;
    fill(0, 0);
    cp_commit();

    for (int c = 0; c < NC; ++c) {
        if (c + 1 < NC) { fill((c + 1) & 1, (c + 1) * 32); cp_commit(); cp_wait<1>(); }
        else            { cp_wait<0>(); }
        __syncthreads();

        const int buf = c & 1;
        const float* As_c = smem_f + buf * A_FLOATS;
        const float* Bs_c = smem_f + 2 * A_FLOATS + buf * B_FLOATS;

#pragma unroll
        for (int s = 0; s < 4; ++s) {
            uint32_t af[4][4];
#pragma unroll
            for (int mt = 0; mt < 4; ++mt) {
                const float* p = As_c + a_off + mt * 16 * 36 + s * 8;
                af[mt][0] = __float_as_uint(p[0]);
                af[mt][1] = __float_as_uint(p[8 * 36]);
                af[mt][2] = __float_as_uint(p[4]);
                af[mt][3] = __float_as_uint(p[8 * 36 + 4]);
            }
            uint32_t bf[4][2];
#pragma unroll
            for (int nt = 0; nt < 4; ++nt) {
                const float* p = Bs_c + b_off + nt * 8 * 36 + s * 8;
                bf[nt][0] = __float_as_uint(p[0]);
                bf[nt][1] = __float_as_uint(p[4]);
            }
#pragma unroll
            for (int mt = 0; mt < 4; ++mt)
#pragma unroll
                for (int nt = 0; nt < 4; ++nt)
                    mma_tf32(acc[mt][nt], af[mt], bf[nt]);
        }
        __syncthreads();
    }

    const int row0 = by * 128 + wm * 64 + g;
    const int coll = wn * 32 + tg * 2;
#pragma unroll
    for (int mt = 0; mt < 4; ++mt) {
        const int m = row0 + mt * 16;
#pragma unroll
        for (int nt = 0; nt < 4; ++nt) {
            const int n = bx * 128 + coll + nt * 8;
            if (!OUT_BF16) {
                float* Cg = (float*)C;
                *(float2*)(Cg + (size_t)m * ldc + n) =
                    make_float2(acc[mt][nt][0], acc[mt][nt][1]);
                *(float2*)(Cg + (size_t)(m + 8) * ldc + n) =
                    make_float2(acc[mt][nt][2], acc[mt][nt][3]);
            } else {
                __nv_bfloat16* Cg = (__nv_bfloat16*)C;
                *(__nv_bfloat162*)(Cg + (size_t)m * ldc + n) =
                    __float22bfloat162_rn(make_float2(acc[mt][nt][0], acc[mt][nt][1]));
                *(__nv_bfloat162*)(Cg + (size_t)(m + 8) * ldc + n) =
                    __float22bfloat162_rn(make_float2(acc[mt][nt][2], acc[mt][nt][3]));
            }
        }
    }
}

// ---------------------------------------------------------------------------
// bf16 m16n8k16 GEMM (NT): C[m,n] = sum_k A[m,k] * B[n*ldb + k]; A,B bf16.
// CTA tile 128 x BN, BK=64 halves, 256 threads, SMEM stride 72 halves.
// Double-buffer loop degrades cleanly to NC=1 (K=64).
// ---------------------------------------------------------------------------
template <int BN, bool OUT_BF16, bool RESID>
__global__ void __launch_bounds__(256)
gemm_bf16(const __nv_bfloat16* __restrict__ A, int lda, long long sA,
          const __nv_bfloat16* __restrict__ B, int ldb, long long sB,
          const float* __restrict__ R,
          void* __restrict__ C, int ldc, long long sC, int K)
{
    constexpr int WM = (BN == 128) ? 2 : 4;
    constexpr int MT = 8 / WM;
    constexpr int A_HALVES = 128 * 72;
    constexpr int B_HALVES = BN * 72;

    extern __shared__ __align__(16) __nv_bfloat16 sm_h[];
    const uint32_t sbase = smem_u32(sm_h);

    const int tid = threadIdx.x;
    const int wid = tid >> 5, lane = tid & 31;
    const int wm = wid % WM, wn = wid / WM;
    const int bx = blockIdx.x, by = blockIdx.y, bz = blockIdx.z;

    const __nv_bfloat16* Ah = A + (long long)bz * sA + (size_t)(by * 128) * lda;
    const __nv_bfloat16* Bh = B + (long long)bz * sB + (size_t)(bx * BN) * ldb;

    auto fill = [&](int buf, int k0) {
        const uint32_t Ab = sbase + (uint32_t)(buf * A_HALVES) * 2u;
        const uint32_t Bb = sbase + (uint32_t)(2 * A_HALVES + buf * B_HALVES) * 2u;
#pragma unroll
        for (int p = 0; p < 4; ++p) {
            int ch = tid + p * 256;
            int row = ch >> 3, c8 = ch & 7;
            cp16(Ab + (uint32_t)(row * 72 + c8 * 8) * 2u,
                 Ah + (size_t)row * lda + k0 + c8 * 8);
        }
#pragma unroll
        for (int p = 0; p < BN * 8 / 256; ++p) {
            int ch = tid + p * 256;
            int row = ch >> 3, c8 = ch & 7;
            cp16(Bb + (uint32_t)(row * 72 + c8 * 8) * 2u,
                 Bh + (size_t)row * ldb + k0 + c8 * 8);
        }
    };

    float acc[MT][4][4];
#pragma unroll
    for (int mt = 0; mt < MT; ++mt)
#pragma unroll
        for (int nt = 0; nt < 4; ++nt)
#pragma unroll
            for (int j = 0; j < 4; ++j) acc[mt][nt][j] = 0.0f;

    const int g = lane >> 2, tg = lane & 3;
    const int a_off = (wm * (128 / WM) + g) * 36 + tg;   // word index
    const int b_off = (wn * 32 + g) * 36 + tg;

    const int NC = K / 64;
    fill(0, 0);
    cp_commit();

    for (int c = 0; c < NC; ++c) {
        if (c + 1 < NC) { fill((c + 1) & 1, (c + 1) * 64); cp_commit(); cp_wait<1>(); }
        else            { cp_wait<0>(); }
        __syncthreads();

        const int buf = c & 1;
        const uint32_t* Aw = (const uint32_t*)sm_h + buf * (A_HALVES / 2);
        const uint32_t* Bw = (const uint32_t*)sm_h + A_HALVES + buf * (B_HALVES / 2);

#pragma unroll
        for (int s = 0; s < 4; ++s) {
            uint32_t af[MT][4];
#pragma unroll
            for (int mt = 0; mt < MT; ++mt) {
                const uint32_t* p = Aw + a_off + mt * 16 * 36 + s * 8;
                af[mt][0] = p[0];
                af[mt][1] = p[8 * 36];
                af[mt][2] = p[4];
                af[mt][3] = p[8 * 36 + 4];
            }
            uint32_t bfr[4][2];
#pragma unroll
            for (int nt = 0; nt < 4; ++nt) {
                const uint32_t* p = Bw + b_off + nt * 8 * 36 + s * 8;
                bfr[nt][0] = p[0];
                bfr[nt][1] = p[4];
            }
#pragma unroll
            for (int mt = 0; mt < MT; ++mt)
#pragma unroll
                for (int nt = 0; nt < 4; ++nt)
                    mma_bf16(acc[mt][nt], af[mt], bfr[nt]);
        }
        __syncthreads();
    }

    const int row0 = by * 128 + wm * (128 / WM) + g;
    const int coll = wn * 32 + tg * 2;
#pragma unroll
    for (int mt = 0; mt < MT; ++mt) {
        const int m = row0 + mt * 16;
#pragma unroll
        for (int nt = 0; nt < 4; ++nt) {
            const int n = bx * BN + coll + nt * 8;
            if (!OUT_BF16) {
                float* Cg = (float*)C + (long long)bz * sC;
                float2 v0 = make_float2(acc[mt][nt][0], acc[mt][nt][1]);
                float2 v1 = make_float2(acc[mt][nt][2], acc[mt][nt][3]);
                if (RESID) {
                    float2 r0 = *(const float2*)(R + (size_t)m * ldc + n);
                    float2 r1 = *(const float2*)(R + (size_t)(m + 8) * ldc + n);
                    v0.x += r0.x; v0.y += r0.y;
                    v1.x += r1.x; v1.y += r1.y;
                }
                *(float2*)(Cg + (size_t)m * ldc + n)       = v0;
                *(float2*)(Cg + (size_t)(m + 8) * ldc + n) = v1;
            } else {
                __nv_bfloat16* Cg = (__nv_bfloat16*)C + (long long)bz * sC;
                *(__nv_bfloat162*)(Cg + (size_t)m * ldc + n) =
                    __float22bfloat162_rn(make_float2(acc[mt][nt][0], acc[mt][nt][1]));
                *(__nv_bfloat162*)(Cg + (size_t)(m + 8) * ldc + n) =
                    __float22bfloat162_rn(make_float2(acc[mt][nt][2], acc[mt][nt][3]));
            }
        }
    }
}

// ---------------------------------------------------------------------------
// K3: fused attention — 2-barrier structure, full prefetch. hbar -> bf16.
// ---------------------------------------------------------------------------
__global__ void __launch_bounds__(256) attn_kernel(
    const float* __restrict__ hist, const __nv_bfloat16* __restrict__ qk,
    __nv_bfloat16* __restrict__ hbar)
{
    __shared__ float red[H_HEADS][NPREV][8];
    __shared__ __align__(16) float attn_s[H_HEADS][NPREV];

    const int m    = blockIdx.x;
    const int tid  = threadIdx.x;
    const int lane = tid & 31;
    const int warp = tid >> 5;

    const __nv_bfloat16* qrow = qk + (size_t)m * (H_HEADS * D_DIM) + tid * 4;
    uint2 q2[H_HEADS];
#pragma unroll
    for (int h = 0; h < H_HEADS; h++)
        q2[h] = *(const uint2*)(qrow + h * D_DIM);

    float4 hv[NPREV];
    const float* hg = hist + (size_t)m * NPREV * D_DIM + tid * 4;
#pragma unroll
    for (int n = 0; n < NPREV; n++)
        hv[n] = *(const float4*)(hg + n * D_DIM);

#pragma unroll
    for (int h = 0; h < H_HEADS; h++) {
        float2 qa = __bfloat1622float2(*reinterpret_cast<__nv_bfloat162*>(&q2[h].x));
        float2 qb = __bfloat1622float2(*reinterpret_cast<__nv_bfloat162*>(&q2[h].y));
        float part[NPREV];
#pragma unroll
        for (int n = 0; n < NPREV; n++)
            part[n] = qa.x * hv[n].x + qa.y * hv[n].y
                    + qb.x * hv[n].z + qb.y * hv[n].w;
#pragma unroll
        for (int n = 0; n < NPREV; n++) {
            float v = part[n];
#pragma unroll
            for (int o = 16; o > 0; o >>= 1)
                v += __shfl_xor_sync(0xffffffffu, v, o);
            if (lane == 0) red[h][n][warp] = v;
        }
    }
    __syncthreads();

    if (tid < H_HEADS) {
        const int h = tid;
        float lg[NPREV];
        float mx = -1e30f;
#pragma unroll
        for (int n = 0; n < NPREV; n++) {
            float4 s0 = *(const float4*)&red[h][n][0];
            float4 s1 = *(const float4*)&red[h][n][4];
            float s = (s0.x + s0.y) + (s0.z + s0.w)
                    + (s1.x + s1.y) + (s1.z + s1.w);
            lg[n] = s * 0.125f;
            mx = fmaxf(mx, lg[n]);
        }
        float den = 0.0f;
#pragma unroll
        for (int n = 0; n < NPREV; n++) { lg[n] = expf(lg[n] - mx); den += lg[n]; }
        float inv = 1.0f / den;
#pragma unroll
        for (int n = 0; n < NPREV; n++) attn_s[h][n] = lg[n] * inv;
    }
    __syncthreads();

    __nv_bfloat16* orow = hbar + (size_t)m * (H_HEADS * D_DIM) + tid * 4;
#pragma unroll
    for (int h = 0; h < H_HEADS; h++) {
        float4 w0 = *(const float4*)&attn_s[h][0];
        float4 w1 = *(const float4*)&attn_s[h][4];
        float4 a4;
        a4.x = w0.x * hv[0].x; a4.y = w0.x * hv[0].y;
        a4.z = w0.x * hv[0].z; a4.w = w0.x * hv[0].w;
        a4.x = fmaf(w0.y, hv[1].x, a4.x); a4.y = fmaf(w0.y, hv[1].y, a4.y);
        a4.z = fmaf(w0.y, hv[1].z, a4.z); a4.w = fmaf(w0.y, hv[1].w, a4.w);
        a4.x = fmaf(w0.z, hv[2].x, a4.x); a4.y = fmaf(w0.z, hv[2].y, a4.y);
        a4.z = fmaf(w0.z, hv[2].z, a4.z); a4.w = fmaf(w0.z, hv[2].w, a4.w);
        a4.x = fmaf(w0.w, hv[3].x, a4.x); a4.y = fmaf(w0.w, hv[3].y, a4.y);
        a4.z = fmaf(w0.w, hv[3].z, a4.z); a4.w = fmaf(w0.w, hv[3].w, a4.w);
        a4.x = fmaf(w1.x, hv[4].x, a4.x); a4.y = fmaf(w1.x, hv[4].y, a4.y);
        a4.z = fmaf(w1.x, hv[4].z, a4.z); a4.w = fmaf(w1.x, hv[4].w, a4.w);
        a4.x = fmaf(w1.y, hv[5].x, a4.x); a4.y = fmaf(w1.y, hv[5].y, a4.y);
        a4.z = fmaf(w1.y, hv[5].z, a4.z); a4.w = fmaf(w1.y, hv[5].w, a4.w);
        a4.x = fmaf(w1.z, hv[6].x, a4.x); a4.y = fmaf(w1.z, hv[6].y, a4.y);
        a4.z = fmaf(w1.z, hv[6].z, a4.z); a4.w = fmaf(w1.z, hv[6].w, a4.w);
        a4.x = fmaf(w1.w, hv[7].x, a4.x); a4.y = fmaf(w1.w, hv[7].y, a4.y);
        a4.z = fmaf(w1.w, hv[7].z, a4.z); a4.w = fmaf(w1.w, hv[7].w, a4.w);
        uint2 ov;
        __nv_bfloat162 o0 = __float22bfloat162_rn(make_float2(a4.x, a4.y));
        __nv_bfloat162 o1 = __float22bfloat162_rn(make_float2(a4.z, a4.w));
        ov.x = *reinterpret_cast<uint32_t*>(&o0);
        ov.y = *reinterpret_cast<uint32_t*>(&o1);
        *(uint2*)(orow + h * D_DIM) = ov;
    }
}

// ---------------------------------------------------------------------------
extern "C" void kernel_launch(void* const* d_in, const int* in_sizes, int n_in,
                              void* d_out, int out_size)
{
    const float* cur  = (const float*)d_in[0];
    const float* hist = (const float*)d_in[1];
    const float* Wq   = (const float*)d_in[2];
    const float* Wk   = (const float*)d_in[3];
    const float* Wv   = (const float*)d_in[4];
    const float* Wo   = (const float*)d_in[5];
    float* out = (float*)d_out;

    const int D = D_DIM;
    const int M = in_sizes[0] / D;   // 8192

    __nv_bfloat16 *qb = nullptr, *qk = nullptr, *hb = nullptr, *ob = nullptr;
    __nv_bfloat16 *wkt = nullptr, *wv = nullptr, *wo = nullptr;
    cudaGetSymbolAddress((void**)&qb,  g_qb);
    cudaGetSymbolAddress((void**)&qk,  g_qk);
    cudaGetSymbolAddress((void**)&hb,  g_hb);
    cudaGetSymbolAddress((void**)&ob,  g_ob);
    cudaGetSymbolAddress((void**)&wkt, g_wkt);
    cudaGetSymbolAddress((void**)&wv,  g_wv);
    cudaGetSymbolAddress((void**)&wo,  g_wo);

    constexpr int SM_T32 = 2 * (128 * 36 * 4) + 2 * (128 * 36 * 4);  // 73728
    constexpr int SM_B64 = (2 * (128 * 72) + 2 * (64 * 72)) * 2;     // 55296
    constexpr int SM_B128 = (2 * (128 * 72) + 2 * (128 * 72)) * 2;   // 73728

    cudaFuncSetAttribute(gemm_tf32<true>,
                         cudaFuncAttributeMaxDynamicSharedMemorySize, SM_T32);
    cudaFuncSetAttribute(gemm_bf16<64, true,  false>,
                         cudaFuncAttributeMaxDynamicSharedMemorySize, SM_B64);
    cudaFuncSetAttribute(gemm_bf16<128, false, true>,
                         cudaFuncAttributeMaxDynamicSharedMemorySize, SM_B128);

    // P0: weight prep
    transpose_wk_bf16<<<dim3(32, 32), dim3(32, 8)>>>(Wk, wkt);
    convert_w<<<D * D / 4 / 256, 256>>>(Wv, Wo, wv, wo);

    // K1: q = cur @ Wq^T  (tf32) -> bf16
    gemm_tf32<true>
        <<<dim3(D / 128, M / 128), 256, SM_T32>>>(
            cur, D, Wq, D, qb, D, D);

    // K2: qk_h = q_h @ Wk_h  (bf16, NT via WkT, K=64, NC=1) -> bf16
    gemm_bf16<64, true, false>
        <<<dim3(D / 64, M / 128, H_HEADS), 256, SM_B64>>>(
            qb, D, HD,                 // A = q[:, h*64 : (h+1)*64]
            wkt, D, HD,                // B rows j, cols h*64 : (h+1)*64
            nullptr,
            qk, H_HEADS * D, D,        // C = qk[:, h, :]
            HD);

    // K3: attention -> hbar (bf16)
    attn_kernel<<<M, 256>>>(hist, qk, hb);

    // K4: out_h = hbar_h @ Wv_h^T (bf16) -> out bf16
    gemm_bf16<64, true, false>
        <<<dim3(1, M / 128, H_HEADS), 256, SM_B64>>>(
            hb, H_HEADS * D, D,
            wv, D, (long long)HD * D,
            nullptr,
            ob, D, HD,
            D);

    // K5: final = cur + out @ Wo^T  (bf16 + fp32 residual)
    gemm_bf16<128, false, true>
        <<<dim3(D / 128, M / 128, 1), 256, SM_B128>>>(
            ob, D, 0, wo, D, 0, cur, out, D, 0, D);
}

// round 11
// speedup vs baseline: 2.4462x; 1.2102x over previous
#include <cuda_runtime.h>
#include <cuda_bf16.h>
#include <cstdint>

// ============================================================================
// CrossDepthAttention, mma.sync tensor cores (base-target legal).
//   P0: Wk -> transpose+bf16 (g_wkt); Wv, Wo -> bf16
//   K1: q    = cur @ Wq^T            tf32 m16n8k8  -> q bf16
//   K2: qk_h = q_h @ Wk_h            bf16, persistent j-loop (A resident)
//       FIX vs R10: fill loops copy the FULL 64-half K range (1024 chunks).
//   K3: fused attention (2 barriers, multi-value butterfly) -> hbar bf16
//   K4: out_h = hbar_h @ Wv_h^T      bf16 m16n8k16 -> out bf16
//   K5: final = cur + out @ Wo^T     bf16 m16n8k16 + fp32 residual
// ============================================================================

#define D_DIM   1024
#define H_HEADS 16
#define HD      64
#define NPREV   8
#define M_MAX   8192

__device__ __nv_bfloat16 g_qb[M_MAX * D_DIM];                      // q (bf16)
__device__ __nv_bfloat16 g_qk[(size_t)M_MAX * H_HEADS * D_DIM];    // qk (bf16)
__device__ __nv_bfloat16 g_hb[(size_t)M_MAX * H_HEADS * D_DIM];    // hbar (bf16)
__device__ __nv_bfloat16 g_ob[M_MAX * D_DIM];                      // out (bf16)
__device__ __nv_bfloat16 g_wkt[D_DIM * D_DIM];                     // Wk^T (bf16)
__device__ __nv_bfloat16 g_wv[D_DIM * D_DIM];                      // Wv (bf16)
__device__ __nv_bfloat16 g_wo[D_DIM * D_DIM];                      // Wo (bf16)

// ---------------------------------------------------------------------------
__device__ __forceinline__ uint32_t smem_u32(const void* p) {
    uint32_t a;
    asm("{ .reg .u64 t; cvta.to.shared.u64 t, %1; cvt.u32.u64 %0, t; }"
        : "=r"(a) : "l"(p));
    return a;
}
__device__ __forceinline__ void cp16(uint32_t s, const void* g) {
    asm volatile("cp.async.cg.shared.global [%0], [%1], 16;\n" :: "r"(s), "l"(g));
}
__device__ __forceinline__ void cp_commit() {
    asm volatile("cp.async.commit_group;\n" ::: "memory");
}
template <int N> __device__ __forceinline__ void cp_wait() {
    asm volatile("cp.async.wait_group %0;\n" :: "n"(N) : "memory");
}
__device__ __forceinline__ void mma_tf32(float* c, const uint32_t* a,
                                         const uint32_t* b) {
    asm volatile(
        "mma.sync.aligned.m16n8k8.row.col.f32.tf32.tf32.f32 "
        "{%0,%1,%2,%3}, {%4,%5,%6,%7}, {%8,%9}, {%0,%1,%2,%3};\n"
        : "+f"(c[0]), "+f"(c[1]), "+f"(c[2]), "+f"(c[3])
        : "r"(a[0]), "r"(a[1]), "r"(a[2]), "r"(a[3]), "r"(b[0]), "r"(b[1]));
}
__device__ __forceinline__ void mma_bf16(float* c, const uint32_t* a,
                                         const uint32_t* b) {
    asm volatile(
        "mma.sync.aligned.m16n8k16.row.col.f32.bf16.bf16.f32 "
        "{%0,%1,%2,%3}, {%4,%5,%6,%7}, {%8,%9}, {%0,%1,%2,%3};\n"
        : "+f"(c[0]), "+f"(c[1]), "+f"(c[2]), "+f"(c[3])
        : "r"(a[0]), "r"(a[1]), "r"(a[2]), "r"(a[3]), "r"(b[0]), "r"(b[1]));
}

// ---------------------------------------------------------------------------
// P0a: Wk transpose + bf16 convert, tiled 32x32.
// ---------------------------------------------------------------------------
__global__ void __launch_bounds__(256) transpose_wk_bf16(
    const float* __restrict__ in, __nv_bfloat16* __restrict__ outp)
{
    __shared__ float t[32][33];
    const int bx = blockIdx.x * 32, by = blockIdx.y * 32;
    int x = bx + threadIdx.x;
#pragma unroll
    for (int i = 0; i < 32; i += 8)
        t[threadIdx.y + i][threadIdx.x] = in[(size_t)(by + threadIdx.y + i) * D_DIM + x];
    __syncthreads();
    x = by + threadIdx.x;
#pragma unroll
    for (int i = 0; i < 32; i += 8)
        outp[(size_t)(bx + threadIdx.y + i) * D_DIM + x] =
            __float2bfloat16(t[threadIdx.x][threadIdx.y + i]);
}

// P0b: Wv, Wo -> bf16
__global__ void __launch_bounds__(256) convert_w(
    const float* __restrict__ wv, const float* __restrict__ wo,
    __nv_bfloat16* __restrict__ ov, __nv_bfloat16* __restrict__ oo)
{
    int i = (blockIdx.x * 256 + threadIdx.x) * 4;
    float4 a = *(const float4*)(wv + i);
    float4 b = *(const float4*)(wo + i);
    *(__nv_bfloat162*)(ov + i)     = __float22bfloat162_rn(make_float2(a.x, a.y));
    *(__nv_bfloat162*)(ov + i + 2) = __float22bfloat162_rn(make_float2(a.z, a.w));
    *(__nv_bfloat162*)(oo + i)     = __float22bfloat162_rn(make_float2(b.x, b.y));
    *(__nv_bfloat162*)(oo + i + 2) = __float22bfloat162_rn(make_float2(b.z, b.w));
}

// ---------------------------------------------------------------------------
// K1: tf32 GEMM (NT): C[m,n] = sum_k A[m,k] * B[n*ldb + k] -> bf16 out.
// ---------------------------------------------------------------------------
__global__ void __launch_bounds__(256)
gemm_tf32(const float* __restrict__ A, int lda,
          const float* __restrict__ B, int ldb,
          __nv_bfloat16* __restrict__ C, int ldc, int K)
{
    constexpr int A_FLOATS = 128 * 36;
    constexpr int B_FLOATS = 128 * 36;

    extern __shared__ float smem_f[];
    const uint32_t sbase = smem_u32(smem_f);

    const int tid = threadIdx.x;
    const int wid = tid >> 5, lane = tid & 31;
    const int wm = wid & 1, wn = wid >> 1;
    const int bx = blockIdx.x, by = blockIdx.y;

    const float* Af = A + (size_t)(by * 128) * lda;
    const float* Bg = B + (size_t)(bx * 128) * ldb;

    auto fill = [&](int buf, int k0) {
        const uint32_t As_b = sbase + (uint32_t)(buf * A_FLOATS) * 4u;
        const uint32_t Bs_b = sbase + (uint32_t)(2 * A_FLOATS + buf * B_FLOATS) * 4u;
#pragma unroll
        for (int p = 0; p < 4; ++p) {
            int ch = tid + p * 256;
            int row = ch >> 3, c4 = ch & 7;
            cp16(As_b + (uint32_t)(row * 36 + c4 * 4) * 4u,
                 Af + (size_t)row * lda + k0 + c4 * 4);
        }
#pragma unroll
        for (int p = 0; p < 4; ++p) {
            int ch = tid + p * 256;
            int row = ch >> 3, c4 = ch & 7;
            cp16(Bs_b + (uint32_t)(row * 36 + c4 * 4) * 4u,
                 Bg + (size_t)row * ldb + k0 + c4 * 4);
        }
    };

    float acc[4][4][4];
#pragma unroll
    for (int mt = 0; mt < 4; ++mt)
#pragma unroll
        for (int nt = 0; nt < 4; ++nt)
#pragma unroll
            for (int j = 0; j < 4; ++j) acc[mt][nt][j] = 0.0f;

    const int g = lane >> 2, tg = lane & 3;
    const int a_off = (wm * 64 + g) * 36 + tg;
    const int b_off = (wn * 32 + g) * 36 + tg;

    const int NC = K / 32;
    fill(0, 0);
    cp_commit();

    for (int c = 0; c < NC; ++c) {
        if (c + 1 < NC) { fill((c + 1) & 1, (c + 1) * 32); cp_commit(); cp_wait<1>(); }
        else            { cp_wait<0>(); }
        __syncthreads();

        const int buf = c & 1;
        const float* As_c = smem_f + buf * A_FLOATS;
        const float* Bs_c = smem_f + 2 * A_FLOATS + buf * B_FLOATS;

#pragma unroll
        for (int s = 0; s < 4; ++s) {
            uint32_t af[4][4];
#pragma unroll
            for (int mt = 0; mt < 4; ++mt) {
                const float* p = As_c + a_off + mt * 16 * 36 + s * 8;
                af[mt][0] = __float_as_uint(p[0]);
                af[mt][1] = __float_as_uint(p[8 * 36]);
                af[mt][2] = __float_as_uint(p[4]);
                af[mt][3] = __float_as_uint(p[8 * 36 + 4]);
            }
            uint32_t bf[4][2];
#pragma unroll
            for (int nt = 0; nt < 4; ++nt) {
                const float* p = Bs_c + b_off + nt * 8 * 36 + s * 8;
                bf[nt][0] = __float_as_uint(p[0]);
                bf[nt][1] = __float_as_uint(p[4]);
            }
#pragma unroll
            for (int mt = 0; mt < 4; ++mt)
#pragma unroll
                for (int nt = 0; nt < 4; ++nt)
                    mma_tf32(acc[mt][nt], af[mt], bf[nt]);
        }
        __syncthreads();
    }

    const int row0 = by * 128 + wm * 64 + g;
    const int coll = wn * 32 + tg * 2;
#pragma unroll
    for (int mt = 0; mt < 4; ++mt) {
        const int m = row0 + mt * 16;
#pragma unroll
        for (int nt = 0; nt < 4; ++nt) {
            const int n = bx * 128 + coll + nt * 8;
            *(__nv_bfloat162*)(C + (size_t)m * ldc + n) =
                __float22bfloat162_rn(make_float2(acc[mt][nt][0], acc[mt][nt][1]));
            *(__nv_bfloat162*)(C + (size_t)(m + 8) * ldc + n) =
                __float22bfloat162_rn(make_float2(acc[mt][nt][2], acc[mt][nt][3]));
        }
    }
}

// ---------------------------------------------------------------------------
// K2: persistent j-loop bf16 GEMM.  (FILL FIXED: full 64-half K range.)
// ---------------------------------------------------------------------------
__global__ void __launch_bounds__(256)
gemm_k2(const __nv_bfloat16* __restrict__ Q,
        const __nv_bfloat16* __restrict__ WKT,
        __nv_bfloat16* __restrict__ QK)
{
    constexpr int A_HALVES = 128 * 72;
    constexpr int B_HALVES = 128 * 72;

    extern __shared__ __align__(16) __nv_bfloat16 sm_h[];
    const uint32_t sbase = smem_u32(sm_h);

    const int tid = threadIdx.x;
    const int wid = tid >> 5, lane = tid & 31;
    const int wm = wid & 1, wn = wid >> 1;
    const int by = blockIdx.x;           // m-tile
    const int h  = blockIdx.y;           // head

    const __nv_bfloat16* Ah = Q + (size_t)(by * 128) * D_DIM + h * HD;
    const __nv_bfloat16* Bh = WKT + h * HD;

    // A: 128 rows x 64 halves = 1024 chunks of 16B (4 per thread)
#pragma unroll
    for (int p = 0; p < 4; ++p) {
        int ch = tid + p * 256;
        int row = ch >> 3, c8 = ch & 7;
        cp16(sbase + (uint32_t)(row * 72 + c8 * 8) * 2u,
             Ah + (size_t)row * D_DIM + c8 * 8);
    }
    auto fillB = [&](int buf, int j0) {
        const uint32_t Bb = sbase + (uint32_t)(A_HALVES + buf * B_HALVES) * 2u;
#pragma unroll
        for (int p = 0; p < 4; ++p) {
            int ch = tid + p * 256;
            int row = ch >> 3, c8 = ch & 7;
            cp16(Bb + (uint32_t)(row * 72 + c8 * 8) * 2u,
                 Bh + (size_t)(j0 + row) * D_DIM + c8 * 8);
        }
    };
    fillB(0, 0);
    cp_commit();        // group 0: A + B0

    const int g = lane >> 2, tg = lane & 3;
    const int a_off = (wm * 64 + g) * 36 + tg;     // word index
    const int b_off = (wn * 32 + g) * 36 + tg;
    const uint32_t* Aw = (const uint32_t*)sm_h;

    const int row0 = by * 128 + wm * 64 + g;
    const int coll = wn * 32 + tg * 2;

    for (int jt = 0; jt < 8; ++jt) {
        if (jt + 1 < 8) { fillB((jt + 1) & 1, (jt + 1) * 128); cp_commit(); cp_wait<1>(); }
        else            { cp_wait<0>(); }
        __syncthreads();

        const uint32_t* Bw = (const uint32_t*)sm_h
                           + (A_HALVES + (jt & 1) * B_HALVES) / 2;

        float acc[4][4][4];
#pragma unroll
        for (int mt = 0; mt < 4; ++mt)
#pragma unroll
            for (int nt = 0; nt < 4; ++nt)
#pragma unroll
                for (int j = 0; j < 4; ++j) acc[mt][nt][j] = 0.0f;

#pragma unroll
        for (int s = 0; s < 4; ++s) {              // 4 x k16 over K=64
            uint32_t af[4][4];
#pragma unroll
            for (int mt = 0; mt < 4; ++mt) {
                const uint32_t* p = Aw + a_off + mt * 16 * 36 + s * 8;
                af[mt][0] = p[0];
                af[mt][1] = p[8 * 36];
                af[mt][2] = p[4];
                af[mt][3] = p[8 * 36 + 4];
            }
            uint32_t bfr[4][2];
#pragma unroll
            for (int nt = 0; nt < 4; ++nt) {
                const uint32_t* p = Bw + b_off + nt * 8 * 36 + s * 8;
                bfr[nt][0] = p[0];
                bfr[nt][1] = p[4];
            }
#pragma unroll
            for (int mt = 0; mt < 4; ++mt)
#pragma unroll
                for (int nt = 0; nt < 4; ++nt)
                    mma_bf16(acc[mt][nt], af[mt], bfr[nt]);
        }

        // epilogue for this j-tile
        __nv_bfloat16* Cg = QK + (size_t)h * D_DIM + (size_t)jt * 128;
#pragma unroll
        for (int mt = 0; mt < 4; ++mt) {
            const int m = row0 + mt * 16;
#pragma unroll
            for (int nt = 0; nt < 4; ++nt) {
                const int n = coll + nt * 8;
                *(__nv_bfloat162*)(Cg + (size_t)m * (H_HEADS * D_DIM) + n) =
                    __float22bfloat162_rn(make_float2(acc[mt][nt][0], acc[mt][nt][1]));
                *(__nv_bfloat162*)(Cg + (size_t)(m + 8) * (H_HEADS * D_DIM) + n) =
                    __float22bfloat162_rn(make_float2(acc[mt][nt][2], acc[mt][nt][3]));
            }
        }
        __syncthreads();
    }
}

// ---------------------------------------------------------------------------
// bf16 m16n8k16 GEMM (NT): C[m,n] = sum_k A[m,k] * B[n*ldb + k]; A,B bf16.
// ---------------------------------------------------------------------------
template <int BN, bool OUT_BF16, bool RESID>
__global__ void __launch_bounds__(256)
gemm_bf16(const __nv_bfloat16* __restrict__ A, int lda, long long sA,
          const __nv_bfloat16* __restrict__ B, int ldb, long long sB,
          const float* __restrict__ R,
          void* __restrict__ C, int ldc, long long sC, int K)
{
    constexpr int WM = (BN == 128) ? 2 : 4;
    constexpr int MT = 8 / WM;
    constexpr int A_HALVES = 128 * 72;
    constexpr int B_HALVES = BN * 72;

    extern __shared__ __align__(16) __nv_bfloat16 sm_h[];
    const uint32_t sbase = smem_u32(sm_h);

    const int tid = threadIdx.x;
    const int wid = tid >> 5, lane = tid & 31;
    const int wm = wid % WM, wn = wid / WM;
    const int bx = blockIdx.x, by = blockIdx.y, bz = blockIdx.z;

    const __nv_bfloat16* Ah = A + (long long)bz * sA + (size_t)(by * 128) * lda;
    const __nv_bfloat16* Bh = B + (long long)bz * sB + (size_t)(bx * BN) * ldb;

    auto fill = [&](int buf, int k0) {
        const uint32_t Ab = sbase + (uint32_t)(buf * A_HALVES) * 2u;
        const uint32_t Bb = sbase + (uint32_t)(2 * A_HALVES + buf * B_HALVES) * 2u;
#pragma unroll
        for (int p = 0; p < 4; ++p) {
            int ch = tid + p * 256;
            int row = ch >> 3, c8 = ch & 7;
            cp16(Ab + (uint32_t)(row * 72 + c8 * 8) * 2u,
                 Ah + (size_t)row * lda + k0 + c8 * 8);
        }
#pragma unroll
        for (int p = 0; p < BN * 8 / 256; ++p) {
            int ch = tid + p * 256;
            int row = ch >> 3, c8 = ch & 7;
            cp16(Bb + (uint32_t)(row * 72 + c8 * 8) * 2u,
                 Bh + (size_t)row * ldb + k0 + c8 * 8);
        }
    };

    float acc[MT][4][4];
#pragma unroll
    for (int mt = 0; mt < MT; ++mt)
#pragma unroll
        for (int nt = 0; nt < 4; ++nt)
#pragma unroll
            for (int j = 0; j < 4; ++j) acc[mt][nt][j] = 0.0f;

    const int g = lane >> 2, tg = lane & 3;
    const int a_off = (wm * (128 / WM) + g) * 36 + tg;
    const int b_off = (wn * 32 + g) * 36 + tg;

    const int NC = K / 64;
    fill(0, 0);
    cp_commit();

    for (int c = 0; c < NC; ++c) {
        if (c + 1 < NC) { fill((c + 1) & 1, (c + 1) * 64); cp_commit(); cp_wait<1>(); }
        else            { cp_wait<0>(); }
        __syncthreads();

        const int buf = c & 1;
        const uint32_t* Aw = (const uint32_t*)sm_h + buf * (A_HALVES / 2);
        const uint32_t* Bw = (const uint32_t*)sm_h + A_HALVES + buf * (B_HALVES / 2);

#pragma unroll
        for (int s = 0; s < 4; ++s) {
            uint32_t af[MT][4];
#pragma unroll
            for (int mt = 0; mt < MT; ++mt) {
                const uint32_t* p = Aw + a_off + mt * 16 * 36 + s * 8;
                af[mt][0] = p[0];
                af[mt][1] = p[8 * 36];
                af[mt][2] = p[4];
                af[mt][3] = p[8 * 36 + 4];
            }
            uint32_t bfr[4][2];
#pragma unroll
            for (int nt = 0; nt < 4; ++nt) {
                const uint32_t* p = Bw + b_off + nt * 8 * 36 + s * 8;
                bfr[nt][0] = p[0];
                bfr[nt][1] = p[4];
            }
#pragma unroll
            for (int mt = 0; mt < MT; ++mt)
#pragma unroll
                for (int nt = 0; nt < 4; ++nt)
                    mma_bf16(acc[mt][nt], af[mt], bfr[nt]);
        }
        __syncthreads();
    }

    const int row0 = by * 128 + wm * (128 / WM) + g;
    const int coll = wn * 32 + tg * 2;
#pragma unroll
    for (int mt = 0; mt < MT; ++mt) {
        const int m = row0 + mt * 16;
#pragma unroll
        for (int nt = 0; nt < 4; ++nt) {
            const int n = bx * BN + coll + nt * 8;
            if (!OUT_BF16) {
                float* Cg = (float*)C + (long long)bz * sC;
                float2 v0 = make_float2(acc[mt][nt][0], acc[mt][nt][1]);
                float2 v1 = make_float2(acc[mt][nt][2], acc[mt][nt][3]);
                if (RESID) {
                    float2 r0 = *(const float2*)(R + (size_t)m * ldc + n);
                    float2 r1 = *(const float2*)(R + (size_t)(m + 8) * ldc + n);
                    v0.x += r0.x; v0.y += r0.y;
                    v1.x += r1.x; v1.y += r1.y;
                }
                *(float2*)(Cg + (size_t)m * ldc + n)       = v0;
                *(float2*)(Cg + (size_t)(m + 8) * ldc + n) = v1;
            } else {
                __nv_bfloat16* Cg = (__nv_bfloat16*)C + (long long)bz * sC;
                *(__nv_bfloat162*)(Cg + (size_t)m * ldc + n) =
                    __float22bfloat162_rn(make_float2(acc[mt][nt][0], acc[mt][nt][1]));
                *(__nv_bfloat162*)(Cg + (size_t)(m + 8) * ldc + n) =
                    __float22bfloat162_rn(make_float2(acc[mt][nt][2], acc[mt][nt][3]));
            }
        }
    }
}

// ---------------------------------------------------------------------------
// K3: fused attention — 2 barriers + multi-value butterfly. hbar -> bf16.
// ---------------------------------------------------------------------------
__global__ void __launch_bounds__(256) attn_kernel(
    const float* __restrict__ hist, const __nv_bfloat16* __restrict__ qk,
    __nv_bfloat16* __restrict__ hbar)
{
    __shared__ float red[H_HEADS][NPREV][8];
    __shared__ __align__(16) float attn_s[H_HEADS][NPREV];

    const int m    = blockIdx.x;
    const int tid  = threadIdx.x;
    const int lane = tid & 31;
    const int warp = tid >> 5;

    const __nv_bfloat16* qrow = qk + (size_t)m * (H_HEADS * D_DIM) + tid * 4;
    uint2 q2[H_HEADS];
#pragma unroll
    for (int h = 0; h < H_HEADS; h++)
        q2[h] = *(const uint2*)(qrow + h * D_DIM);

    float4 hv[NPREV];
    const float* hg = hist + (size_t)m * NPREV * D_DIM + tid * 4;
#pragma unroll
    for (int n = 0; n < NPREV; n++)
        hv[n] = *(const float4*)(hg + n * D_DIM);

    // ---- Phase A: dots + multi-value butterfly reduction ----
#pragma unroll
    for (int h = 0; h < H_HEADS; h++) {
        float2 qa = __bfloat1622float2(*reinterpret_cast<__nv_bfloat162*>(&q2[h].x));
        float2 qb = __bfloat1622float2(*reinterpret_cast<__nv_bfloat162*>(&q2[h].y));
        float p[NPREV];
#pragma unroll
        for (int n = 0; n < NPREV; n++)
            p[n] = qa.x * hv[n].x + qa.y * hv[n].y
                 + qb.x * hv[n].z + qb.y * hv[n].w;

#pragma unroll
        for (int i = 0; i < 4; i++) {
            float send = (lane & 16) ? p[i] : p[i + 4];
            float recv = __shfl_xor_sync(0xffffffffu, send, 16);
            p[i] = ((lane & 16) ? p[i + 4] : p[i]) + recv;
        }
#pragma unroll
        for (int i = 0; i < 2; i++) {
            float send = (lane & 8) ? p[i] : p[i + 2];
            float recv = __shfl_xor_sync(0xffffffffu, send, 8);
            p[i] = ((lane & 8) ? p[i + 2] : p[i]) + recv;
        }
        {
            float send = (lane & 4) ? p[0] : p[1];
            float recv = __shfl_xor_sync(0xffffffffu, send, 4);
            p[0] = ((lane & 4) ? p[1] : p[0]) + recv;
        }
        p[0] += __shfl_xor_sync(0xffffffffu, p[0], 2);
        p[0] += __shfl_xor_sync(0xffffffffu, p[0], 1);
        if ((lane & 3) == 0) red[h][lane >> 2][warp] = p[0];
    }
    __syncthreads();

    // ---- Phase B: 16 parallel softmaxes ----
    if (tid < H_HEADS) {
        const int h = tid;
        float lg[NPREV];
        float mx = -1e30f;
#pragma unroll
        for (int n = 0; n < NPREV; n++) {
            float4 s0 = *(const float4*)&red[h][n][0];
            float4 s1 = *(const float4*)&red[h][n][4];
            float s = (s0.x + s0.y) + (s0.z + s0.w)
                    + (s1.x + s1.y) + (s1.z + s1.w);
            lg[n] = s * 0.125f;
            mx = fmaxf(mx, lg[n]);
        }
        float den = 0.0f;
#pragma unroll
        for (int n = 0; n < NPREV; n++) { lg[n] = expf(lg[n] - mx); den += lg[n]; }
        float inv = 1.0f / den;
#pragma unroll
        for (int n = 0; n < NPREV; n++) attn_s[h][n] = lg[n] * inv;
    }
    __syncthreads();

    // ---- Phase C: weighted sums + bf16 stores ----
    __nv_bfloat16* orow = hbar + (size_t)m * (H_HEADS * D_DIM) + tid * 4;
#pragma unroll
    for (int h = 0; h < H_HEADS; h++) {
        float4 w0 = *(const float4*)&attn_s[h][0];
        float4 w1 = *(const float4*)&attn_s[h][4];
        float4 a4;
        a4.x = w0.x * hv[0].x; a4.y = w0.x * hv[0].y;
        a4.z = w0.x * hv[0].z; a4.w = w0.x * hv[0].w;
        a4.x = fmaf(w0.y, hv[1].x, a4.x); a4.y = fmaf(w0.y, hv[1].y, a4.y);
        a4.z = fmaf(w0.y, hv[1].z, a4.z); a4.w = fmaf(w0.y, hv[1].w, a4.w);
        a4.x = fmaf(w0.z, hv[2].x, a4.x); a4.y = fmaf(w0.z, hv[2].y, a4.y);
        a4.z = fmaf(w0.z, hv[2].z, a4.z); a4.w = fmaf(w0.z, hv[2].w, a4.w);
        a4.x = fmaf(w0.w, hv[3].x, a4.x); a4.y = fmaf(w0.w, hv[3].y, a4.y);
        a4.z = fmaf(w0.w, hv[3].z, a4.z); a4.w = fmaf(w0.w, hv[3].w, a4.w);
        a4.x = fmaf(w1.x, hv[4].x, a4.x); a4.y = fmaf(w1.x, hv[4].y, a4.y);
        a4.z = fmaf(w1.x, hv[4].z, a4.z); a4.w = fmaf(w1.x, hv[4].w, a4.w);
        a4.x = fmaf(w1.y, hv[5].x, a4.x); a4.y = fmaf(w1.y, hv[5].y, a4.y);
        a4.z = fmaf(w1.y, hv[5].z, a4.z); a4.w = fmaf(w1.y, hv[5].w, a4.w);
        a4.x = fmaf(w1.z, hv[6].x, a4.x); a4.y = fmaf(w1.z, hv[6].y, a4.y);
        a4.z = fmaf(w1.z, hv[6].z, a4.z); a4.w = fmaf(w1.z, hv[6].w, a4.w);
        a4.x = fmaf(w1.w, hv[7].x, a4.x); a4.y = fmaf(w1.w, hv[7].y, a4.y);
        a4.z = fmaf(w1.w, hv[7].z, a4.z); a4.w = fmaf(w1.w, hv[7].w, a4.w);
        uint2 ov;
        __nv_bfloat162 o0 = __float22bfloat162_rn(make_float2(a4.x, a4.y));
        __nv_bfloat162 o1 = __float22bfloat162_rn(make_float2(a4.z, a4.w));
        ov.x = *reinterpret_cast<uint32_t*>(&o0);
        ov.y = *reinterpret_cast<uint32_t*>(&o1);
        *(uint2*)(orow + h * D_DIM) = ov;
    }
}

// ---------------------------------------------------------------------------
extern "C" void kernel_launch(void* const* d_in, const int* in_sizes, int n_in,
                              void* d_out, int out_size)
{
    const float* cur  = (const float*)d_in[0];
    const float* hist = (const float*)d_in[1];
    const float* Wq   = (const float*)d_in[2];
    const float* Wk   = (const float*)d_in[3];
    const float* Wv   = (const float*)d_in[4];
    const float* Wo   = (const float*)d_in[5];
    float* out = (float*)d_out;

    const int D = D_DIM;
    const int M = in_sizes[0] / D;   // 8192

    __nv_bfloat16 *qb = nullptr, *qk = nullptr, *hb = nullptr, *ob = nullptr;
    __nv_bfloat16 *wkt = nullptr, *wv = nullptr, *wo = nullptr;
    cudaGetSymbolAddress((void**)&qb,  g_qb);
    cudaGetSymbolAddress((void**)&qk,  g_qk);
    cudaGetSymbolAddress((void**)&hb,  g_hb);
    cudaGetSymbolAddress((void**)&ob,  g_ob);
    cudaGetSymbolAddress((void**)&wkt, g_wkt);
    cudaGetSymbolAddress((void**)&wv,  g_wv);
    cudaGetSymbolAddress((void**)&wo,  g_wo);

    constexpr int SM_T32 = 2 * (128 * 36 * 4) + 2 * (128 * 36 * 4);  // 73728
    constexpr int SM_K2  = (128 * 72 + 2 * (128 * 72)) * 2;          // 55296
    constexpr int SM_B64 = (2 * (128 * 72) + 2 * (64 * 72)) * 2;     // 55296
    constexpr int SM_B128 = (2 * (128 * 72) + 2 * (128 * 72)) * 2;   // 73728

    cudaFuncSetAttribute(gemm_tf32,
                         cudaFuncAttributeMaxDynamicSharedMemorySize, SM_T32);
    cudaFuncSetAttribute(gemm_k2,
                         cudaFuncAttributeMaxDynamicSharedMemorySize, SM_K2);
    cudaFuncSetAttribute(gemm_bf16<64, true,  false>,
                         cudaFuncAttributeMaxDynamicSharedMemorySize, SM_B64);
    cudaFuncSetAttribute(gemm_bf16<128, false, true>,
                         cudaFuncAttributeMaxDynamicSharedMemorySize, SM_B128);

    // P0: weight prep
    transpose_wk_bf16<<<dim3(32, 32), dim3(32, 8)>>>(Wk, wkt);
    convert_w<<<D * D / 4 / 256, 256>>>(Wv, Wo, wv, wo);

    // K1: q = cur @ Wq^T  (tf32) -> bf16
    gemm_tf32<<<dim3(D / 128, M / 128), 256, SM_T32>>>(
            cur, D, Wq, D, qb, D, D);

    // K2: qk_h = q_h @ Wk_h  (bf16, persistent j-loop) -> bf16
    gemm_k2<<<dim3(M / 128, H_HEADS), 256, SM_K2>>>(qb, wkt, qk);

    // K3: attention -> hbar (bf16)
    attn_kernel<<<M, 256>>>(hist, qk, hb);

    // K4: out_h = hbar_h @ Wv_h^T (bf16) -> out bf16
    gemm_bf16<64, true, false>
        <<<dim3(1, M / 128, H_HEADS), 256, SM_B64>>>(
            hb, H_HEADS * D, D,
            wv, D, (long long)HD * D,
            nullptr,
            ob, D, HD,
            D);

    // K5: final = cur + out @ Wo^T  (bf16 + fp32 residual)
    gemm_bf16<128, false, true>
        <<<dim3(D / 128, M / 128, 1), 256, SM_B128>>>(
            ob, D, 0, wo, D, 0, cur, out, D, 0, D);
}

// round 12
// speedup vs baseline: 2.8047x; 1.1466x over previous
#include <cuda_runtime.h>
#include <cuda_bf16.h>
#include <cstdint>

// ============================================================================
// CrossDepthAttention, mma.sync tensor cores (base-target legal).
//   P0: cur,Wq,Wv,Wo -> bf16; Wk -> transpose+bf16
//   K1: q    = cur @ Wq^T            bf16 m16n8k16 (ldmatrix) -> bf16
//   K2: qk_h = q_h @ Wk_h            bf16 persistent j-loop (ldmatrix)
//   K3: fused attention (2 barriers, multi-value butterfly) -> hbar bf16
//   K4: out_h = hbar_h @ Wv_h^T      bf16 (ldmatrix) -> out bf16
//   K5: final = cur + out @ Wo^T     bf16 (ldmatrix) + fp32 residual
// ============================================================================

#define D_DIM   1024
#define H_HEADS 16
#define HD      64
#define NPREV   8
#define M_MAX   8192

__device__ __nv_bfloat16 g_cb[M_MAX * D_DIM];                      // cur (bf16)
__device__ __nv_bfloat16 g_qb[M_MAX * D_DIM];                      // q (bf16)
__device__ __nv_bfloat16 g_qk[(size_t)M_MAX * H_HEADS * D_DIM];    // qk (bf16)
__device__ __nv_bfloat16 g_hb[(size_t)M_MAX * H_HEADS * D_DIM];    // hbar (bf16)
__device__ __nv_bfloat16 g_ob[M_MAX * D_DIM];                      // out (bf16)
__device__ __nv_bfloat16 g_wq[D_DIM * D_DIM];                      // Wq (bf16)
__device__ __nv_bfloat16 g_wkt[D_DIM * D_DIM];                     // Wk^T (bf16)
__device__ __nv_bfloat16 g_wv[D_DIM * D_DIM];                      // Wv (bf16)
__device__ __nv_bfloat16 g_wo[D_DIM * D_DIM];                      // Wo (bf16)

// ---------------------------------------------------------------------------
__device__ __forceinline__ uint32_t smem_u32(const void* p) {
    uint32_t a;
    asm("{ .reg .u64 t; cvta.to.shared.u64 t, %1; cvt.u32.u64 %0, t; }"
        : "=r"(a) : "l"(p));
    return a;
}
__device__ __forceinline__ void cp16(uint32_t s, const void* g) {
    asm volatile("cp.async.cg.shared.global [%0], [%1], 16;\n" :: "r"(s), "l"(g));
}
__device__ __forceinline__ void cp_commit() {
    asm volatile("cp.async.commit_group;\n" ::: "memory");
}
template <int N> __device__ __forceinline__ void cp_wait() {
    asm volatile("cp.async.wait_group %0;\n" :: "n"(N) : "memory");
}
__device__ __forceinline__ void mma_bf16(float* c, const uint32_t* a,
                                         const uint32_t* b) {
    asm volatile(
        "mma.sync.aligned.m16n8k16.row.col.f32.bf16.bf16.f32 "
        "{%0,%1,%2,%3}, {%4,%5,%6,%7}, {%8,%9}, {%0,%1,%2,%3};\n"
        : "+f"(c[0]), "+f"(c[1]), "+f"(c[2]), "+f"(c[3])
        : "r"(a[0]), "r"(a[1]), "r"(a[2]), "r"(a[3]), "r"(b[0]), "r"(b[1]));
}
__device__ __forceinline__ void ldsm_x4(uint32_t& r0, uint32_t& r1,
                                        uint32_t& r2, uint32_t& r3,
                                        uint32_t addr) {
    asm volatile("ldmatrix.sync.aligned.m8n8.x4.shared.b16 {%0,%1,%2,%3}, [%4];"
                 : "=r"(r0), "=r"(r1), "=r"(r2), "=r"(r3) : "r"(addr));
}

// ---------------------------------------------------------------------------
// P0a: Wk transpose + bf16 convert, tiled 32x32.
// ---------------------------------------------------------------------------
__global__ void __launch_bounds__(256) transpose_wk_bf16(
    const float* __restrict__ in, __nv_bfloat16* __restrict__ outp)
{
    __shared__ float t[32][33];
    const int bx = blockIdx.x * 32, by = blockIdx.y * 32;
    int x = bx + threadIdx.x;
#pragma unroll
    for (int i = 0; i < 32; i += 8)
        t[threadIdx.y + i][threadIdx.x] = in[(size_t)(by + threadIdx.y + i) * D_DIM + x];
    __syncthreads();
    x = by + threadIdx.x;
#pragma unroll
    for (int i = 0; i < 32; i += 8)
        outp[(size_t)(bx + threadIdx.y + i) * D_DIM + x] =
            __float2bfloat16(t[threadIdx.x][threadIdx.y + i]);
}

// P0b: generic fp32 -> bf16 (n multiple of 1024)
__global__ void __launch_bounds__(256) convert_f2b(
    const float* __restrict__ in, __nv_bfloat16* __restrict__ outp)
{
    int i = (blockIdx.x * 256 + threadIdx.x) * 4;
    float4 a = *(const float4*)(in + i);
    *(__nv_bfloat162*)(outp + i)     = __float22bfloat162_rn(make_float2(a.x, a.y));
    *(__nv_bfloat162*)(outp + i + 2) = __float22bfloat162_rn(make_float2(a.z, a.w));
}

// ---------------------------------------------------------------------------
// bf16 m16n8k16 GEMM (NT) with ldmatrix fragment loads.
//   C[m,n] = sum_k A[m,k] * B[n*ldb + k]; A,B bf16.
// CTA tile 128 x BN, BK=64 halves, 256 threads, SMEM stride 72 halves.
// ---------------------------------------------------------------------------
template <int BN, bool OUT_BF16, bool RESID>
__global__ void __launch_bounds__(256)
gemm_bf16(const __nv_bfloat16* __restrict__ A, int lda, long long sA,
          const __nv_bfloat16* __restrict__ B, int ldb, long long sB,
          const float* __restrict__ R,
          void* __restrict__ C, int ldc, long long sC, int K)
{
    constexpr int WM = (BN == 128) ? 2 : 4;
    constexpr int MT = 8 / WM;
    constexpr int A_HALVES = 128 * 72;
    constexpr int B_HALVES = BN * 72;

    extern __shared__ __align__(16) __nv_bfloat16 sm_h[];
    const uint32_t sbase = smem_u32(sm_h);

    const int tid = threadIdx.x;
    const int wid = tid >> 5, lane = tid & 31;
    const int wm = wid % WM, wn = wid / WM;
    const int bx = blockIdx.x, by = blockIdx.y, bz = blockIdx.z;

    const __nv_bfloat16* Ah = A + (long long)bz * sA + (size_t)(by * 128) * lda;
    const __nv_bfloat16* Bh = B + (long long)bz * sB + (size_t)(bx * BN) * ldb;

    auto fill = [&](int buf, int k0) {
        const uint32_t Ab = sbase + (uint32_t)(buf * A_HALVES) * 2u;
        const uint32_t Bb = sbase + (uint32_t)(2 * A_HALVES + buf * B_HALVES) * 2u;
#pragma unroll
        for (int p = 0; p < 4; ++p) {
            int ch = tid + p * 256;
            int row = ch >> 3, c8 = ch & 7;
            cp16(Ab + (uint32_t)(row * 72 + c8 * 8) * 2u,
                 Ah + (size_t)row * lda + k0 + c8 * 8);
        }
#pragma unroll
        for (int p = 0; p < BN * 8 / 256; ++p) {
            int ch = tid + p * 256;
            int row = ch >> 3, c8 = ch & 7;
            cp16(Bb + (uint32_t)(row * 72 + c8 * 8) * 2u,
                 Bh + (size_t)row * ldb + k0 + c8 * 8);
        }
    };

    float acc[MT][4][4];
#pragma unroll
    for (int mt = 0; mt < MT; ++mt)
#pragma unroll
        for (int nt = 0; nt < 4; ++nt)
#pragma unroll
            for (int j = 0; j < 4; ++j) acc[mt][nt][j] = 0.0f;

    // ldmatrix lane address bases (in halves)
    const int r8 = lane & 7;
    const int a_base_h = (wm * (128 / WM) + ((lane >> 3) & 1) * 8 + r8) * 72
                       + ((lane >> 4) & 1) * 8;
    const int b_sel = (lane >> 3) & 3;
    const int b_base_h = (wn * 32 + (b_sel >> 1) * 8 + r8) * 72 + (b_sel & 1) * 8;

    const int NC = K / 64;
    fill(0, 0);
    cp_commit();

    for (int c = 0; c < NC; ++c) {
        if (c + 1 < NC) { fill((c + 1) & 1, (c + 1) * 64); cp_commit(); cp_wait<1>(); }
        else            { cp_wait<0>(); }
        __syncthreads();

        const int buf = c & 1;
        const uint32_t Ab = sbase + (uint32_t)(buf * A_HALVES) * 2u;
        const uint32_t Bb = sbase + (uint32_t)(2 * A_HALVES + buf * B_HALVES) * 2u;

#pragma unroll
        for (int s = 0; s < 4; ++s) {
            uint32_t af[MT][4];
#pragma unroll
            for (int mt = 0; mt < MT; ++mt)
                ldsm_x4(af[mt][0], af[mt][1], af[mt][2], af[mt][3],
                        Ab + (uint32_t)(a_base_h + mt * 16 * 72 + s * 16) * 2u);
            uint32_t bfr[4][2];
#pragma unroll
            for (int ntp = 0; ntp < 2; ++ntp)
                ldsm_x4(bfr[2 * ntp][0], bfr[2 * ntp][1],
                        bfr[2 * ntp + 1][0], bfr[2 * ntp + 1][1],
                        Bb + (uint32_t)(b_base_h + ntp * 16 * 72 + s * 16) * 2u);
#pragma unroll
            for (int mt = 0; mt < MT; ++mt)
#pragma unroll
                for (int nt = 0; nt < 4; ++nt)
                    mma_bf16(acc[mt][nt], af[mt], bfr[nt]);
        }
        __syncthreads();
    }

    const int g = lane >> 2, tg = lane & 3;
    const int row0 = by * 128 + wm * (128 / WM) + g;
    const int coll = wn * 32 + tg * 2;
#pragma unroll
    for (int mt = 0; mt < MT; ++mt) {
        const int m = row0 + mt * 16;
#pragma unroll
        for (int nt = 0; nt < 4; ++nt) {
            const int n = bx * BN + coll + nt * 8;
            if (!OUT_BF16) {
                float* Cg = (float*)C + (long long)bz * sC;
                float2 v0 = make_float2(acc[mt][nt][0], acc[mt][nt][1]);
                float2 v1 = make_float2(acc[mt][nt][2], acc[mt][nt][3]);
                if (RESID) {
                    float2 r0 = *(const float2*)(R + (size_t)m * ldc + n);
                    float2 r1 = *(const float2*)(R + (size_t)(m + 8) * ldc + n);
                    v0.x += r0.x; v0.y += r0.y;
                    v1.x += r1.x; v1.y += r1.y;
                }
                *(float2*)(Cg + (size_t)m * ldc + n)       = v0;
                *(float2*)(Cg + (size_t)(m + 8) * ldc + n) = v1;
            } else {
                __nv_bfloat16* Cg = (__nv_bfloat16*)C + (long long)bz * sC;
                *(__nv_bfloat162*)(Cg + (size_t)m * ldc + n) =
                    __float22bfloat162_rn(make_float2(acc[mt][nt][0], acc[mt][nt][1]));
                *(__nv_bfloat162*)(Cg + (size_t)(m + 8) * ldc + n) =
                    __float22bfloat162_rn(make_float2(acc[mt][nt][2], acc[mt][nt][3]));
            }
        }
    }
}

// ---------------------------------------------------------------------------
// K2: persistent j-loop bf16 GEMM with ldmatrix.
//   qk[m, h*1024 + j] = sum_d q[m, h*64+d] * wkt[j, h*64+d]
// Grid (M/128, 16 heads). A tile resident; 8 j-tiles of B double-buffered.
// ---------------------------------------------------------------------------
__global__ void __launch_bounds__(256)
gemm_k2(const __nv_bfloat16* __restrict__ Q,
        const __nv_bfloat16* __restrict__ WKT,
        __nv_bfloat16* __restrict__ QK)
{
    constexpr int A_HALVES = 128 * 72;
    constexpr int B_HALVES = 128 * 72;

    extern __shared__ __align__(16) __nv_bfloat16 sm_h[];
    const uint32_t sbase = smem_u32(sm_h);

    const int tid = threadIdx.x;
    const int wid = tid >> 5, lane = tid & 31;
    const int wm = wid & 1, wn = wid >> 1;
    const int by = blockIdx.x;           // m-tile
    const int h  = blockIdx.y;           // head

    const __nv_bfloat16* Ah = Q + (size_t)(by * 128) * D_DIM + h * HD;
    const __nv_bfloat16* Bh = WKT + h * HD;

    // A: 128 rows x 64 halves = 1024 chunks of 16B (4 per thread)
#pragma unroll
    for (int p = 0; p < 4; ++p) {
        int ch = tid + p * 256;
        int row = ch >> 3, c8 = ch & 7;
        cp16(sbase + (uint32_t)(row * 72 + c8 * 8) * 2u,
             Ah + (size_t)row * D_DIM + c8 * 8);
    }
    auto fillB = [&](int buf, int j0) {
        const uint32_t Bb = sbase + (uint32_t)(A_HALVES + buf * B_HALVES) * 2u;
#pragma unroll
        for (int p = 0; p < 4; ++p) {
            int ch = tid + p * 256;
            int row = ch >> 3, c8 = ch & 7;
            cp16(Bb + (uint32_t)(row * 72 + c8 * 8) * 2u,
                 Bh + (size_t)(j0 + row) * D_DIM + c8 * 8);
        }
    };
    fillB(0, 0);
    cp_commit();        // group 0: A + B0

    // ldmatrix bases
    const int r8 = lane & 7;
    const int a_base_h = (wm * 64 + ((lane >> 3) & 1) * 8 + r8) * 72
                       + ((lane >> 4) & 1) * 8;
    const int b_sel = (lane >> 3) & 3;
    const int b_base_h = (wn * 32 + (b_sel >> 1) * 8 + r8) * 72 + (b_sel & 1) * 8;

    const int g = lane >> 2, tg = lane & 3;
    const int row0 = by * 128 + wm * 64 + g;
    const int coll = wn * 32 + tg * 2;

    for (int jt = 0; jt < 8; ++jt) {
        if (jt + 1 < 8) { fillB((jt + 1) & 1, (jt + 1) * 128); cp_commit(); cp_wait<1>(); }
        else            { cp_wait<0>(); }
        __syncthreads();

        const uint32_t Bb = sbase + (uint32_t)(A_HALVES + (jt & 1) * B_HALVES) * 2u;

        float acc[4][4][4];
#pragma unroll
        for (int mt = 0; mt < 4; ++mt)
#pragma unroll
            for (int nt = 0; nt < 4; ++nt)
#pragma unroll
                for (int j = 0; j < 4; ++j) acc[mt][nt][j] = 0.0f;

#pragma unroll
        for (int s = 0; s < 4; ++s) {              // 4 x k16 over K=64
            uint32_t af[4][4];
#pragma unroll
            for (int mt = 0; mt < 4; ++mt)
                ldsm_x4(af[mt][0], af[mt][1], af[mt][2], af[mt][3],
                        sbase + (uint32_t)(a_base_h + mt * 16 * 72 + s * 16) * 2u);
            uint32_t bfr[4][2];
#pragma unroll
            for (int ntp = 0; ntp < 2; ++ntp)
                ldsm_x4(bfr[2 * ntp][0], bfr[2 * ntp][1],
                        bfr[2 * ntp + 1][0], bfr[2 * ntp + 1][1],
                        Bb + (uint32_t)(b_base_h + ntp * 16 * 72 + s * 16) * 2u);
#pragma unroll
            for (int mt = 0; mt < 4; ++mt)
#pragma unroll
                for (int nt = 0; nt < 4; ++nt)
                    mma_bf16(acc[mt][nt], af[mt], bfr[nt]);
        }

        // epilogue for this j-tile
        __nv_bfloat16* Cg = QK + (size_t)h * D_DIM + (size_t)jt * 128;
#pragma unroll
        for (int mt = 0; mt < 4; ++mt) {
            const int m = row0 + mt * 16;
#pragma unroll
            for (int nt = 0; nt < 4; ++nt) {
                const int n = coll + nt * 8;
                *(__nv_bfloat162*)(Cg + (size_t)m * (H_HEADS * D_DIM) + n) =
                    __float22bfloat162_rn(make_float2(acc[mt][nt][0], acc[mt][nt][1]));
                *(__nv_bfloat162*)(Cg + (size_t)(m + 8) * (H_HEADS * D_DIM) + n) =
                    __float22bfloat162_rn(make_float2(acc[mt][nt][2], acc[mt][nt][3]));
            }
        }
        __syncthreads();
    }
}

// ---------------------------------------------------------------------------
// K3: fused attention — 2 barriers + multi-value butterfly. hbar -> bf16.
// ---------------------------------------------------------------------------
__global__ void __launch_bounds__(256) attn_kernel(
    const float* __restrict__ hist, const __nv_bfloat16* __restrict__ qk,
    __nv_bfloat16* __restrict__ hbar)
{
    __shared__ float red[H_HEADS][NPREV][8];
    __shared__ __align__(16) float attn_s[H_HEADS][NPREV];

    const int m    = blockIdx.x;
    const int tid  = threadIdx.x;
    const int lane = tid & 31;
    const int warp = tid >> 5;

    const __nv_bfloat16* qrow = qk + (size_t)m * (H_HEADS * D_DIM) + tid * 4;
    uint2 q2[H_HEADS];
#pragma unroll
    for (int h = 0; h < H_HEADS; h++)
        q2[h] = *(const uint2*)(qrow + h * D_DIM);

    float4 hv[NPREV];
    const float* hg = hist + (size_t)m * NPREV * D_DIM + tid * 4;
#pragma unroll
    for (int n = 0; n < NPREV; n++)
        hv[n] = *(const float4*)(hg + n * D_DIM);

    // ---- Phase A: dots + multi-value butterfly reduction ----
#pragma unroll
    for (int h = 0; h < H_HEADS; h++) {
        float2 qa = __bfloat1622float2(*reinterpret_cast<__nv_bfloat162*>(&q2[h].x));
        float2 qb = __bfloat1622float2(*reinterpret_cast<__nv_bfloat162*>(&q2[h].y));
        float p[NPREV];
#pragma unroll
        for (int n = 0; n < NPREV; n++)
            p[n] = qa.x * hv[n].x + qa.y * hv[n].y
                 + qb.x * hv[n].z + qb.y * hv[n].w;

#pragma unroll
        for (int i = 0; i < 4; i++) {
            float send = (lane & 16) ? p[i] : p[i + 4];
            float recv = __shfl_xor_sync(0xffffffffu, send, 16);
            p[i] = ((lane & 16) ? p[i + 4] : p[i]) + recv;
        }
#pragma unroll
        for (int i = 0; i < 2; i++) {
            float send = (lane & 8) ? p[i] : p[i + 2];
            float recv = __shfl_xor_sync(0xffffffffu, send, 8);
            p[i] = ((lane & 8) ? p[i + 2] : p[i]) + recv;
        }
        {
            float send = (lane & 4) ? p[0] : p[1];
            float recv = __shfl_xor_sync(0xffffffffu, send, 4);
            p[0] = ((lane & 4) ? p[1] : p[0]) + recv;
        }
        p[0] += __shfl_xor_sync(0xffffffffu, p[0], 2);
        p[0] += __shfl_xor_sync(0xffffffffu, p[0], 1);
        if ((lane & 3) == 0) red[h][lane >> 2][warp] = p[0];
    }
    __syncthreads();

    // ---- Phase B: 16 parallel softmaxes ----
    if (tid < H_HEADS) {
        const int h = tid;
        float lg[NPREV];
        float mx = -1e30f;
#pragma unroll
        for (int n = 0; n < NPREV; n++) {
            float4 s0 = *(const float4*)&red[h][n][0];
            float4 s1 = *(const float4*)&red[h][n][4];
            float s = (s0.x + s0.y) + (s0.z + s0.w)
                    + (s1.x + s1.y) + (s1.z + s1.w);
            lg[n] = s * 0.125f;
            mx = fmaxf(mx, lg[n]);
        }
        float den = 0.0f;
#pragma unroll
        for (int n = 0; n < NPREV; n++) { lg[n] = expf(lg[n] - mx); den += lg[n]; }
        float inv = 1.0f / den;
#pragma unroll
        for (int n = 0; n < NPREV; n++) attn_s[h][n] = lg[n] * inv;
    }
    __syncthreads();

    // ---- Phase C: weighted sums + bf16 stores ----
    __nv_bfloat16* orow = hbar + (size_t)m * (H_HEADS * D_DIM) + tid * 4;
#pragma unroll
    for (int h = 0; h < H_HEADS; h++) {
        float4 w0 = *(const float4*)&attn_s[h][0];
        float4 w1 = *(const float4*)&attn_s[h][4];
        float4 a4;
        a4.x = w0.x * hv[0].x; a4.y = w0.x * hv[0].y;
        a4.z = w0.x * hv[0].z; a4.w = w0.x * hv[0].w;
        a4.x = fmaf(w0.y, hv[1].x, a4.x); a4.y = fmaf(w0.y, hv[1].y, a4.y);
        a4.z = fmaf(w0.y, hv[1].z, a4.z); a4.w = fmaf(w0.y, hv[1].w, a4.w);
        a4.x = fmaf(w0.z, hv[2].x, a4.x); a4.y = fmaf(w0.z, hv[2].y, a4.y);
        a4.z = fmaf(w0.z, hv[2].z, a4.z); a4.w = fmaf(w0.z, hv[2].w, a4.w);
        a4.x = fmaf(w0.w, hv[3].x, a4.x); a4.y = fmaf(w0.w, hv[3].y, a4.y);
        a4.z = fmaf(w0.w, hv[3].z, a4.z); a4.w = fmaf(w0.w, hv[3].w, a4.w);
        a4.x = fmaf(w1.x, hv[4].x, a4.x); a4.y = fmaf(w1.x, hv[4].y, a4.y);
        a4.z = fmaf(w1.x, hv[4].z, a4.z); a4.w = fmaf(w1.x, hv[4].w, a4.w);
        a4.x = fmaf(w1.y, hv[5].x, a4.x); a4.y = fmaf(w1.y, hv[5].y, a4.y);
        a4.z = fmaf(w1.y, hv[5].z, a4.z); a4.w = fmaf(w1.y, hv[5].w, a4.w);
        a4.x = fmaf(w1.z, hv[6].x, a4.x); a4.y = fmaf(w1.z, hv[6].y, a4.y);
        a4.z = fmaf(w1.z, hv[6].z, a4.z); a4.w = fmaf(w1.z, hv[6].w, a4.w);
        a4.x = fmaf(w1.w, hv[7].x, a4.x); a4.y = fmaf(w1.w, hv[7].y, a4.y);
        a4.z = fmaf(w1.w, hv[7].z, a4.z); a4.w = fmaf(w1.w, hv[7].w, a4.w);
        uint2 ov;
        __nv_bfloat162 o0 = __float22bfloat162_rn(make_float2(a4.x, a4.y));
        __nv_bfloat162 o1 = __float22bfloat162_rn(make_float2(a4.z, a4.w));
        ov.x = *reinterpret_cast<uint32_t*>(&o0);
        ov.y = *reinterpret_cast<uint32_t*>(&o1);
        *(uint2*)(orow + h * D_DIM) = ov;
    }
}

// ---------------------------------------------------------------------------
extern "C" void kernel_launch(void* const* d_in, const int* in_sizes, int n_in,
                              void* d_out, int out_size)
{
    const float* cur  = (const float*)d_in[0];
    const float* hist = (const float*)d_in[1];
    const float* Wq   = (const float*)d_in[2];
    const float* Wk   = (const float*)d_in[3];
    const float* Wv   = (const float*)d_in[4];
    const float* Wo   = (const float*)d_in[5];
    float* out = (float*)d_out;

    const int D = D_DIM;
    const int M = in_sizes[0] / D;   // 8192

    __nv_bfloat16 *cb = nullptr, *qb = nullptr, *qk = nullptr, *hb = nullptr;
    __nv_bfloat16 *ob = nullptr, *wq = nullptr, *wkt = nullptr, *wv = nullptr, *wo = nullptr;
    cudaGetSymbolAddress((void**)&cb,  g_cb);
    cudaGetSymbolAddress((void**)&qb,  g_qb);
    cudaGetSymbolAddress((void**)&qk,  g_qk);
    cudaGetSymbolAddress((void**)&hb,  g_hb);
    cudaGetSymbolAddress((void**)&ob,  g_ob);
    cudaGetSymbolAddress((void**)&wq,  g_wq);
    cudaGetSymbolAddress((void**)&wkt, g_wkt);
    cudaGetSymbolAddress((void**)&wv,  g_wv);
    cudaGetSymbolAddress((void**)&wo,  g_wo);

    constexpr int SM_K2   = (128 * 72 + 2 * (128 * 72)) * 2;          // 55296
    constexpr int SM_B64  = (2 * (128 * 72) + 2 * (64 * 72)) * 2;     // 55296
    constexpr int SM_B128 = (2 * (128 * 72) + 2 * (128 * 72)) * 2;    // 73728

    cudaFuncSetAttribute(gemm_k2,
                         cudaFuncAttributeMaxDynamicSharedMemorySize, SM_K2);
    cudaFuncSetAttribute(gemm_bf16<64, true,  false>,
                         cudaFuncAttributeMaxDynamicSharedMemorySize, SM_B64);
    cudaFuncSetAttribute(gemm_bf16<128, true,  false>,
                         cudaFuncAttributeMaxDynamicSharedMemorySize, SM_B128);
    cudaFuncSetAttribute(gemm_bf16<128, false, true>,
                         cudaFuncAttributeMaxDynamicSharedMemorySize, SM_B128);

    // P0: conversions
    convert_f2b<<<M * D / 4 / 256, 256>>>(cur, cb);
    convert_f2b<<<D * D / 4 / 256, 256>>>(Wq, wq);
    transpose_wk_bf16<<<dim3(32, 32), dim3(32, 8)>>>(Wk, wkt);
    convert_f2b<<<D * D / 4 / 256, 256>>>(Wv, wv);
    convert_f2b<<<D * D / 4 / 256, 256>>>(Wo, wo);

    // K1: q = cur @ Wq^T  (bf16) -> bf16
    gemm_bf16<128, true, false>
        <<<dim3(D / 128, M / 128, 1), 256, SM_B128>>>(
            cb, D, 0, wq, D, 0, nullptr, qb, D, 0, D);

    // K2: qk_h = q_h @ Wk_h  (bf16, persistent j-loop) -> bf16
    gemm_k2<<<dim3(M / 128, H_HEADS), 256, SM_K2>>>(qb, wkt, qk);

    // K3: attention -> hbar (bf16)
    attn_kernel<<<M, 256>>>(hist, qk, hb);

    // K4: out_h = hbar_h @ Wv_h^T (bf16) -> out bf16
    gemm_bf16<64, true, false>
        <<<dim3(1, M / 128, H_HEADS), 256, SM_B64>>>(
            hb, H_HEADS * D, D,
            wv, D, (long long)HD * D,
            nullptr,
            ob, D, HD,
            D);

    // K5: final = cur + out @ Wo^T  (bf16 + fp32 residual)
    gemm_bf16<128, false, true>
        <<<dim3(D / 128, M / 128, 1), 256, SM_B128>>>(
            ob, D, 0, wo, D, 0, cur, out, D, 0, D);
}

// round 13
// speedup vs baseline: 2.9546x; 1.0534x over previous
#include <cuda_runtime.h>
#include <cuda_bf16.h>
#include <cstdint>

// ============================================================================
// CrossDepthAttention, mma.sync tensor cores (base-target legal).
//   P0: cur,Wq,Wv,Wo -> bf16; Wk -> transpose+bf16
//   K1: q    = cur @ Wq^T            bf16 (ldmatrix, staged epilogue)
//   K2: qk_h = q_h @ Wk_h            bf16 persistent j-loop (staged epilogue)
//   K3: fused attention (2 barriers, multi-value butterfly) -> hbar bf16
//   K4: out_h = hbar_h @ Wv_h^T      bf16 (staged epilogue) -> out bf16
//   K5: final = cur + out @ Wo^T     bf16 + fp32 residual (sector-clean)
// ============================================================================

#define D_DIM   1024
#define H_HEADS 16
#define HD      64
#define NPREV   8
#define M_MAX   8192

__device__ __nv_bfloat16 g_cb[M_MAX * D_DIM];                      // cur (bf16)
__device__ __nv_bfloat16 g_qb[M_MAX * D_DIM];                      // q (bf16)
__device__ __nv_bfloat16 g_qk[(size_t)M_MAX * H_HEADS * D_DIM];    // qk (bf16)
__device__ __nv_bfloat16 g_hb[(size_t)M_MAX * H_HEADS * D_DIM];    // hbar (bf16)
__device__ __nv_bfloat16 g_ob[M_MAX * D_DIM];                      // out (bf16)
__device__ __nv_bfloat16 g_wq[D_DIM * D_DIM];                      // Wq (bf16)
__device__ __nv_bfloat16 g_wkt[D_DIM * D_DIM];                     // Wk^T (bf16)
__device__ __nv_bfloat16 g_wv[D_DIM * D_DIM];                      // Wv (bf16)
__device__ __nv_bfloat16 g_wo[D_DIM * D_DIM];                      // Wo (bf16)

// ---------------------------------------------------------------------------
__device__ __forceinline__ uint32_t smem_u32(const void* p) {
    uint32_t a;
    asm("{ .reg .u64 t; cvta.to.shared.u64 t, %1; cvt.u32.u64 %0, t; }"
        : "=r"(a) : "l"(p));
    return a;
}
__device__ __forceinline__ void cp16(uint32_t s, const void* g) {
    asm volatile("cp.async.cg.shared.global [%0], [%1], 16;\n" :: "r"(s), "l"(g));
}
__device__ __forceinline__ void cp_commit() {
    asm volatile("cp.async.commit_group;\n" ::: "memory");
}
template <int N> __device__ __forceinline__ void cp_wait() {
    asm volatile("cp.async.wait_group %0;\n" :: "n"(N) : "memory");
}
__device__ __forceinline__ void mma_bf16(float* c, const uint32_t* a,
                                         const uint32_t* b) {
    asm volatile(
        "mma.sync.aligned.m16n8k16.row.col.f32.bf16.bf16.f32 "
        "{%0,%1,%2,%3}, {%4,%5,%6,%7}, {%8,%9}, {%0,%1,%2,%3};\n"
        : "+f"(c[0]), "+f"(c[1]), "+f"(c[2]), "+f"(c[3])
        : "r"(a[0]), "r"(a[1]), "r"(a[2]), "r"(a[3]), "r"(b[0]), "r"(b[1]));
}
__device__ __forceinline__ void ldsm_x4(uint32_t& r0, uint32_t& r1,
                                        uint32_t& r2, uint32_t& r3,
                                        uint32_t addr) {
    asm volatile("ldmatrix.sync.aligned.m8n8.x4.shared.b16 {%0,%1,%2,%3}, [%4];"
                 : "=r"(r0), "=r"(r1), "=r"(r2), "=r"(r3) : "r"(addr));
}
__device__ __forceinline__ uint32_t pack_bf162(float lo, float hi) {
    __nv_bfloat162 p = __float22bfloat162_rn(make_float2(lo, hi));
    return *reinterpret_cast<uint32_t*>(&p);
}

// ---------------------------------------------------------------------------
// P0a: Wk transpose + bf16 convert, tiled 32x32.
// ---------------------------------------------------------------------------
__global__ void __launch_bounds__(256) transpose_wk_bf16(
    const float* __restrict__ in, __nv_bfloat16* __restrict__ outp)
{
    __shared__ float t[32][33];
    const int bx = blockIdx.x * 32, by = blockIdx.y * 32;
    int x = bx + threadIdx.x;
#pragma unroll
    for (int i = 0; i < 32; i += 8)
        t[threadIdx.y + i][threadIdx.x] = in[(size_t)(by + threadIdx.y + i) * D_DIM + x];
    __syncthreads();
    x = by + threadIdx.x;
#pragma unroll
    for (int i = 0; i < 32; i += 8)
        outp[(size_t)(bx + threadIdx.y + i) * D_DIM + x] =
            __float2bfloat16(t[threadIdx.x][threadIdx.y + i]);
}

// P0b: generic fp32 -> bf16 (n multiple of 1024)
__global__ void __launch_bounds__(256) convert_f2b(
    const float* __restrict__ in, __nv_bfloat16* __restrict__ outp)
{
    int i = (blockIdx.x * 256 + threadIdx.x) * 4;
    float4 a = *(const float4*)(in + i);
    *(__nv_bfloat162*)(outp + i)     = __float22bfloat162_rn(make_float2(a.x, a.y));
    *(__nv_bfloat162*)(outp + i + 2) = __float22bfloat162_rn(make_float2(a.z, a.w));
}

// ---------------------------------------------------------------------------
// bf16 m16n8k16 GEMM (NT), ldmatrix loads, SMEM-staged bf16 epilogue.
//   C[m,n] = sum_k A[m,k] * B[n*ldb + k]; A,B bf16.
// CTA tile 128 x BN, BK=64 halves, 256 threads, SMEM stride 72 halves.
// ---------------------------------------------------------------------------
template <int BN, bool OUT_BF16, bool RESID>
__global__ void __launch_bounds__(256)
gemm_bf16(const __nv_bfloat16* __restrict__ A, int lda, long long sA,
          const __nv_bfloat16* __restrict__ B, int ldb, long long sB,
          const float* __restrict__ R,
          void* __restrict__ C, int ldc, long long sC, int K)
{
    constexpr int WM = (BN == 128) ? 2 : 4;
    constexpr int MT = 8 / WM;
    constexpr int A_HALVES = 128 * 72;
    constexpr int B_HALVES = BN * 72;
    constexpr int STW = BN + 8;                    // stage stride (halves)

    extern __shared__ __align__(16) __nv_bfloat16 sm_h[];
    const uint32_t sbase = smem_u32(sm_h);

    const int tid = threadIdx.x;
    const int wid = tid >> 5, lane = tid & 31;
    const int wm = wid % WM, wn = wid / WM;
    const int bx = blockIdx.x, by = blockIdx.y, bz = blockIdx.z;

    const __nv_bfloat16* Ah = A + (long long)bz * sA + (size_t)(by * 128) * lda;
    const __nv_bfloat16* Bh = B + (long long)bz * sB + (size_t)(bx * BN) * ldb;

    auto fill = [&](int buf, int k0) {
        const uint32_t Ab = sbase + (uint32_t)(buf * A_HALVES) * 2u;
        const uint32_t Bb = sbase + (uint32_t)(2 * A_HALVES + buf * B_HALVES) * 2u;
#pragma unroll
        for (int p = 0; p < 4; ++p) {
            int ch = tid + p * 256;
            int row = ch >> 3, c8 = ch & 7;
            cp16(Ab + (uint32_t)(row * 72 + c8 * 8) * 2u,
                 Ah + (size_t)row * lda + k0 + c8 * 8);
        }
#pragma unroll
        for (int p = 0; p < BN * 8 / 256; ++p) {
            int ch = tid + p * 256;
            int row = ch >> 3, c8 = ch & 7;
            cp16(Bb + (uint32_t)(row * 72 + c8 * 8) * 2u,
                 Bh + (size_t)row * ldb + k0 + c8 * 8);
        }
    };

    float acc[MT][4][4];
#pragma unroll
    for (int mt = 0; mt < MT; ++mt)
#pragma unroll
        for (int nt = 0; nt < 4; ++nt)
#pragma unroll
            for (int j = 0; j < 4; ++j) acc[mt][nt][j] = 0.0f;

    // ldmatrix lane address bases (in halves)
    const int r8 = lane & 7;
    const int a_base_h = (wm * (128 / WM) + ((lane >> 3) & 1) * 8 + r8) * 72
                       + ((lane >> 4) & 1) * 8;
    const int b_sel = (lane >> 3) & 3;
    const int b_base_h = (wn * 32 + (b_sel >> 1) * 8 + r8) * 72 + (b_sel & 1) * 8;

    const int NC = K / 64;
    fill(0, 0);
    cp_commit();

    for (int c = 0; c < NC; ++c) {
        if (c + 1 < NC) { fill((c + 1) & 1, (c + 1) * 64); cp_commit(); cp_wait<1>(); }
        else            { cp_wait<0>(); }
        __syncthreads();

        const int buf = c & 1;
        const uint32_t Ab = sbase + (uint32_t)(buf * A_HALVES) * 2u;
        const uint32_t Bb = sbase + (uint32_t)(2 * A_HALVES + buf * B_HALVES) * 2u;

#pragma unroll
        for (int s = 0; s < 4; ++s) {
            uint32_t af[MT][4];
#pragma unroll
            for (int mt = 0; mt < MT; ++mt)
                ldsm_x4(af[mt][0], af[mt][1], af[mt][2], af[mt][3],
                        Ab + (uint32_t)(a_base_h + mt * 16 * 72 + s * 16) * 2u);
            uint32_t bfr[4][2];
#pragma unroll
            for (int ntp = 0; ntp < 2; ++ntp)
                ldsm_x4(bfr[2 * ntp][0], bfr[2 * ntp][1],
                        bfr[2 * ntp + 1][0], bfr[2 * ntp + 1][1],
                        Bb + (uint32_t)(b_base_h + ntp * 16 * 72 + s * 16) * 2u);
#pragma unroll
            for (int mt = 0; mt < MT; ++mt)
#pragma unroll
                for (int nt = 0; nt < 4; ++nt)
                    mma_bf16(acc[mt][nt], af[mt], bfr[nt]);
        }
        __syncthreads();
    }

    const int g = lane >> 2, tg = lane & 3;
    if (!OUT_BF16) {
        const int row0 = by * 128 + wm * (128 / WM) + g;
        const int coll = wn * 32 + tg * 2;
#pragma unroll
        for (int mt = 0; mt < MT; ++mt) {
            const int m = row0 + mt * 16;
#pragma unroll
            for (int nt = 0; nt < 4; ++nt) {
                const int n = bx * BN + coll + nt * 8;
                float* Cg = (float*)C + (long long)bz * sC;
                float2 v0 = make_float2(acc[mt][nt][0], acc[mt][nt][1]);
                float2 v1 = make_float2(acc[mt][nt][2], acc[mt][nt][3]);
                if (RESID) {
                    float2 r0 = *(const float2*)(R + (size_t)m * ldc + n);
                    float2 r1 = *(const float2*)(R + (size_t)(m + 8) * ldc + n);
                    v0.x += r0.x; v0.y += r0.y;
                    v1.x += r1.x; v1.y += r1.y;
                }
                *(float2*)(Cg + (size_t)m * ldc + n)       = v0;
                *(float2*)(Cg + (size_t)(m + 8) * ldc + n) = v1;
            }
        }
    } else {
        // staged epilogue: SMEM stage tile -> coalesced 16B stores
        __nv_bfloat16* stg = sm_h + 2 * A_HALVES + 2 * B_HALVES;
        const int ml0 = wm * (128 / WM) + g;
        const int nl0 = wn * 32 + tg * 2;
#pragma unroll
        for (int mt = 0; mt < MT; ++mt) {
            const int ml = ml0 + mt * 16;
#pragma unroll
            for (int nt = 0; nt < 4; ++nt) {
                const int nl = nl0 + nt * 8;
                *(uint32_t*)&stg[ml * STW + nl] =
                    pack_bf162(acc[mt][nt][0], acc[mt][nt][1]);
                *(uint32_t*)&stg[(ml + 8) * STW + nl] =
                    pack_bf162(acc[mt][nt][2], acc[mt][nt][3]);
            }
        }
        __syncthreads();
        __nv_bfloat16* Cg = (__nv_bfloat16*)C + (long long)bz * sC;
#pragma unroll
        for (int p = 0; p < 128 * BN / 8 / 256; ++p) {
            int ch = tid + p * 256;
            int row = ch / (BN / 8), c8 = ch % (BN / 8);
            uint4 v = *(uint4*)&stg[row * STW + c8 * 8];
            *(uint4*)(Cg + (size_t)(by * 128 + row) * ldc + bx * BN + c8 * 8) = v;
        }
    }
}

// ---------------------------------------------------------------------------
// K2: persistent j-loop bf16 GEMM, ldmatrix, SMEM-staged epilogue.
//   qk[m, h*1024 + j] = sum_d q[m, h*64+d] * wkt[j, h*64+d]
// ---------------------------------------------------------------------------
__global__ void __launch_bounds__(256)
gemm_k2(const __nv_bfloat16* __restrict__ Q,
        const __nv_bfloat16* __restrict__ WKT,
        __nv_bfloat16* __restrict__ QK)
{
    constexpr int A_HALVES = 128 * 72;
    constexpr int B_HALVES = 128 * 72;
    constexpr int STW = 136;                       // stage stride (halves)

    extern __shared__ __align__(16) __nv_bfloat16 sm_h[];
    const uint32_t sbase = smem_u32(sm_h);

    const int tid = threadIdx.x;
    const int wid = tid >> 5, lane = tid & 31;
    const int wm = wid & 1, wn = wid >> 1;
    const int by = blockIdx.x;           // m-tile
    const int h  = blockIdx.y;           // head

    const __nv_bfloat16* Ah = Q + (size_t)(by * 128) * D_DIM + h * HD;
    const __nv_bfloat16* Bh = WKT + h * HD;

    // A: 128 rows x 64 halves = 1024 chunks of 16B (4 per thread)
#pragma unroll
    for (int p = 0; p < 4; ++p) {
        int ch = tid + p * 256;
        int row = ch >> 3, c8 = ch & 7;
        cp16(sbase + (uint32_t)(row * 72 + c8 * 8) * 2u,
             Ah + (size_t)row * D_DIM + c8 * 8);
    }
    auto fillB = [&](int buf, int j0) {
        const uint32_t Bb = sbase + (uint32_t)(A_HALVES + buf * B_HALVES) * 2u;
#pragma unroll
        for (int p = 0; p < 4; ++p) {
            int ch = tid + p * 256;
            int row = ch >> 3, c8 = ch & 7;
            cp16(Bb + (uint32_t)(row * 72 + c8 * 8) * 2u,
                 Bh + (size_t)(j0 + row) * D_DIM + c8 * 8);
        }
    };
    fillB(0, 0);
    cp_commit();        // group 0: A + B0

    // ldmatrix bases
    const int r8 = lane & 7;
    const int a_base_h = (wm * 64 + ((lane >> 3) & 1) * 8 + r8) * 72
                       + ((lane >> 4) & 1) * 8;
    const int b_sel = (lane >> 3) & 3;
    const int b_base_h = (wn * 32 + (b_sel >> 1) * 8 + r8) * 72 + (b_sel & 1) * 8;

    const int g = lane >> 2, tg = lane & 3;
    __nv_bfloat16* stg = sm_h + A_HALVES + 2 * B_HALVES;

    for (int jt = 0; jt < 8; ++jt) {
        if (jt + 1 < 8) { fillB((jt + 1) & 1, (jt + 1) * 128); cp_commit(); cp_wait<1>(); }
        else            { cp_wait<0>(); }
        __syncthreads();

        const uint32_t Bb = sbase + (uint32_t)(A_HALVES + (jt & 1) * B_HALVES) * 2u;

        float acc[4][4][4];
#pragma unroll
        for (int mt = 0; mt < 4; ++mt)
#pragma unroll
            for (int nt = 0; nt < 4; ++nt)
#pragma unroll
                for (int j = 0; j < 4; ++j) acc[mt][nt][j] = 0.0f;

#pragma unroll
        for (int s = 0; s < 4; ++s) {              // 4 x k16 over K=64
            uint32_t af[4][4];
#pragma unroll
            for (int mt = 0; mt < 4; ++mt)
                ldsm_x4(af[mt][0], af[mt][1], af[mt][2], af[mt][3],
                        sbase + (uint32_t)(a_base_h + mt * 16 * 72 + s * 16) * 2u);
            uint32_t bfr[4][2];
#pragma unroll
            for (int ntp = 0; ntp < 2; ++ntp)
                ldsm_x4(bfr[2 * ntp][0], bfr[2 * ntp][1],
                        bfr[2 * ntp + 1][0], bfr[2 * ntp + 1][1],
                        Bb + (uint32_t)(b_base_h + ntp * 16 * 72 + s * 16) * 2u);
#pragma unroll
            for (int mt = 0; mt < 4; ++mt)
#pragma unroll
                for (int nt = 0; nt < 4; ++nt)
                    mma_bf16(acc[mt][nt], af[mt], bfr[nt]);
        }

        // staged epilogue for this j-tile
        const int ml0 = wm * 64 + g;
        const int nl0 = wn * 32 + tg * 2;
#pragma unroll
        for (int mt = 0; mt < 4; ++mt) {
            const int ml = ml0 + mt * 16;
#pragma unroll
            for (int nt = 0; nt < 4; ++nt) {
                const int nl = nl0 + nt * 8;
                *(uint32_t*)&stg[ml * STW + nl] =
                    pack_bf162(acc[mt][nt][0], acc[mt][nt][1]);
                *(uint32_t*)&stg[(ml + 8) * STW + nl] =
                    pack_bf162(acc[mt][nt][2], acc[mt][nt][3]);
            }
        }
        __syncthreads();
        __nv_bfloat16* Cg = QK + (size_t)h * D_DIM + (size_t)jt * 128;
#pragma unroll
        for (int p = 0; p < 8; ++p) {
            int ch = tid + p * 256;
            int row = ch >> 4, c8 = ch & 15;
            uint4 v = *(uint4*)&stg[row * STW + c8 * 8];
            *(uint4*)(Cg + (size_t)(by * 128 + row) * (H_HEADS * D_DIM) + c8 * 8) = v;
        }
    }
}

// ---------------------------------------------------------------------------
// K3: fused attention — 2 barriers + multi-value butterfly. hbar -> bf16.
// ---------------------------------------------------------------------------
__global__ void __launch_bounds__(256) attn_kernel(
    const float* __restrict__ hist, const __nv_bfloat16* __restrict__ qk,
    __nv_bfloat16* __restrict__ hbar)
{
    __shared__ float red[H_HEADS][NPREV][8];
    __shared__ __align__(16) float attn_s[H_HEADS][NPREV];

    const int m    = blockIdx.x;
    const int tid  = threadIdx.x;
    const int lane = tid & 31;
    const int warp = tid >> 5;

    const __nv_bfloat16* qrow = qk + (size_t)m * (H_HEADS * D_DIM) + tid * 4;
    uint2 q2[H_HEADS];
#pragma unroll
    for (int h = 0; h < H_HEADS; h++)
        q2[h] = *(const uint2*)(qrow + h * D_DIM);

    float4 hv[NPREV];
    const float* hg = hist + (size_t)m * NPREV * D_DIM + tid * 4;
#pragma unroll
    for (int n = 0; n < NPREV; n++)
        hv[n] = *(const float4*)(hg + n * D_DIM);

    // ---- Phase A: dots + multi-value butterfly reduction ----
#pragma unroll
    for (int h = 0; h < H_HEADS; h++) {
        float2 qa = __bfloat1622float2(*reinterpret_cast<__nv_bfloat162*>(&q2[h].x));
        float2 qb = __bfloat1622float2(*reinterpret_cast<__nv_bfloat162*>(&q2[h].y));
        float p[NPREV];
#pragma unroll
        for (int n = 0; n < NPREV; n++)
            p[n] = qa.x * hv[n].x + qa.y * hv[n].y
                 + qb.x * hv[n].z + qb.y * hv[n].w;

#pragma unroll
        for (int i = 0; i < 4; i++) {
            float send = (lane & 16) ? p[i] : p[i + 4];
            float recv = __shfl_xor_sync(0xffffffffu, send, 16);
            p[i] = ((lane & 16) ? p[i + 4] : p[i]) + recv;
        }
#pragma unroll
        for (int i = 0; i < 2; i++) {
            float send = (lane & 8) ? p[i] : p[i + 2];
            float recv = __shfl_xor_sync(0xffffffffu, send, 8);
            p[i] = ((lane & 8) ? p[i + 2] : p[i]) + recv;
        }
        {
            float send = (lane & 4) ? p[0] : p[1];
            float recv = __shfl_xor_sync(0xffffffffu, send, 4);
            p[0] = ((lane & 4) ? p[1] : p[0]) + recv;
        }
        p[0] += __shfl_xor_sync(0xffffffffu, p[0], 2);
        p[0] += __shfl_xor_sync(0xffffffffu, p[0], 1);
        if ((lane & 3) == 0) red[h][lane >> 2][warp] = p[0];
    }
    __syncthreads();

    // ---- Phase B: 16 parallel softmaxes ----
    if (tid < H_HEADS) {
        const int h = tid;
        float lg[NPREV];
        float mx = -1e30f;
#pragma unroll
        for (int n = 0; n < NPREV; n++) {
            float4 s0 = *(const float4*)&red[h][n][0];
            float4 s1 = *(const float4*)&red[h][n][4];
            float s = (s0.x + s0.y) + (s0.z + s0.w)
                    + (s1.x + s1.y) + (s1.z + s1.w);
            lg[n] = s * 0.125f;
            mx = fmaxf(mx, lg[n]);
        }
        float den = 0.0f;
#pragma unroll
        for (int n = 0; n < NPREV; n++) { lg[n] = expf(lg[n] - mx); den += lg[n]; }
        float inv = 1.0f / den;
#pragma unroll
        for (int n = 0; n < NPREV; n++) attn_s[h][n] = lg[n] * inv;
    }
    __syncthreads();

    // ---- Phase C: weighted sums + bf16 stores ----
    __nv_bfloat16* orow = hbar + (size_t)m * (H_HEADS * D_DIM) + tid * 4;
#pragma unroll
    for (int h = 0; h < H_HEADS; h++) {
        float4 w0 = *(const float4*)&attn_s[h][0];
        float4 w1 = *(const float4*)&attn_s[h][4];
        float4 a4;
        a4.x = w0.x * hv[0].x; a4.y = w0.x * hv[0].y;
        a4.z = w0.x * hv[0].z; a4.w = w0.x * hv[0].w;
        a4.x = fmaf(w0.y, hv[1].x, a4.x); a4.y = fmaf(w0.y, hv[1].y, a4.y);
        a4.z = fmaf(w0.y, hv[1].z, a4.z); a4.w = fmaf(w0.y, hv[1].w, a4.w);
        a4.x = fmaf(w0.z, hv[2].x, a4.x); a4.y = fmaf(w0.z, hv[2].y, a4.y);
        a4.z = fmaf(w0.z, hv[2].z, a4.z); a4.w = fmaf(w0.z, hv[2].w, a4.w);
        a4.x = fmaf(w0.w, hv[3].x, a4.x); a4.y = fmaf(w0.w, hv[3].y, a4.y);
        a4.z = fmaf(w0.w, hv[3].z, a4.z); a4.w = fmaf(w0.w, hv[3].w, a4.w);
        a4.x = fmaf(w1.x, hv[4].x, a4.x); a4.y = fmaf(w1.x, hv[4].y, a4.y);
        a4.z = fmaf(w1.x, hv[4].z, a4.z); a4.w = fmaf(w1.x, hv[4].w, a4.w);
        a4.x = fmaf(w1.y, hv[5].x, a4.x); a4.y = fmaf(w1.y, hv[5].y, a4.y);
        a4.z = fmaf(w1.y, hv[5].z, a4.z); a4.w = fmaf(w1.y, hv[5].w, a4.w);
        a4.x = fmaf(w1.z, hv[6].x, a4.x); a4.y = fmaf(w1.z, hv[6].y, a4.y);
        a4.z = fmaf(w1.z, hv[6].z, a4.z); a4.w = fmaf(w1.z, hv[6].w, a4.w);
        a4.x = fmaf(w1.w, hv[7].x, a4.x); a4.y = fmaf(w1.w, hv[7].y, a4.y);
        a4.z = fmaf(w1.w, hv[7].z, a4.z); a4.w = fmaf(w1.w, hv[7].w, a4.w);
        uint2 ov;
        ov.x = pack_bf162(a4.x, a4.y);
        ov.y = pack_bf162(a4.z, a4.w);
        *(uint2*)(orow + h * D_DIM) = ov;
    }
}

// ---------------------------------------------------------------------------
extern "C" void kernel_launch(void* const* d_in, const int* in_sizes, int n_in,
                              void* d_out, int out_size)
{
    const float* cur  = (const float*)d_in[0];
    const float* hist = (const float*)d_in[1];
    const float* Wq   = (const float*)d_in[2];
    const float* Wk   = (const float*)d_in[3];
    const float* Wv   = (const float*)d_in[4];
    const float* Wo   = (const float*)d_in[5];
    float* out = (float*)d_out;

    const int D = D_DIM;
    const int M = in_sizes[0] / D;   // 8192

    __nv_bfloat16 *cb = nullptr, *qb = nullptr, *qk = nullptr, *hb = nullptr;
    __nv_bfloat16 *ob = nullptr, *wq = nullptr, *wkt = nullptr, *wv = nullptr, *wo = nullptr;
    cudaGetSymbolAddress((void**)&cb,  g_cb);
    cudaGetSymbolAddress((void**)&qb,  g_qb);
    cudaGetSymbolAddress((void**)&qk,  g_qk);
    cudaGetSymbolAddress((void**)&hb,  g_hb);
    cudaGetSymbolAddress((void**)&ob,  g_ob);
    cudaGetSymbolAddress((void**)&wq,  g_wq);
    cudaGetSymbolAddress((void**)&wkt, g_wkt);
    cudaGetSymbolAddress((void**)&wv,  g_wv);
    cudaGetSymbolAddress((void**)&wo,  g_wo);

    // SMEM budgets (bytes)
    constexpr int SM_K2     = (128 * 72 + 2 * (128 * 72) + 128 * 136) * 2;   // 90112
    constexpr int SM_B64_S  = (2 * (128 * 72) + 2 * (64 * 72) + 128 * 72) * 2;   // 73728
    constexpr int SM_B128_S = (2 * (128 * 72) + 2 * (128 * 72) + 128 * 136) * 2; // 108544
    constexpr int SM_B128   = (2 * (128 * 72) + 2 * (128 * 72)) * 2;             // 73728

    cudaFuncSetAttribute(gemm_k2,
                         cudaFuncAttributeMaxDynamicSharedMemorySize, SM_K2);
    cudaFuncSetAttribute(gemm_bf16<64, true,  false>,
                         cudaFuncAttributeMaxDynamicSharedMemorySize, SM_B64_S);
    cudaFuncSetAttribute(gemm_bf16<128, true,  false>,
                         cudaFuncAttributeMaxDynamicSharedMemorySize, SM_B128_S);
    cudaFuncSetAttribute(gemm_bf16<128, false, true>,
                         cudaFuncAttributeMaxDynamicSharedMemorySize, SM_B128);

    // P0: conversions
    convert_f2b<<<M * D / 4 / 256, 256>>>(cur, cb);
    convert_f2b<<<D * D / 4 / 256, 256>>>(Wq, wq);
    transpose_wk_bf16<<<dim3(32, 32), dim3(32, 8)>>>(Wk, wkt);
    convert_f2b<<<D * D / 4 / 256, 256>>>(Wv, wv);
    convert_f2b<<<D * D / 4 / 256, 256>>>(Wo, wo);

    // K1: q = cur @ Wq^T  (bf16) -> bf16 (staged)
    gemm_bf16<128, true, false>
        <<<dim3(D / 128, M / 128, 1), 256, SM_B128_S>>>(
            cb, D, 0, wq, D, 0, nullptr, qb, D, 0, D);

    // K2: qk_h = q_h @ Wk_h  (bf16, persistent j-loop, staged) -> bf16
    gemm_k2<<<dim3(M / 128, H_HEADS), 256, SM_K2>>>(qb, wkt, qk);

    // K3: attention -> hbar (bf16)
    attn_kernel<<<M, 256>>>(hist, qk, hb);

    // K4: out_h = hbar_h @ Wv_h^T (bf16, staged) -> out bf16
    gemm_bf16<64, true, false>
        <<<dim3(1, M / 128, H_HEADS), 256, SM_B64_S>>>(
            hb, H_HEADS * D, D,
            wv, D, (long long)HD * D,
            nullptr,
            ob, D, HD,
            D);

    // K5: final = cur + out @ Wo^T  (bf16 + fp32 residual)
    gemm_bf16<128, false, true>
        <<<dim3(D / 128, M / 128, 1), 256, SM_B128>>>(
            ob, D, 0, wo, D, 0, cur, out, D, 0, D);
}

// round 14
// speedup vs baseline: 2.9671x; 1.0042x over previous
#include <cuda_runtime.h>
#include <cuda_bf16.h>
#include <cstdint>

// ============================================================================
// CrossDepthAttention, mma.sync tensor cores (base-target legal).
//   P0: cur -> bf16; {Wq,Wv,Wo} -> bf16 (one launch); Wk -> transpose+bf16
//   K1: q    = cur @ Wq^T            bf16 (ldmatrix, stage aliased on bufs)
//   K2: qk_h = q_h @ Wk_h            bf16 persistent j-loop (dedicated stage)
//   K3: fused attention (2 barriers, multi-value butterfly) -> hbar bf16
//   K4: out_h = hbar_h @ Wv_h^T      bf16 (stage aliased) -> out bf16
//   K5: final = cur + out @ Wo^T     bf16 + fp32 residual (sector-clean)
// ============================================================================

#define D_DIM   1024
#define H_HEADS 16
#define HD      64
#define NPREV   8
#define M_MAX   8192

__device__ __nv_bfloat16 g_cb[M_MAX * D_DIM];                      // cur (bf16)
__device__ __nv_bfloat16 g_qb[M_MAX * D_DIM];                      // q (bf16)
__device__ __nv_bfloat16 g_qk[(size_t)M_MAX * H_HEADS * D_DIM];    // qk (bf16)
__device__ __nv_bfloat16 g_hb[(size_t)M_MAX * H_HEADS * D_DIM];    // hbar (bf16)
__device__ __nv_bfloat16 g_ob[M_MAX * D_DIM];                      // out (bf16)
__device__ __nv_bfloat16 g_wq[D_DIM * D_DIM];                      // Wq (bf16)
__device__ __nv_bfloat16 g_wkt[D_DIM * D_DIM];                     // Wk^T (bf16)
__device__ __nv_bfloat16 g_wv[D_DIM * D_DIM];                      // Wv (bf16)
__device__ __nv_bfloat16 g_wo[D_DIM * D_DIM];                      // Wo (bf16)

// ---------------------------------------------------------------------------
__device__ __forceinline__ uint32_t smem_u32(const void* p) {
    uint32_t a;
    asm("{ .reg .u64 t; cvta.to.shared.u64 t, %1; cvt.u32.u64 %0, t; }"
        : "=r"(a) : "l"(p));
    return a;
}
__device__ __forceinline__ void cp16(uint32_t s, const void* g) {
    asm volatile("cp.async.cg.shared.global [%0], [%1], 16;\n" :: "r"(s), "l"(g));
}
__device__ __forceinline__ void cp_commit() {
    asm volatile("cp.async.commit_group;\n" ::: "memory");
}
template <int N> __device__ __forceinline__ void cp_wait() {
    asm volatile("cp.async.wait_group %0;\n" :: "n"(N) : "memory");
}
__device__ __forceinline__ void mma_bf16(float* c, const uint32_t* a,
                                         const uint32_t* b) {
    asm volatile(
        "mma.sync.aligned.m16n8k16.row.col.f32.bf16.bf16.f32 "
        "{%0,%1,%2,%3}, {%4,%5,%6,%7}, {%8,%9}, {%0,%1,%2,%3};\n"
        : "+f"(c[0]), "+f"(c[1]), "+f"(c[2]), "+f"(c[3])
        : "r"(a[0]), "r"(a[1]), "r"(a[2]), "r"(a[3]), "r"(b[0]), "r"(b[1]));
}
__device__ __forceinline__ void ldsm_x4(uint32_t& r0, uint32_t& r1,
                                        uint32_t& r2, uint32_t& r3,
                                        uint32_t addr) {
    asm volatile("ldmatrix.sync.aligned.m8n8.x4.shared.b16 {%0,%1,%2,%3}, [%4];"
                 : "=r"(r0), "=r"(r1), "=r"(r2), "=r"(r3) : "r"(addr));
}
__device__ __forceinline__ uint32_t pack_bf162(float lo, float hi) {
    __nv_bfloat162 p = __float22bfloat162_rn(make_float2(lo, hi));
    return *reinterpret_cast<uint32_t*>(&p);
}

// ---------------------------------------------------------------------------
// P0a: Wk transpose + bf16 convert, tiled 32x32.
// ---------------------------------------------------------------------------
__global__ void __launch_bounds__(256) transpose_wk_bf16(
    const float* __restrict__ in, __nv_bfloat16* __restrict__ outp)
{
    __shared__ float t[32][33];
    const int bx = blockIdx.x * 32, by = blockIdx.y * 32;
    int x = bx + threadIdx.x;
#pragma unroll
    for (int i = 0; i < 32; i += 8)
        t[threadIdx.y + i][threadIdx.x] = in[(size_t)(by + threadIdx.y + i) * D_DIM + x];
    __syncthreads();
    x = by + threadIdx.x;
#pragma unroll
    for (int i = 0; i < 32; i += 8)
        outp[(size_t)(bx + threadIdx.y + i) * D_DIM + x] =
            __float2bfloat16(t[threadIdx.x][threadIdx.y + i]);
}

// P0b: fp32 -> bf16, single tensor (cur)
__global__ void __launch_bounds__(256) convert_f2b(
    const float* __restrict__ in, __nv_bfloat16* __restrict__ outp)
{
    int i = (blockIdx.x * 256 + threadIdx.x) * 4;
    float4 a = *(const float4*)(in + i);
    *(__nv_bfloat162*)(outp + i)     = __float22bfloat162_rn(make_float2(a.x, a.y));
    *(__nv_bfloat162*)(outp + i + 2) = __float22bfloat162_rn(make_float2(a.z, a.w));
}

// P0c: fp32 -> bf16 for three weight matrices in one launch
__global__ void __launch_bounds__(256) convert_w3(
    const float* __restrict__ w0, __nv_bfloat16* __restrict__ o0,
    const float* __restrict__ w1, __nv_bfloat16* __restrict__ o1,
    const float* __restrict__ w2, __nv_bfloat16* __restrict__ o2)
{
    const float* in;
    __nv_bfloat16* outp;
    if (blockIdx.y == 0)      { in = w0; outp = o0; }
    else if (blockIdx.y == 1) { in = w1; outp = o1; }
    else                      { in = w2; outp = o2; }
    int i = (blockIdx.x * 256 + threadIdx.x) * 4;
    float4 a = *(const float4*)(in + i);
    *(__nv_bfloat162*)(outp + i)     = __float22bfloat162_rn(make_float2(a.x, a.y));
    *(__nv_bfloat162*)(outp + i + 2) = __float22bfloat162_rn(make_float2(a.z, a.w));
}

// ---------------------------------------------------------------------------
// bf16 m16n8k16 GEMM (NT), ldmatrix loads.
//   OUT_BF16 epilogue: staged through SMEM, ALIASED onto the (dead) mainloop
//   buffers -> no extra SMEM, higher occupancy. Safe: stage writes happen
//   only after the final mainloop __syncthreads().
// CTA tile 128 x BN, BK=64 halves, 256 threads, SMEM stride 72 halves.
// ---------------------------------------------------------------------------
template <int BN, bool OUT_BF16, bool RESID>
__global__ void __launch_bounds__(256)
gemm_bf16(const __nv_bfloat16* __restrict__ A, int lda, long long sA,
          const __nv_bfloat16* __restrict__ B, int ldb, long long sB,
          const float* __restrict__ R,
          void* __restrict__ C, int ldc, long long sC, int K)
{
    constexpr int WM = (BN == 128) ? 2 : 4;
    constexpr int MT = 8 / WM;
    constexpr int A_HALVES = 128 * 72;
    constexpr int B_HALVES = BN * 72;
    constexpr int STW = BN + 8;                    // stage stride (halves)

    extern __shared__ __align__(16) __nv_bfloat16 sm_h[];
    const uint32_t sbase = smem_u32(sm_h);

    const int tid = threadIdx.x;
    const int wid = tid >> 5, lane = tid & 31;
    const int wm = wid % WM, wn = wid / WM;
    const int bx = blockIdx.x, by = blockIdx.y, bz = blockIdx.z;

    const __nv_bfloat16* Ah = A + (long long)bz * sA + (size_t)(by * 128) * lda;
    const __nv_bfloat16* Bh = B + (long long)bz * sB + (size_t)(bx * BN) * ldb;

    auto fill = [&](int buf, int k0) {
        const uint32_t Ab = sbase + (uint32_t)(buf * A_HALVES) * 2u;
        const uint32_t Bb = sbase + (uint32_t)(2 * A_HALVES + buf * B_HALVES) * 2u;
#pragma unroll
        for (int p = 0; p < 4; ++p) {
            int ch = tid + p * 256;
            int row = ch >> 3, c8 = ch & 7;
            cp16(Ab + (uint32_t)(row * 72 + c8 * 8) * 2u,
                 Ah + (size_t)row * lda + k0 + c8 * 8);
        }
#pragma unroll
        for (int p = 0; p < BN * 8 / 256; ++p) {
            int ch = tid + p * 256;
            int row = ch >> 3, c8 = ch & 7;
            cp16(Bb + (uint32_t)(row * 72 + c8 * 8) * 2u,
                 Bh + (size_t)row * ldb + k0 + c8 * 8);
        }
    };

    float acc[MT][4][4];
#pragma unroll
    for (int mt = 0; mt < MT; ++mt)
#pragma unroll
        for (int nt = 0; nt < 4; ++nt)
#pragma unroll
            for (int j = 0; j < 4; ++j) acc[mt][nt][j] = 0.0f;

    // ldmatrix lane address bases (in halves)
    const int r8 = lane & 7;
    const int a_base_h = (wm * (128 / WM) + ((lane >> 3) & 1) * 8 + r8) * 72
                       + ((lane >> 4) & 1) * 8;
    const int b_sel = (lane >> 3) & 3;
    const int b_base_h = (wn * 32 + (b_sel >> 1) * 8 + r8) * 72 + (b_sel & 1) * 8;

    const int NC = K / 64;
    fill(0, 0);
    cp_commit();

    for (int c = 0; c < NC; ++c) {
        if (c + 1 < NC) { fill((c + 1) & 1, (c + 1) * 64); cp_commit(); cp_wait<1>(); }
        else            { cp_wait<0>(); }
        __syncthreads();

        const int buf = c & 1;
        const uint32_t Ab = sbase + (uint32_t)(buf * A_HALVES) * 2u;
        const uint32_t Bb = sbase + (uint32_t)(2 * A_HALVES + buf * B_HALVES) * 2u;

#pragma unroll
        for (int s = 0; s < 4; ++s) {
            uint32_t af[MT][4];
#pragma unroll
            for (int mt = 0; mt < MT; ++mt)
                ldsm_x4(af[mt][0], af[mt][1], af[mt][2], af[mt][3],
                        Ab + (uint32_t)(a_base_h + mt * 16 * 72 + s * 16) * 2u);
            uint32_t bfr[4][2];
#pragma unroll
            for (int ntp = 0; ntp < 2; ++ntp)
                ldsm_x4(bfr[2 * ntp][0], bfr[2 * ntp][1],
                        bfr[2 * ntp + 1][0], bfr[2 * ntp + 1][1],
                        Bb + (uint32_t)(b_base_h + ntp * 16 * 72 + s * 16) * 2u);
#pragma unroll
            for (int mt = 0; mt < MT; ++mt)
#pragma unroll
                for (int nt = 0; nt < 4; ++nt)
                    mma_bf16(acc[mt][nt], af[mt], bfr[nt]);
        }
        __syncthreads();
    }

    const int g = lane >> 2, tg = lane & 3;
    if (!OUT_BF16) {
        const int row0 = by * 128 + wm * (128 / WM) + g;
        const int coll = wn * 32 + tg * 2;
#pragma unroll
        for (int mt = 0; mt < MT; ++mt) {
            const int m = row0 + mt * 16;
#pragma unroll
            for (int nt = 0; nt < 4; ++nt) {
                const int n = bx * BN + coll + nt * 8;
                float* Cg = (float*)C + (long long)bz * sC;
                float2 v0 = make_float2(acc[mt][nt][0], acc[mt][nt][1]);
                float2 v1 = make_float2(acc[mt][nt][2], acc[mt][nt][3]);
                if (RESID) {
                    float2 r0 = *(const float2*)(R + (size_t)m * ldc + n);
                    float2 r1 = *(const float2*)(R + (size_t)(m + 8) * ldc + n);
                    v0.x += r0.x; v0.y += r0.y;
                    v1.x += r1.x; v1.y += r1.y;
                }
                *(float2*)(Cg + (size_t)m * ldc + n)       = v0;
                *(float2*)(Cg + (size_t)(m + 8) * ldc + n) = v1;
            }
        }
    } else {
        // staged epilogue ALIASED onto mainloop buffers (dead after last sync)
        __nv_bfloat16* stg = sm_h;
        const int ml0 = wm * (128 / WM) + g;
        const int nl0 = wn * 32 + tg * 2;
#pragma unroll
        for (int mt = 0; mt < MT; ++mt) {
            const int ml = ml0 + mt * 16;
#pragma unroll
            for (int nt = 0; nt < 4; ++nt) {
                const int nl = nl0 + nt * 8;
                *(uint32_t*)&stg[ml * STW + nl] =
                    pack_bf162(acc[mt][nt][0], acc[mt][nt][1]);
                *(uint32_t*)&stg[(ml + 8) * STW + nl] =
                    pack_bf162(acc[mt][nt][2], acc[mt][nt][3]);
            }
        }
        __syncthreads();
        __nv_bfloat16* Cg = (__nv_bfloat16*)C + (long long)bz * sC;
#pragma unroll
        for (int p = 0; p < 128 * BN / 8 / 256; ++p) {
            int ch = tid + p * 256;
            int row = ch / (BN / 8), c8 = ch % (BN / 8);
            uint4 v = *(uint4*)&stg[row * STW + c8 * 8];
            *(uint4*)(Cg + (size_t)(by * 128 + row) * ldc + bx * BN + c8 * 8) = v;
        }
    }
}

// ---------------------------------------------------------------------------
// K2: persistent j-loop bf16 GEMM, ldmatrix, dedicated SMEM stage.
//   qk[m, h*1024 + j] = sum_d q[m, h*64+d] * wkt[j, h*64+d]
// ---------------------------------------------------------------------------
__global__ void __launch_bounds__(256)
gemm_k2(const __nv_bfloat16* __restrict__ Q,
        const __nv_bfloat16* __restrict__ WKT,
        __nv_bfloat16* __restrict__ QK)
{
    constexpr int A_HALVES = 128 * 72;
    constexpr int B_HALVES = 128 * 72;
    constexpr int STW = 136;                       // stage stride (halves)

    extern __shared__ __align__(16) __nv_bfloat16 sm_h[];
    const uint32_t sbase = smem_u32(sm_h);

    const int tid = threadIdx.x;
    const int wid = tid >> 5, lane = tid & 31;
    const int wm = wid & 1, wn = wid >> 1;
    const int by = blockIdx.x;           // m-tile
    const int h  = blockIdx.y;           // head

    const __nv_bfloat16* Ah = Q + (size_t)(by * 128) * D_DIM + h * HD;
    const __nv_bfloat16* Bh = WKT + h * HD;

    // A: 128 rows x 64 halves = 1024 chunks of 16B (4 per thread)
#pragma unroll
    for (int p = 0; p < 4; ++p) {
        int ch = tid + p * 256;
        int row = ch >> 3, c8 = ch & 7;
        cp16(sbase + (uint32_t)(row * 72 + c8 * 8) * 2u,
             Ah + (size_t)row * D_DIM + c8 * 8);
    }
    auto fillB = [&](int buf, int j0) {
        const uint32_t Bb = sbase + (uint32_t)(A_HALVES + buf * B_HALVES) * 2u;
#pragma unroll
        for (int p = 0; p < 4; ++p) {
            int ch = tid + p * 256;
            int row = ch >> 3, c8 = ch & 7;
            cp16(Bb + (uint32_t)(row * 72 + c8 * 8) * 2u,
                 Bh + (size_t)(j0 + row) * D_DIM + c8 * 8);
        }
    };
    fillB(0, 0);
    cp_commit();        // group 0: A + B0

    // ldmatrix bases
    const int r8 = lane & 7;
    const int a_base_h = (wm * 64 + ((lane >> 3) & 1) * 8 + r8) * 72
                       + ((lane >> 4) & 1) * 8;
    const int b_sel = (lane >> 3) & 3;
    const int b_base_h = (wn * 32 + (b_sel >> 1) * 8 + r8) * 72 + (b_sel & 1) * 8;

    const int g = lane >> 2, tg = lane & 3;
    __nv_bfloat16* stg = sm_h + A_HALVES + 2 * B_HALVES;

    for (int jt = 0; jt < 8; ++jt) {
        if (jt + 1 < 8) { fillB((jt + 1) & 1, (jt + 1) * 128); cp_commit(); cp_wait<1>(); }
        else            { cp_wait<0>(); }
        __syncthreads();

        const uint32_t Bb = sbase + (uint32_t)(A_HALVES + (jt & 1) * B_HALVES) * 2u;

        float acc[4][4][4];
#pragma unroll
        for (int mt = 0; mt < 4; ++mt)
#pragma unroll
            for (int nt = 0; nt < 4; ++nt)
#pragma unroll
                for (int j = 0; j < 4; ++j) acc[mt][nt][j] = 0.0f;

#pragma unroll
        for (int s = 0; s < 4; ++s) {              // 4 x k16 over K=64
            uint32_t af[4][4];
#pragma unroll
            for (int mt = 0; mt < 4; ++mt)
                ldsm_x4(af[mt][0], af[mt][1], af[mt][2], af[mt][3],
                        sbase + (uint32_t)(a_base_h + mt * 16 * 72 + s * 16) * 2u);
            uint32_t bfr[4][2];
#pragma unroll
            for (int ntp = 0; ntp < 2; ++ntp)
                ldsm_x4(bfr[2 * ntp][0], bfr[2 * ntp][1],
                        bfr[2 * ntp + 1][0], bfr[2 * ntp + 1][1],
                        Bb + (uint32_t)(b_base_h + ntp * 16 * 72 + s * 16) * 2u);
#pragma unroll
            for (int mt = 0; mt < 4; ++mt)
#pragma unroll
                for (int nt = 0; nt < 4; ++nt)
                    mma_bf16(acc[mt][nt], af[mt], bfr[nt]);
        }

        // staged epilogue for this j-tile
        const int ml0 = wm * 64 + g;
        const int nl0 = wn * 32 + tg * 2;
#pragma unroll
        for (int mt = 0; mt < 4; ++mt) {
            const int ml = ml0 + mt * 16;
#pragma unroll
            for (int nt = 0; nt < 4; ++nt) {
                const int nl = nl0 + nt * 8;
                *(uint32_t*)&stg[ml * STW + nl] =
                    pack_bf162(acc[mt][nt][0], acc[mt][nt][1]);
                *(uint32_t*)&stg[(ml + 8) * STW + nl] =
                    pack_bf162(acc[mt][nt][2], acc[mt][nt][3]);
            }
        }
        __syncthreads();
        __nv_bfloat16* Cg = QK + (size_t)h * D_DIM + (size_t)jt * 128;
#pragma unroll
        for (int p = 0; p < 8; ++p) {
            int ch = tid + p * 256;
            int row = ch >> 4, c8 = ch & 15;
            uint4 v = *(uint4*)&stg[row * STW + c8 * 8];
            *(uint4*)(Cg + (size_t)(by * 128 + row) * (H_HEADS * D_DIM) + c8 * 8) = v;
        }
    }
}

// ---------------------------------------------------------------------------
// K3: fused attention — 2 barriers + multi-value butterfly. hbar -> bf16.
// ---------------------------------------------------------------------------
__global__ void __launch_bounds__(256) attn_kernel(
    const float* __restrict__ hist, const __nv_bfloat16* __restrict__ qk,
    __nv_bfloat16* __restrict__ hbar)
{
    __shared__ float red[H_HEADS][NPREV][8];
    __shared__ __align__(16) float attn_s[H_HEADS][NPREV];

    const int m    = blockIdx.x;
    const int tid  = threadIdx.x;
    const int lane = tid & 31;
    const int warp = tid >> 5;

    const __nv_bfloat16* qrow = qk + (size_t)m * (H_HEADS * D_DIM) + tid * 4;
    uint2 q2[H_HEADS];
#pragma unroll
    for (int h = 0; h < H_HEADS; h++)
        q2[h] = *(const uint2*)(qrow + h * D_DIM);

    float4 hv[NPREV];
    const float* hg = hist + (size_t)m * NPREV * D_DIM + tid * 4;
#pragma unroll
    for (int n = 0; n < NPREV; n++)
        hv[n] = *(const float4*)(hg + n * D_DIM);

    // ---- Phase A: dots + multi-value butterfly reduction ----
#pragma unroll
    for (int h = 0; h < H_HEADS; h++) {
        float2 qa = __bfloat1622float2(*reinterpret_cast<__nv_bfloat162*>(&q2[h].x));
        float2 qb = __bfloat1622float2(*reinterpret_cast<__nv_bfloat162*>(&q2[h].y));
        float p[NPREV];
#pragma unroll
        for (int n = 0; n < NPREV; n++)
            p[n] = qa.x * hv[n].x + qa.y * hv[n].y
                 + qb.x * hv[n].z + qb.y * hv[n].w;

#pragma unroll
        for (int i = 0; i < 4; i++) {
            float send = (lane & 16) ? p[i] : p[i + 4];
            float recv = __shfl_xor_sync(0xffffffffu, send, 16);
            p[i] = ((lane & 16) ? p[i + 4] : p[i]) + recv;
        }
#pragma unroll
        for (int i = 0; i < 2; i++) {
            float send = (lane & 8) ? p[i] : p[i + 2];
            float recv = __shfl_xor_sync(0xffffffffu, send, 8);
            p[i] = ((lane & 8) ? p[i + 2] : p[i]) + recv;
        }
        {
            float send = (lane & 4) ? p[0] : p[1];
            float recv = __shfl_xor_sync(0xffffffffu, send, 4);
            p[0] = ((lane & 4) ? p[1] : p[0]) + recv;
        }
        p[0] += __shfl_xor_sync(0xffffffffu, p[0], 2);
        p[0] += __shfl_xor_sync(0xffffffffu, p[0], 1);
        if ((lane & 3) == 0) red[h][lane >> 2][warp] = p[0];
    }
    __syncthreads();

    // ---- Phase B: 16 parallel softmaxes ----
    if (tid < H_HEADS) {
        const int h = tid;
        float lg[NPREV];
        float mx = -1e30f;
#pragma unroll
        for (int n = 0; n < NPREV; n++) {
            float4 s0 = *(const float4*)&red[h][n][0];
            float4 s1 = *(const float4*)&red[h][n][4];
            float s = (s0.x + s0.y) + (s0.z + s0.w)
                    + (s1.x + s1.y) + (s1.z + s1.w);
            lg[n] = s * 0.125f;
            mx = fmaxf(mx, lg[n]);
        }
        float den = 0.0f;
#pragma unroll
        for (int n = 0; n < NPREV; n++) { lg[n] = expf(lg[n] - mx); den += lg[n]; }
        float inv = 1.0f / den;
#pragma unroll
        for (int n = 0; n < NPREV; n++) attn_s[h][n] = lg[n] * inv;
    }
    __syncthreads();

    // ---- Phase C: weighted sums + bf16 stores ----
    __nv_bfloat16* orow = hbar + (size_t)m * (H_HEADS * D_DIM) + tid * 4;
#pragma unroll
    for (int h = 0; h < H_HEADS; h++) {
        float4 w0 = *(const float4*)&attn_s[h][0];
        float4 w1 = *(const float4*)&attn_s[h][4];
        float4 a4;
        a4.x = w0.x * hv[0].x; a4.y = w0.x * hv[0].y;
        a4.z = w0.x * hv[0].z; a4.w = w0.x * hv[0].w;
        a4.x = fmaf(w0.y, hv[1].x, a4.x); a4.y = fmaf(w0.y, hv[1].y, a4.y);
        a4.z = fmaf(w0.y, hv[1].z, a4.z); a4.w = fmaf(w0.y, hv[1].w, a4.w);
        a4.x = fmaf(w0.z, hv[2].x, a4.x); a4.y = fmaf(w0.z, hv[2].y, a4.y);
        a4.z = fmaf(w0.z, hv[2].z, a4.z); a4.w = fmaf(w0.z, hv[2].w, a4.w);
        a4.x = fmaf(w0.w, hv[3].x, a4.x); a4.y = fmaf(w0.w, hv[3].y, a4.y);
        a4.z = fmaf(w0.w, hv[3].z, a4.z); a4.w = fmaf(w0.w, hv[3].w, a4.w);
        a4.x = fmaf(w1.x, hv[4].x, a4.x); a4.y = fmaf(w1.x, hv[4].y, a4.y);
        a4.z = fmaf(w1.x, hv[4].z, a4.z); a4.w = fmaf(w1.x, hv[4].w, a4.w);
        a4.x = fmaf(w1.y, hv[5].x, a4.x); a4.y = fmaf(w1.y, hv[5].y, a4.y);
        a4.z = fmaf(w1.y, hv[5].z, a4.z); a4.w = fmaf(w1.y, hv[5].w, a4.w);
        a4.x = fmaf(w1.z, hv[6].x, a4.x); a4.y = fmaf(w1.z, hv[6].y, a4.y);
        a4.z = fmaf(w1.z, hv[6].z, a4.z); a4.w = fmaf(w1.z, hv[6].w, a4.w);
        a4.x = fmaf(w1.w, hv[7].x, a4.x); a4.y = fmaf(w1.w, hv[7].y, a4.y);
        a4.z = fmaf(w1.w, hv[7].z, a4.z); a4.w = fmaf(w1.w, hv[7].w, a4.w);
        uint2 ov;
        ov.x = pack_bf162(a4.x, a4.y);
        ov.y = pack_bf162(a4.z, a4.w);
        *(uint2*)(orow + h * D_DIM) = ov;
    }
}

// ---------------------------------------------------------------------------
extern "C" void kernel_launch(void* const* d_in, const int* in_sizes, int n_in,
                              void* d_out, int out_size)
{
    const float* cur  = (const float*)d_in[0];
    const float* hist = (const float*)d_in[1];
    const float* Wq   = (const float*)d_in[2];
    const float* Wk   = (const float*)d_in[3];
    const float* Wv   = (const float*)d_in[4];
    const float* Wo   = (const float*)d_in[5];
    float* out = (float*)d_out;

    const int D = D_DIM;
    const int M = in_sizes[0] / D;   // 8192

    __nv_bfloat16 *cb = nullptr, *qb = nullptr, *qk = nullptr, *hb = nullptr;
    __nv_bfloat16 *ob = nullptr, *wq = nullptr, *wkt = nullptr, *wv = nullptr, *wo = nullptr;
    cudaGetSymbolAddress((void**)&cb,  g_cb);
    cudaGetSymbolAddress((void**)&qb,  g_qb);
    cudaGetSymbolAddress((void**)&qk,  g_qk);
    cudaGetSymbolAddress((void**)&hb,  g_hb);
    cudaGetSymbolAddress((void**)&ob,  g_ob);
    cudaGetSymbolAddress((void**)&wq,  g_wq);
    cudaGetSymbolAddress((void**)&wkt, g_wkt);
    cudaGetSymbolAddress((void**)&wv,  g_wv);
    cudaGetSymbolAddress((void**)&wo,  g_wo);

    // SMEM budgets (bytes) — stage aliased onto mainloop buffers in gemm_bf16
    constexpr int SM_K2   = (128 * 72 + 2 * (128 * 72) + 128 * 136) * 2;  // 90112
    constexpr int SM_B64  = (2 * (128 * 72) + 2 * (64 * 72)) * 2;         // 55296
    constexpr int SM_B128 = (2 * (128 * 72) + 2 * (128 * 72)) * 2;        // 73728

    cudaFuncSetAttribute(gemm_k2,
                         cudaFuncAttributeMaxDynamicSharedMemorySize, SM_K2);
    cudaFuncSetAttribute(gemm_bf16<64, true,  false>,
                         cudaFuncAttributeMaxDynamicSharedMemorySize, SM_B64);
    cudaFuncSetAttribute(gemm_bf16<128, true,  false>,
                         cudaFuncAttributeMaxDynamicSharedMemorySize, SM_B128);
    cudaFuncSetAttribute(gemm_bf16<128, false, true>,
                         cudaFuncAttributeMaxDynamicSharedMemorySize, SM_B128);

    // P0: conversions
    convert_f2b<<<M * D / 4 / 256, 256>>>(cur, cb);
    convert_w3<<<dim3(D * D / 4 / 256, 3), 256>>>(Wq, wq, Wv, wv, Wo, wo);
    transpose_wk_bf16<<<dim3(32, 32), dim3(32, 8)>>>(Wk, wkt);

    // K1: q = cur @ Wq^T  (bf16) -> bf16 (staged, aliased)
    gemm_bf16<128, true, false>
        <<<dim3(D / 128, M / 128, 1), 256, SM_B128>>>(
            cb, D, 0, wq, D, 0, nullptr, qb, D, 0, D);

    // K2: qk_h = q_h @ Wk_h  (bf16, persistent j-loop, staged) -> bf16
    gemm_k2<<<dim3(M / 128, H_HEADS), 256, SM_K2>>>(qb, wkt, qk);

    // K3: attention -> hbar (bf16)
    attn_kernel<<<M, 256>>>(hist, qk, hb);

    // K4: out_h = hbar_h @ Wv_h^T (bf16, staged, aliased) -> out bf16
    gemm_bf16<64, true, false>
        <<<dim3(1, M / 128, H_HEADS), 256, SM_B64>>>(
            hb, H_HEADS * D, D,
            wv, D, (long long)HD * D,
            nullptr,
            ob, D, HD,
            D);

    // K5: final = cur + out @ Wo^T  (bf16 + fp32 residual)
    gemm_bf16<128, false, true>
        <<<dim3(D / 128, M / 128, 1), 256, SM_B128>>>(
            ob, D, 0, wo, D, 0, cur, out, D, 0, D);
}